// round 1
// baseline (speedup 1.0000x reference)
#include <cuda_runtime.h>
#include <math.h>

#define NW   512           // total windows (B=4 x 128 windows)
#define CDIM 256
#define PDIM 128           // spatial per window (8x16)
#define WSZ  (CDIM*PDIM)   // 32768 floats per window tensor

// ---------------- scratch (static device globals; no allocations) ----------
__device__ float g_mem [NW*WSZ];
__device__ float g_tgt [NW*WSZ];
__device__ float g_tgt2[NW*WSZ];
__device__ float g_tgt3[NW*WSZ];
__device__ float g_q   [NW*WSZ];
__device__ float g_k   [NW*WSZ];
__device__ float g_v   [NW*WSZ];
__device__ float g_hin [NW*WSZ];
__device__ float g_h   [NW*2*WSZ];   // FFN hidden (512 ch)
__device__ float g_fin [NW*WSZ];

// ---------------- window partition: [B,C,H,W] -> [NW,C,128] ----------------
__global__ void partition_kernel(const float* __restrict__ src, float* __restrict__ dst) {
    int idx = blockIdx.x * 256 + threadIdx.x;           // over NW*WSZ
    int p  = idx & 127;
    int c  = (idx >> 7) & 255;
    int bw = idx >> 15;
    int b = bw >> 7, wblk = bw & 127;
    int whi = wblk >> 3, wwi = wblk & 7;
    int y = p >> 4, x = p & 15;
    int h = whi * 8 + y, w = wwi * 16 + x;
    dst[idx] = src[(((size_t)b * 256 + c) * 128 + h) * 128 + w];
}

// ------------- final scatter: [NW,C,128] -> out [1, N=16384, B=4, C] -------
__global__ void scatter_kernel(const float* __restrict__ fin, float* __restrict__ out) {
    int idx = blockIdx.x * 256 + threadIdx.x;
    int p  = idx & 127;
    int c  = (idx >> 7) & 255;
    int bw = idx >> 15;
    int b = bw >> 7, wblk = bw & 127;
    int whi = wblk >> 3, wwi = wblk & 7;
    int y = p >> 4, x = p & 15;
    int h = whi * 8 + y, w = wwi * 16 + x;
    int n = h * 128 + w;
    out[((size_t)n * 4 + b) * 256 + c] = fin[idx];
}

// ---------------- GroupNorm(1 group) [+ poolformer mix + residual] ---------
// do_mix==1: out = base + ls[c] * (avgpool3(gn(in)) - gn(in))
// do_mix==0: out = gn(in)
__global__ __launch_bounds__(256)
void gn_kernel(const float* __restrict__ in, const float* __restrict__ base,
               const float* __restrict__ gw, const float* __restrict__ gb,
               const float* __restrict__ ls, float* __restrict__ out, int do_mix) {
    extern __shared__ float sm[];                       // 32768 floats
    __shared__ float red[16];
    __shared__ float stats[2];
    int win = blockIdx.x, tid = threadIdx.x;
    const float4* xin = (const float4*)(in + (size_t)win * WSZ);
    float4* s4 = (float4*)sm;

    float s = 0.f, sq = 0.f;
#pragma unroll
    for (int k = 0; k < 32; ++k) {
        float4 v = xin[tid + k * 256];
        s4[tid + k * 256] = v;
        s  += v.x + v.y + v.z + v.w;
        sq += v.x*v.x + v.y*v.y + v.z*v.z + v.w*v.w;
    }
#pragma unroll
    for (int off = 16; off; off >>= 1) {
        s  += __shfl_down_sync(0xffffffffu, s,  off);
        sq += __shfl_down_sync(0xffffffffu, sq, off);
    }
    if ((tid & 31) == 0) { red[tid >> 5] = s; red[8 + (tid >> 5)] = sq; }
    __syncthreads();
    if (tid == 0) {
        float ts = 0.f, tq = 0.f;
        for (int i = 0; i < 8; ++i) { ts += red[i]; tq += red[8 + i]; }
        float mean = ts * (1.f / 32768.f);
        float var  = tq * (1.f / 32768.f) - mean * mean;
        stats[0] = mean; stats[1] = rsqrtf(var + 1e-5f);
    }
    __syncthreads();
    float mean = stats[0], rstd = stats[1];

#pragma unroll
    for (int k = 0; k < 32; ++k) {
        int f = tid + k * 256;
        int c = f >> 5;
        float w = gw[c], bb = gb[c];
        float4 v = s4[f];
        v.x = (v.x - mean) * rstd * w + bb;
        v.y = (v.y - mean) * rstd * w + bb;
        v.z = (v.z - mean) * rstd * w + bb;
        v.w = (v.w - mean) * rstd * w + bb;
        s4[f] = v;
    }
    __syncthreads();

    if (!do_mix) {
#pragma unroll
        for (int k = 0; k < 32; ++k) {
            int f = tid + k * 256;
            ((float4*)(out + (size_t)win * WSZ))[f] = s4[f];
        }
    } else {
        const float4* bs4 = (const float4*)(base + (size_t)win * WSZ);
#pragma unroll 8
        for (int k = 0; k < 32; ++k) {
            int f = tid + k * 256;
            int c = f >> 5;
            int p0 = (f & 31) * 4;
            float lsv = ls[c];
            const float* ch = sm + c * 128;
            float4 bv = bs4[f];
            float o[4];
#pragma unroll
            for (int e = 0; e < 4; ++e) {
                int p = p0 + e, y = p >> 4, x = p & 15;
                float sum = 0.f; int cnt = 0;
#pragma unroll
                for (int dy = -1; dy <= 1; ++dy) {
                    int ny = y + dy;
                    if (ny < 0 || ny > 7) continue;
#pragma unroll
                    for (int dx = -1; dx <= 1; ++dx) {
                        int nx = x + dx;
                        if (nx < 0 || nx > 15) continue;
                        sum += ch[ny * 16 + nx]; cnt++;
                    }
                }
                o[e] = sum / (float)cnt - ch[p];
            }
            float4 ov;
            ov.x = bv.x + lsv * o[0];
            ov.y = bv.y + lsv * o[1];
            ov.z = bv.z + lsv * o[2];
            ov.w = bv.w + lsv * o[3];
            ((float4*)(out + (size_t)win * WSZ))[f] = ov;
        }
    }
}

// ---------------- per-window GEMM: Y[win,O,128] = W[O,CIN] @ X[win,CIN,128] -
// mode 0: +bias   mode 1: gelu(.+bias)   mode 2: base + ls[o]*(.+bias)
__global__ __launch_bounds__(256)
void gemm_win_kernel(const float* __restrict__ Wt, const float* __restrict__ bias,
                     const float* __restrict__ X, float* __restrict__ Y,
                     int O, int CIN, int mode,
                     const float* __restrict__ base, const float* __restrict__ ls) {
    extern __shared__ float smv[];
    float* xs = smv;                 // [256][128]
    float* ws = smv + 256 * 128;     // [256][68]  (c-major, o-minor, padded)
    int win = blockIdx.x;
    int tid = threadIdx.x;
    int ty = tid >> 4, tx = tid & 15;
    const float* Xw = X + (size_t)win * CIN * 128;
    int nchunks = CIN >> 8;
    int npass = O >> 6;

    for (int po = 0; po < npass; ++po) {
        float acc[4][8];
#pragma unroll
        for (int i = 0; i < 4; ++i)
#pragma unroll
            for (int j = 0; j < 8; ++j) acc[i][j] = 0.f;

        for (int cc = 0; cc < nchunks; ++cc) {
            __syncthreads();
            const float4* src = (const float4*)(Xw + cc * 256 * 128);
            float4* dst = (float4*)xs;
#pragma unroll
            for (int k = 0; k < 32; ++k) dst[tid + k * 256] = src[tid + k * 256];
#pragma unroll
            for (int k = 0; k < 16; ++k) {
                int idx = tid + k * 256;             // 0..4095
                int o  = idx >> 6;                   // 0..63
                int c4 = idx & 63;
                float4 wv = *(const float4*)(Wt + (size_t)(po * 64 + o) * CIN + cc * 256 + c4 * 4);
                int cb = c4 * 4;
                ws[(cb    ) * 68 + o] = wv.x;
                ws[(cb + 1) * 68 + o] = wv.y;
                ws[(cb + 2) * 68 + o] = wv.z;
                ws[(cb + 3) * 68 + o] = wv.w;
            }
            __syncthreads();
#pragma unroll 4
            for (int c = 0; c < 256; ++c) {
                float4 w4 = *(const float4*)(ws + c * 68 + (ty << 2));
                float4 xa = *(const float4*)(xs + c * 128 + (tx << 2));
                float4 xb = *(const float4*)(xs + c * 128 + 64 + (tx << 2));
                float wv[4] = {w4.x, w4.y, w4.z, w4.w};
                float xv[8] = {xa.x, xa.y, xa.z, xa.w, xb.x, xb.y, xb.z, xb.w};
#pragma unroll
                for (int i = 0; i < 4; ++i)
#pragma unroll
                    for (int j = 0; j < 8; ++j)
                        acc[i][j] = fmaf(wv[i], xv[j], acc[i][j]);
            }
        }
        // epilogue
#pragma unroll
        for (int i = 0; i < 4; ++i) {
            int o = po * 64 + (ty << 2) + i;
            float bv = bias[o];
            float lsv = (mode == 2) ? ls[o] : 0.f;
#pragma unroll
            for (int half = 0; half < 2; ++half) {
                size_t gi = ((size_t)win * O + o) * 128 + half * 64 + (tx << 2);
                float4 r;
                r.x = acc[i][half * 4 + 0] + bv;
                r.y = acc[i][half * 4 + 1] + bv;
                r.z = acc[i][half * 4 + 2] + bv;
                r.w = acc[i][half * 4 + 3] + bv;
                if (mode == 1) {
                    r.x = 0.5f * r.x * (1.f + erff(r.x * 0.70710678118654752f));
                    r.y = 0.5f * r.y * (1.f + erff(r.y * 0.70710678118654752f));
                    r.z = 0.5f * r.z * (1.f + erff(r.z * 0.70710678118654752f));
                    r.w = 0.5f * r.w * (1.f + erff(r.w * 0.70710678118654752f));
                } else if (mode == 2) {
                    float4 b4 = *(const float4*)(base + gi);
                    r.x = b4.x + lsv * r.x;
                    r.y = b4.y + lsv * r.y;
                    r.z = b4.z + lsv * r.z;
                    r.w = b4.w + lsv * r.w;
                }
                *(float4*)(Y + gi) = r;
            }
        }
    }
}

// ---------------- attention (raw-reshape semantics) -------------------------
// Qf,Kf,Vf = raw window buffers viewed [128,256]. S = softmax(Qf @ Kf^T),
// Ofl = S @ Vf (raw [128,256]); tgt3 = tgt2 + Ofl.
__global__ __launch_bounds__(256)
void attn_kernel(const float* __restrict__ Q, const float* __restrict__ K,
                 const float* __restrict__ V, const float* __restrict__ tgt2,
                 float* __restrict__ tgt3) {
    extern __shared__ float smv[];
    float* qT = smv;                 // [128][132]  (j-major)
    float* kT = smv + 128 * 132;     // [128][132]
    int win = blockIdx.x;
    int tid = threadIdx.x;
    int ty = tid >> 4, tx = tid & 15;
    const float* Qw = Q + (size_t)win * WSZ;
    const float* Kw = K + (size_t)win * WSZ;
    const float* Vw = V + (size_t)win * WSZ;

    float acc[8][8];
#pragma unroll
    for (int r = 0; r < 8; ++r)
#pragma unroll
        for (int c = 0; c < 8; ++c) acc[r][c] = 0.f;

    for (int jc = 0; jc < 2; ++jc) {
        __syncthreads();
#pragma unroll 4
        for (int k = 0; k < 64; ++k) {
            int idx = tid + k * 256;             // 0..16383
            int i = idx >> 7, j = idx & 127;
            qT[j * 132 + i] = Qw[i * 256 + jc * 128 + j];
            kT[j * 132 + i] = Kw[i * 256 + jc * 128 + j];
        }
        __syncthreads();
#pragma unroll 2
        for (int j = 0; j < 128; ++j) {
            float4 qa = *(const float4*)(qT + j * 132 + (ty << 3));
            float4 qb = *(const float4*)(qT + j * 132 + (ty << 3) + 4);
            float4 ka = *(const float4*)(kT + j * 132 + (tx << 3));
            float4 kb = *(const float4*)(kT + j * 132 + (tx << 3) + 4);
            float qv[8] = {qa.x, qa.y, qa.z, qa.w, qb.x, qb.y, qb.z, qb.w};
            float kv[8] = {ka.x, ka.y, ka.z, ka.w, kb.x, kb.y, kb.z, kb.w};
#pragma unroll
            for (int r = 0; r < 8; ++r)
#pragma unroll
                for (int c = 0; c < 8; ++c)
                    acc[r][c] = fmaf(qv[r], kv[c], acc[r][c]);
        }
    }

    // softmax over rows (m spread across 16 tx lanes x 8 locals)
#pragma unroll
    for (int r = 0; r < 8; ++r) {
        float mx = acc[r][0];
#pragma unroll
        for (int c = 1; c < 8; ++c) mx = fmaxf(mx, acc[r][c]);
#pragma unroll
        for (int off = 8; off; off >>= 1) mx = fmaxf(mx, __shfl_xor_sync(0xffffffffu, mx, off));
        float sum = 0.f;
#pragma unroll
        for (int c = 0; c < 8; ++c) { acc[r][c] = expf(acc[r][c] - mx); sum += acc[r][c]; }
#pragma unroll
        for (int off = 8; off; off >>= 1) sum += __shfl_xor_sync(0xffffffffu, sum, off);
        float is = 1.f / sum;
#pragma unroll
        for (int c = 0; c < 8; ++c) acc[r][c] *= is;
    }

    __syncthreads();                                   // done with qT/kT
    float* sS = smv;                                   // [128][132]  S[i][m]
    float* vS = smv + 128 * 132;                       // [128][256]  V raw
#pragma unroll
    for (int r = 0; r < 8; ++r) {
        float4 a = {acc[r][0], acc[r][1], acc[r][2], acc[r][3]};
        float4 b = {acc[r][4], acc[r][5], acc[r][6], acc[r][7]};
        *(float4*)(sS + ((ty << 3) + r) * 132 + (tx << 3))     = a;
        *(float4*)(sS + ((ty << 3) + r) * 132 + (tx << 3) + 4) = b;
    }
    {
        const float4* src = (const float4*)Vw;
        float4* dst = (float4*)vS;
#pragma unroll
        for (int k = 0; k < 32; ++k) dst[tid + k * 256] = src[tid + k * 256];
    }
    __syncthreads();

    for (int jp = 0; jp < 2; ++jp) {
        float oacc[8][8];
#pragma unroll
        for (int r = 0; r < 8; ++r)
#pragma unroll
            for (int c = 0; c < 8; ++c) oacc[r][c] = 0.f;
#pragma unroll 2
        for (int m = 0; m < 128; ++m) {
            float sv[8];
#pragma unroll
            for (int r = 0; r < 8; ++r) sv[r] = sS[((ty << 3) + r) * 132 + m];
            float4 va = *(const float4*)(vS + m * 256 + jp * 128 + (tx << 3));
            float4 vb = *(const float4*)(vS + m * 256 + jp * 128 + (tx << 3) + 4);
            float vv[8] = {va.x, va.y, va.z, va.w, vb.x, vb.y, vb.z, vb.w};
#pragma unroll
            for (int r = 0; r < 8; ++r)
#pragma unroll
                for (int c = 0; c < 8; ++c)
                    oacc[r][c] = fmaf(sv[r], vv[c], oacc[r][c]);
        }
#pragma unroll
        for (int r = 0; r < 8; ++r) {
            size_t gi = (size_t)win * WSZ + ((ty << 3) + r) * 256 + jp * 128 + (tx << 3);
            float4 t2a = *(const float4*)(tgt2 + gi);
            float4 t2b = *(const float4*)(tgt2 + gi + 4);
            float4 oa = {t2a.x + oacc[r][0], t2a.y + oacc[r][1], t2a.z + oacc[r][2], t2a.w + oacc[r][3]};
            float4 ob = {t2b.x + oacc[r][4], t2b.y + oacc[r][5], t2b.z + oacc[r][6], t2b.w + oacc[r][7]};
            *(float4*)(tgt3 + gi)     = oa;
            *(float4*)(tgt3 + gi + 4) = ob;
        }
    }
}

// ---------------- host orchestration ---------------------------------------
extern "C" void kernel_launch(void* const* d_in, const int* in_sizes, int n_in,
                              void* d_out, int out_size) {
    const float* src  = (const float*)d_in[0];
    const float* qf   = (const float*)d_in[1];
    const float* gn1w = (const float*)d_in[2];
    const float* gn1b = (const float*)d_in[3];
    const float* gn2w = (const float*)d_in[4];
    const float* gn2b = (const float*)d_in[5];
    const float* ls1  = (const float*)d_in[6];
    const float* ls2  = (const float*)d_in[7];
    const float* ls3  = (const float*)d_in[8];
    const float* qw   = (const float*)d_in[9];
    const float* qb   = (const float*)d_in[10];
    const float* kw   = (const float*)d_in[11];
    const float* kb   = (const float*)d_in[12];
    const float* vw   = (const float*)d_in[13];
    const float* vb   = (const float*)d_in[14];
    const float* fc1w = (const float*)d_in[15];
    const float* fc1b = (const float*)d_in[16];
    const float* fc2w = (const float*)d_in[17];
    const float* fc2b = (const float*)d_in[18];
    const float* gnfw = (const float*)d_in[19];
    const float* gnfb = (const float*)d_in[20];
    float* out = (float*)d_out;

    float *mem, *tgt, *tgt2, *tgt3, *q, *k, *v, *hin, *h, *fin;
    cudaGetSymbolAddress((void**)&mem,  g_mem);
    cudaGetSymbolAddress((void**)&tgt,  g_tgt);
    cudaGetSymbolAddress((void**)&tgt2, g_tgt2);
    cudaGetSymbolAddress((void**)&tgt3, g_tgt3);
    cudaGetSymbolAddress((void**)&q,    g_q);
    cudaGetSymbolAddress((void**)&k,    g_k);
    cudaGetSymbolAddress((void**)&v,    g_v);
    cudaGetSymbolAddress((void**)&hin,  g_hin);
    cudaGetSymbolAddress((void**)&h,    g_h);
    cudaGetSymbolAddress((void**)&fin,  g_fin);

    const int SM_GN   = 131072;   // 32768 floats
    const int SM_GEMM = 200704;   // 50176 floats
    const int SM_ATTN = 198656;   // 49664 floats
    cudaFuncSetAttribute(gn_kernel,       cudaFuncAttributeMaxDynamicSharedMemorySize, SM_GN);
    cudaFuncSetAttribute(gemm_win_kernel, cudaFuncAttributeMaxDynamicSharedMemorySize, SM_GEMM);
    cudaFuncSetAttribute(attn_kernel,     cudaFuncAttributeMaxDynamicSharedMemorySize, SM_ATTN);

    partition_kernel<<<65536, 256>>>(src, mem);
    partition_kernel<<<65536, 256>>>(qf, tgt);

    for (int l = 0; l < 2; ++l) {
        int lC = l * CDIM;
        // tgt2 = tgt + ls1 * mix(gn1(tgt))
        gn_kernel<<<NW, 256, SM_GN>>>(tgt, tgt, gn1w + lC, gn1b + lC, ls1 + lC, tgt2, 1);
        // Q/K/V conv1x1
        gemm_win_kernel<<<NW, 256, SM_GEMM>>>(qw + (size_t)l * CDIM * CDIM, qb + lC, tgt, q, 256, 256, 0, nullptr, nullptr);
        gemm_win_kernel<<<NW, 256, SM_GEMM>>>(kw + (size_t)l * CDIM * CDIM, kb + lC, mem, k, 256, 256, 0, nullptr, nullptr);
        gemm_win_kernel<<<NW, 256, SM_GEMM>>>(vw + (size_t)l * CDIM * CDIM, vb + lC, mem, v, 256, 256, 0, nullptr, nullptr);
        // tgt3 = tgt2 + attention(tgt, mem)
        attn_kernel<<<NW, 256, SM_ATTN>>>(q, k, v, tgt2, tgt3);
        // tgt3 = tgt2 + ls2 * mix(gn1(tgt3))   (in-place safe: per-window smem staging)
        gn_kernel<<<NW, 256, SM_GN>>>(tgt3, tgt2, gn1w + lC, gn1b + lC, ls2 + lC, tgt3, 1);
        // hin = gn2(tgt3)
        gn_kernel<<<NW, 256, SM_GN>>>(tgt3, nullptr, gn2w + lC, gn2b + lC, nullptr, hin, 0);
        // h = gelu(fc1(hin))
        gemm_win_kernel<<<NW, 256, SM_GEMM>>>(fc1w + (size_t)l * 512 * 256, fc1b + (size_t)l * 512, hin, h, 512, 256, 1, nullptr, nullptr);
        // tgt = tgt3 + ls3 * fc2(h)
        gemm_win_kernel<<<NW, 256, SM_GEMM>>>(fc2w + (size_t)l * 256 * 512, fc2b + lC, h, tgt, 256, 512, 2, tgt3, ls3 + lC);
    }

    // final GN + window-reverse scatter to [1, N, B, C]
    gn_kernel<<<NW, 256, SM_GN>>>(tgt, nullptr, gnfw, gnfb, nullptr, fin, 0);
    scatter_kernel<<<65536, 256>>>(fin, out);
}

// round 3
// speedup vs baseline: 2.1441x; 2.1441x over previous
#include <cuda_runtime.h>
#include <cuda_bf16.h>
#include <math.h>
#include <stdint.h>

#define NW   512
#define CDIM 256
#define PDIM 128
#define WSZ  (CDIM*PDIM)

// ---------------- scratch (static device globals; no allocations) ----------
__device__ float g_mem [NW*WSZ];
__device__ float g_tgt [NW*WSZ];
__device__ float g_tgt2[NW*WSZ];
__device__ float g_tgt3[NW*WSZ];
__device__ float g_q   [NW*WSZ];
__device__ float g_k   [NW*WSZ];
__device__ float g_v   [NW*WSZ];
__device__ float g_hin [NW*WSZ];
__device__ float g_h   [NW*2*WSZ];
__device__ float g_fin [NW*WSZ];
// bf16 hi/lo operand buffers (row-major: W[o][k], Xt[win][p][k])
__device__ __nv_bfloat16 g_bxhi[NW*128*512];
__device__ __nv_bfloat16 g_bxlo[NW*128*512];
__device__ __nv_bfloat16 g_memhi[NW*128*256];
__device__ __nv_bfloat16 g_memlo[NW*128*256];
__device__ __nv_bfloat16 g_whi[2*458752];
__device__ __nv_bfloat16 g_wlo[2*458752];

// ================= mma helpers =============================================
__device__ __forceinline__ uint32_t smem_u32(const void* p) {
    uint32_t a;
    asm("{ .reg .u64 t; cvta.to.shared.u64 t, %1; cvt.u32.u64 %0, t; }" : "=r"(a) : "l"(p));
    return a;
}
#define LDSM_X4(r0,r1,r2,r3,addr) \
    asm volatile("ldmatrix.sync.aligned.m8n8.x4.shared.b16 {%0,%1,%2,%3}, [%4];" \
        : "=r"(r0),"=r"(r1),"=r"(r2),"=r"(r3) : "r"(addr))
__device__ __forceinline__ void mma_bf16(float* d, const unsigned* a, const unsigned* b) {
    asm volatile("mma.sync.aligned.m16n8k16.row.col.f32.bf16.bf16.f32 "
        "{%0,%1,%2,%3}, {%4,%5,%6,%7}, {%8,%9}, {%0,%1,%2,%3};"
        : "+f"(d[0]),"+f"(d[1]),"+f"(d[2]),"+f"(d[3])
        : "r"(a[0]),"r"(a[1]),"r"(a[2]),"r"(a[3]), "r"(b[0]),"r"(b[1]));
}

// ---------------- window partition / scatter --------------------------------
__global__ void partition_kernel(const float* __restrict__ src, float* __restrict__ dst) {
    int idx = blockIdx.x * 256 + threadIdx.x;
    int p  = idx & 127;
    int c  = (idx >> 7) & 255;
    int bw = idx >> 15;
    int b = bw >> 7, wblk = bw & 127;
    int whi = wblk >> 3, wwi = wblk & 7;
    int y = p >> 4, x = p & 15;
    int h = whi * 8 + y, w = wwi * 16 + x;
    dst[idx] = src[(((size_t)b * 256 + c) * 128 + h) * 128 + w];
}
__global__ void scatter_kernel(const float* __restrict__ fin, float* __restrict__ out) {
    int idx = blockIdx.x * 256 + threadIdx.x;
    int p  = idx & 127;
    int c  = (idx >> 7) & 255;
    int bw = idx >> 15;
    int b = bw >> 7, wblk = bw & 127;
    int whi = wblk >> 3, wwi = wblk & 7;
    int y = p >> 4, x = p & 15;
    int h = whi * 8 + y, w = wwi * 16 + x;
    int n = h * 128 + w;
    out[((size_t)n * 4 + b) * 256 + c] = fin[idx];
}

// ---------------- fp32 -> bf16 hi/lo conversions ----------------------------
__device__ __forceinline__ void split2(float a, float b, unsigned& h, unsigned& l) {
    __nv_bfloat16 ah = __float2bfloat16(a);
    __nv_bfloat16 bh = __float2bfloat16(b);
    __nv_bfloat16 al = __float2bfloat16(a - __bfloat162float(ah));
    __nv_bfloat16 bl = __float2bfloat16(b - __bfloat162float(bh));
    h = (unsigned)__bfloat16_as_ushort(ah) | ((unsigned)__bfloat16_as_ushort(bh) << 16);
    l = (unsigned)__bfloat16_as_ushort(al) | ((unsigned)__bfloat16_as_ushort(bl) << 16);
}

// weights: W[O,CIN] fp32 -> hi/lo bf16 same layout
__global__ void conv_w_kernel(const float* __restrict__ W, __nv_bfloat16* __restrict__ hi,
                              __nv_bfloat16* __restrict__ lo, int total8) {
    int g = blockIdx.x * 256 + threadIdx.x;
    if (g >= total8) return;
    const float* src = W + (size_t)g * 8;
    unsigned hh[4], ll[4];
#pragma unroll
    for (int j = 0; j < 4; ++j) split2(src[2*j], src[2*j+1], hh[j], ll[j]);
    uint4 vh = {hh[0], hh[1], hh[2], hh[3]};
    uint4 vl = {ll[0], ll[1], ll[2], ll[3]};
    ((uint4*)hi)[g] = vh;
    ((uint4*)lo)[g] = vl;
}

// activations: X[win][CIN][128] fp32 -> Xt[win][128][CIN] hi/lo bf16
__global__ __launch_bounds__(256)
void conv_x_kernel(const float* __restrict__ X, __nv_bfloat16* __restrict__ hi,
                   __nv_bfloat16* __restrict__ lo, int CIN) {
    extern __shared__ float xs[];                 // [256][132]
    int win = blockIdx.x, tid = threadIdx.x;
    int nkb = CIN >> 8;
    const float* Xw = X + (size_t)win * CIN * 128;
    int c8 = CIN >> 3;
    for (int kb = 0; kb < nkb; ++kb) {
        __syncthreads();
#pragma unroll 4
        for (int idx = tid; idx < 8192; idx += 256) {
            int c = idx >> 5, p4 = idx & 31;
            float4 v = *(const float4*)(Xw + (size_t)(kb * 256 + c) * 128 + p4 * 4);
            *(float4*)(xs + c * 132 + p4 * 4) = v;
        }
        __syncthreads();
        uint4* oh = (uint4*)hi + (size_t)win * 16 * CIN + kb * 32;
        uint4* ol = (uint4*)lo + (size_t)win * 16 * CIN + kb * 32;
#pragma unroll 2
        for (int g = tid; g < 4096; g += 256) {
            int p = g & 127, kg = g >> 7;          // kg: 8-elem group within 256
            unsigned hh[4], ll[4];
#pragma unroll
            for (int j = 0; j < 4; ++j)
                split2(xs[(kg * 8 + 2*j) * 132 + p], xs[(kg * 8 + 2*j + 1) * 132 + p],
                       hh[j], ll[j]);
            uint4 vh = {hh[0], hh[1], hh[2], hh[3]};
            uint4 vl = {ll[0], ll[1], ll[2], ll[3]};
            size_t u = (size_t)p * c8 + kg;
            oh[u] = vh;
            ol[u] = vl;
        }
    }
}

// ---------------- tensor-core GEMM: Y[win,O,128] = W[O,CIN] @ Xt[win,:, CIN]^T
// 3-term bf16 split, fp32 accum. grid = (NW, O/128). 8 warps: 4(M) x 2(N), 32x64 each.
// mode 0: +bias   1: gelu(.+bias)   2: base + ls[o]*(.+bias)
__global__ __launch_bounds__(256, 2)
void gemm_tc_kernel(const __nv_bfloat16* __restrict__ Whi, const __nv_bfloat16* __restrict__ Wlo,
                    const __nv_bfloat16* __restrict__ Xhi, const __nv_bfloat16* __restrict__ Xlo,
                    const float* __restrict__ bias, float* __restrict__ Y,
                    int O, int CIN, int mode,
                    const float* __restrict__ base, const float* __restrict__ ls) {
    extern __shared__ __nv_bfloat16 sb[];
    __nv_bfloat16* sWhi = sb;                 // [128][72]
    __nv_bfloat16* sWlo = sb + 9216;
    __nv_bfloat16* sXhi = sb + 18432;
    __nv_bfloat16* sXlo = sb + 27648;
    int win = blockIdx.x, ob = blockIdx.y;
    int tid = threadIdx.x, lane = tid & 31, wid = tid >> 5;
    int wr = wid >> 1, wc = wid & 1;

    const __nv_bfloat16* gWhi = Whi + (size_t)ob * 128 * CIN;
    const __nv_bfloat16* gWlo = Wlo + (size_t)ob * 128 * CIN;
    const __nv_bfloat16* gXhi = Xhi + (size_t)win * 128 * CIN;
    const __nv_bfloat16* gXlo = Xlo + (size_t)win * 128 * CIN;

    float acc[2][8][4];
#pragma unroll
    for (int mt = 0; mt < 2; ++mt)
#pragma unroll
        for (int nt = 0; nt < 8; ++nt)
#pragma unroll
            for (int e = 0; e < 4; ++e) acc[mt][nt][e] = 0.f;

    // ldmatrix lane addressing (element offsets within smem tiles)
    int aRow = (lane & 15), aCol = (lane >> 4) * 8;
    int bRow = (lane & 7) + ((lane >> 4) & 1) * 8, bCol = ((lane >> 3) & 1) * 8;

    for (int kc = 0; kc < CIN; kc += 64) {
        __syncthreads();
#pragma unroll
        for (int i = tid; i < 1024; i += 256) {
            int r = i >> 3, c4 = i & 7;
            size_t go = (size_t)r * CIN + kc + c4 * 8;
            int so = r * 72 + c4 * 8;
            *(uint4*)(sWhi + so) = *(const uint4*)(gWhi + go);
            *(uint4*)(sWlo + so) = *(const uint4*)(gWlo + go);
            *(uint4*)(sXhi + so) = *(const uint4*)(gXhi + go);
            *(uint4*)(sXlo + so) = *(const uint4*)(gXlo + go);
        }
        __syncthreads();
#pragma unroll
        for (int ks = 0; ks < 4; ++ks) {
            unsigned aHi[2][4], aLo[2][4];
#pragma unroll
            for (int mt = 0; mt < 2; ++mt) {
                int ro = (wr * 32 + mt * 16 + aRow) * 72 + ks * 16 + aCol;
                LDSM_X4(aHi[mt][0], aHi[mt][1], aHi[mt][2], aHi[mt][3], smem_u32(sWhi + ro));
                LDSM_X4(aLo[mt][0], aLo[mt][1], aLo[mt][2], aLo[mt][3], smem_u32(sWlo + ro));
            }
#pragma unroll
            for (int np = 0; np < 4; ++np) {
                int no = (wc * 64 + np * 16 + bRow) * 72 + ks * 16 + bCol;
                unsigned bHi[4], bLo[4];
                LDSM_X4(bHi[0], bHi[1], bHi[2], bHi[3], smem_u32(sXhi + no));
                LDSM_X4(bLo[0], bLo[1], bLo[2], bLo[3], smem_u32(sXlo + no));
#pragma unroll
                for (int mt = 0; mt < 2; ++mt) {
                    mma_bf16(acc[mt][np*2],   aHi[mt], bHi);
                    mma_bf16(acc[mt][np*2+1], aHi[mt], bHi + 2);
                    mma_bf16(acc[mt][np*2],   aHi[mt], bLo);
                    mma_bf16(acc[mt][np*2+1], aHi[mt], bLo + 2);
                    mma_bf16(acc[mt][np*2],   aLo[mt], bHi);
                    mma_bf16(acc[mt][np*2+1], aLo[mt], bHi + 2);
                }
            }
        }
    }

    // epilogue
    int O0 = ob * 128;
#pragma unroll
    for (int mt = 0; mt < 2; ++mt)
#pragma unroll
        for (int nt = 0; nt < 8; ++nt) {
            int p = wc * 64 + nt * 8 + (lane & 3) * 2;
#pragma unroll
            for (int half = 0; half < 2; ++half) {
                int o = O0 + wr * 32 + mt * 16 + (lane >> 2) + half * 8;
                float bv = bias[o];
                float2 v;
                v.x = acc[mt][nt][half * 2]     + bv;
                v.y = acc[mt][nt][half * 2 + 1] + bv;
                size_t gi = ((size_t)win * O + o) * 128 + p;
                if (mode == 1) {
                    v.x = 0.5f * v.x * (1.f + erff(v.x * 0.70710678118654752f));
                    v.y = 0.5f * v.y * (1.f + erff(v.y * 0.70710678118654752f));
                } else if (mode == 2) {
                    float lsv = ls[o];
                    float2 b2 = *(const float2*)(base + gi);
                    v.x = b2.x + lsv * v.x;
                    v.y = b2.y + lsv * v.y;
                }
                *(float2*)(Y + gi) = v;
            }
        }
}

// ---------------- GroupNorm(1 group) [+ poolformer mix + residual] ----------
__global__ __launch_bounds__(256)
void gn_kernel(const float* __restrict__ in, const float* __restrict__ base,
               const float* __restrict__ gw, const float* __restrict__ gb,
               const float* __restrict__ ls, float* __restrict__ out, int do_mix) {
    extern __shared__ float sm[];
    __shared__ float red[16];
    __shared__ float stats[2];
    int win = blockIdx.x, tid = threadIdx.x;
    const float4* xin = (const float4*)(in + (size_t)win * WSZ);
    float4* s4 = (float4*)sm;

    float s = 0.f, sq = 0.f;
#pragma unroll
    for (int k = 0; k < 32; ++k) {
        float4 v = xin[tid + k * 256];
        s4[tid + k * 256] = v;
        s  += v.x + v.y + v.z + v.w;
        sq += v.x*v.x + v.y*v.y + v.z*v.z + v.w*v.w;
    }
#pragma unroll
    for (int off = 16; off; off >>= 1) {
        s  += __shfl_down_sync(0xffffffffu, s,  off);
        sq += __shfl_down_sync(0xffffffffu, sq, off);
    }
    if ((tid & 31) == 0) { red[tid >> 5] = s; red[8 + (tid >> 5)] = sq; }
    __syncthreads();
    if (tid == 0) {
        float ts = 0.f, tq = 0.f;
        for (int i = 0; i < 8; ++i) { ts += red[i]; tq += red[8 + i]; }
        float mean = ts * (1.f / 32768.f);
        float var  = tq * (1.f / 32768.f) - mean * mean;
        stats[0] = mean; stats[1] = rsqrtf(var + 1e-5f);
    }
    __syncthreads();
    float mean = stats[0], rstd = stats[1];

#pragma unroll
    for (int k = 0; k < 32; ++k) {
        int f = tid + k * 256;
        int c = f >> 5;
        float w = gw[c], bb = gb[c];
        float4 v = s4[f];
        v.x = (v.x - mean) * rstd * w + bb;
        v.y = (v.y - mean) * rstd * w + bb;
        v.z = (v.z - mean) * rstd * w + bb;
        v.w = (v.w - mean) * rstd * w + bb;
        s4[f] = v;
    }
    __syncthreads();

    if (!do_mix) {
#pragma unroll
        for (int k = 0; k < 32; ++k) {
            int f = tid + k * 256;
            ((float4*)(out + (size_t)win * WSZ))[f] = s4[f];
        }
    } else {
        const float4* bs4 = (const float4*)(base + (size_t)win * WSZ);
#pragma unroll 8
        for (int k = 0; k < 32; ++k) {
            int f = tid + k * 256;
            int c = f >> 5;
            int p0 = (f & 31) * 4;
            float lsv = ls[c];
            const float* ch = sm + c * 128;
            float4 bv = bs4[f];
            float o[4];
#pragma unroll
            for (int e = 0; e < 4; ++e) {
                int p = p0 + e, y = p >> 4, x = p & 15;
                float sum = 0.f; int cnt = 0;
#pragma unroll
                for (int dy = -1; dy <= 1; ++dy) {
                    int ny = y + dy;
                    if (ny < 0 || ny > 7) continue;
#pragma unroll
                    for (int dx = -1; dx <= 1; ++dx) {
                        int nx = x + dx;
                        if (nx < 0 || nx > 15) continue;
                        sum += ch[ny * 16 + nx]; cnt++;
                    }
                }
                o[e] = sum / (float)cnt - ch[p];
            }
            float4 ov;
            ov.x = bv.x + lsv * o[0];
            ov.y = bv.y + lsv * o[1];
            ov.z = bv.z + lsv * o[2];
            ov.w = bv.w + lsv * o[3];
            ((float4*)(out + (size_t)win * WSZ))[f] = ov;
        }
    }
}

// ---------------- attention (raw-reshape semantics), FFMA -------------------
__global__ __launch_bounds__(256)
void attn_kernel(const float* __restrict__ Q, const float* __restrict__ K,
                 const float* __restrict__ V, const float* __restrict__ tgt2,
                 float* __restrict__ tgt3) {
    extern __shared__ float smv[];
    float* qT = smv;
    float* kT = smv + 128 * 132;
    int win = blockIdx.x;
    int tid = threadIdx.x;
    int ty = tid >> 4, tx = tid & 15;
    const float* Qw = Q + (size_t)win * WSZ;
    const float* Kw = K + (size_t)win * WSZ;
    const float* Vw = V + (size_t)win * WSZ;

    float acc[8][8];
#pragma unroll
    for (int r = 0; r < 8; ++r)
#pragma unroll
        for (int c = 0; c < 8; ++c) acc[r][c] = 0.f;

    for (int jc = 0; jc < 2; ++jc) {
        __syncthreads();
#pragma unroll 4
        for (int k = 0; k < 64; ++k) {
            int idx = tid + k * 256;
            int i = idx >> 7, j = idx & 127;
            qT[j * 132 + i] = Qw[i * 256 + jc * 128 + j];
            kT[j * 132 + i] = Kw[i * 256 + jc * 128 + j];
        }
        __syncthreads();
#pragma unroll 2
        for (int j = 0; j < 128; ++j) {
            float4 qa = *(const float4*)(qT + j * 132 + (ty << 3));
            float4 qb = *(const float4*)(qT + j * 132 + (ty << 3) + 4);
            float4 ka = *(const float4*)(kT + j * 132 + (tx << 3));
            float4 kb = *(const float4*)(kT + j * 132 + (tx << 3) + 4);
            float qv[8] = {qa.x, qa.y, qa.z, qa.w, qb.x, qb.y, qb.z, qb.w};
            float kv[8] = {ka.x, ka.y, ka.z, ka.w, kb.x, kb.y, kb.z, kb.w};
#pragma unroll
            for (int r = 0; r < 8; ++r)
#pragma unroll
                for (int c = 0; c < 8; ++c)
                    acc[r][c] = fmaf(qv[r], kv[c], acc[r][c]);
        }
    }

#pragma unroll
    for (int r = 0; r < 8; ++r) {
        float mx = acc[r][0];
#pragma unroll
        for (int c = 1; c < 8; ++c) mx = fmaxf(mx, acc[r][c]);
#pragma unroll
        for (int off = 8; off; off >>= 1) mx = fmaxf(mx, __shfl_xor_sync(0xffffffffu, mx, off));
        float sum = 0.f;
#pragma unroll
        for (int c = 0; c < 8; ++c) { acc[r][c] = expf(acc[r][c] - mx); sum += acc[r][c]; }
#pragma unroll
        for (int off = 8; off; off >>= 1) sum += __shfl_xor_sync(0xffffffffu, sum, off);
        float is = 1.f / sum;
#pragma unroll
        for (int c = 0; c < 8; ++c) acc[r][c] *= is;
    }

    __syncthreads();
    float* sS = smv;
    float* vS = smv + 128 * 132;
#pragma unroll
    for (int r = 0; r < 8; ++r) {
        float4 a = {acc[r][0], acc[r][1], acc[r][2], acc[r][3]};
        float4 b = {acc[r][4], acc[r][5], acc[r][6], acc[r][7]};
        *(float4*)(sS + ((ty << 3) + r) * 132 + (tx << 3))     = a;
        *(float4*)(sS + ((ty << 3) + r) * 132 + (tx << 3) + 4) = b;
    }
    {
        const float4* src = (const float4*)Vw;
        float4* dst = (float4*)vS;
#pragma unroll
        for (int k = 0; k < 32; ++k) dst[tid + k * 256] = src[tid + k * 256];
    }
    __syncthreads();

    for (int jp = 0; jp < 2; ++jp) {
        float oacc[8][8];
#pragma unroll
        for (int r = 0; r < 8; ++r)
#pragma unroll
            for (int c = 0; c < 8; ++c) oacc[r][c] = 0.f;
#pragma unroll 2
        for (int m = 0; m < 128; ++m) {
            float sv[8];
#pragma unroll
            for (int r = 0; r < 8; ++r) sv[r] = sS[((ty << 3) + r) * 132 + m];
            float4 va = *(const float4*)(vS + m * 256 + jp * 128 + (tx << 3));
            float4 vb = *(const float4*)(vS + m * 256 + jp * 128 + (tx << 3) + 4);
            float vv[8] = {va.x, va.y, va.z, va.w, vb.x, vb.y, vb.z, vb.w};
#pragma unroll
            for (int r = 0; r < 8; ++r)
#pragma unroll
                for (int c = 0; c < 8; ++c)
                    oacc[r][c] = fmaf(sv[r], vv[c], oacc[r][c]);
        }
#pragma unroll
        for (int r = 0; r < 8; ++r) {
            size_t gi = (size_t)win * WSZ + ((ty << 3) + r) * 256 + jp * 128 + (tx << 3);
            float4 t2a = *(const float4*)(tgt2 + gi);
            float4 t2b = *(const float4*)(tgt2 + gi + 4);
            float4 oa = {t2a.x + oacc[r][0], t2a.y + oacc[r][1], t2a.z + oacc[r][2], t2a.w + oacc[r][3]};
            float4 ob = {t2b.x + oacc[r][4], t2b.y + oacc[r][5], t2b.z + oacc[r][6], t2b.w + oacc[r][7]};
            *(float4*)(tgt3 + gi)     = oa;
            *(float4*)(tgt3 + gi + 4) = ob;
        }
    }
}

// ---------------- host orchestration ---------------------------------------
extern "C" void kernel_launch(void* const* d_in, const int* in_sizes, int n_in,
                              void* d_out, int out_size) {
    const float* src  = (const float*)d_in[0];
    const float* qf   = (const float*)d_in[1];
    const float* gn1w = (const float*)d_in[2];
    const float* gn1b = (const float*)d_in[3];
    const float* gn2w = (const float*)d_in[4];
    const float* gn2b = (const float*)d_in[5];
    const float* ls1  = (const float*)d_in[6];
    const float* ls2  = (const float*)d_in[7];
    const float* ls3  = (const float*)d_in[8];
    const float* qw   = (const float*)d_in[9];
    const float* qb   = (const float*)d_in[10];
    const float* kw   = (const float*)d_in[11];
    const float* kb   = (const float*)d_in[12];
    const float* vw   = (const float*)d_in[13];
    const float* vb   = (const float*)d_in[14];
    const float* fc1w = (const float*)d_in[15];
    const float* fc1b = (const float*)d_in[16];
    const float* fc2w = (const float*)d_in[17];
    const float* fc2b = (const float*)d_in[18];
    const float* gnfw = (const float*)d_in[19];
    const float* gnfb = (const float*)d_in[20];
    float* out = (float*)d_out;

    float *mem, *tgt, *tgt2, *tgt3, *q, *k, *v, *hin, *h, *fin;
    __nv_bfloat16 *bxhi, *bxlo, *memhi, *memlo, *whi, *wlo;
    cudaGetSymbolAddress((void**)&mem,  g_mem);
    cudaGetSymbolAddress((void**)&tgt,  g_tgt);
    cudaGetSymbolAddress((void**)&tgt2, g_tgt2);
    cudaGetSymbolAddress((void**)&tgt3, g_tgt3);
    cudaGetSymbolAddress((void**)&q,    g_q);
    cudaGetSymbolAddress((void**)&k,    g_k);
    cudaGetSymbolAddress((void**)&v,    g_v);
    cudaGetSymbolAddress((void**)&hin,  g_hin);
    cudaGetSymbolAddress((void**)&h,    g_h);
    cudaGetSymbolAddress((void**)&fin,  g_fin);
    cudaGetSymbolAddress((void**)&bxhi, g_bxhi);
    cudaGetSymbolAddress((void**)&bxlo, g_bxlo);
    cudaGetSymbolAddress((void**)&memhi,g_memhi);
    cudaGetSymbolAddress((void**)&memlo,g_memlo);
    cudaGetSymbolAddress((void**)&whi,  g_whi);
    cudaGetSymbolAddress((void**)&wlo,  g_wlo);

    const int SM_GN   = 131072;
    const int SM_ATTN = 198656;
    const int SM_CONV = 135168;
    const int SM_TC   = 73728;
    cudaFuncSetAttribute(gn_kernel,      cudaFuncAttributeMaxDynamicSharedMemorySize, SM_GN);
    cudaFuncSetAttribute(attn_kernel,    cudaFuncAttributeMaxDynamicSharedMemorySize, SM_ATTN);
    cudaFuncSetAttribute(conv_x_kernel,  cudaFuncAttributeMaxDynamicSharedMemorySize, SM_CONV);
    cudaFuncSetAttribute(gemm_tc_kernel, cudaFuncAttributeMaxDynamicSharedMemorySize, SM_TC);

    partition_kernel<<<65536, 256>>>(src, mem);
    partition_kernel<<<65536, 256>>>(qf, tgt);

    // weight prep: per-layer offsets into whi/wlo (elements):
    // q 0, k 65536, v 131072, fc1 196608, fc2 327680; layer stride 458752
    for (int l = 0; l < 2; ++l) {
        size_t lb = (size_t)l * 458752;
        conv_w_kernel<<<32, 256>>>(qw  + (size_t)l*65536,  whi + lb,          wlo + lb,          8192);
        conv_w_kernel<<<32, 256>>>(kw  + (size_t)l*65536,  whi + lb + 65536,  wlo + lb + 65536,  8192);
        conv_w_kernel<<<32, 256>>>(vw  + (size_t)l*65536,  whi + lb + 131072, wlo + lb + 131072, 8192);
        conv_w_kernel<<<64, 256>>>(fc1w+ (size_t)l*131072, whi + lb + 196608, wlo + lb + 196608, 16384);
        conv_w_kernel<<<64, 256>>>(fc2w+ (size_t)l*131072, whi + lb + 327680, wlo + lb + 327680, 16384);
    }
    conv_x_kernel<<<NW, 256, SM_CONV>>>(mem, memhi, memlo, 256);

    for (int l = 0; l < 2; ++l) {
        int lC = l * CDIM;
        size_t lb = (size_t)l * 458752;
        gn_kernel<<<NW, 256, SM_GN>>>(tgt, tgt, gn1w + lC, gn1b + lC, ls1 + lC, tgt2, 1);
        conv_x_kernel<<<NW, 256, SM_CONV>>>(tgt, bxhi, bxlo, 256);
        gemm_tc_kernel<<<dim3(NW,2), 256, SM_TC>>>(whi + lb,          wlo + lb,          bxhi,  bxlo,  qb + lC, q, 256, 256, 0, nullptr, nullptr);
        gemm_tc_kernel<<<dim3(NW,2), 256, SM_TC>>>(whi + lb + 65536,  wlo + lb + 65536,  memhi, memlo, kb + lC, k, 256, 256, 0, nullptr, nullptr);
        gemm_tc_kernel<<<dim3(NW,2), 256, SM_TC>>>(whi + lb + 131072, wlo + lb + 131072, memhi, memlo, vb + lC, v, 256, 256, 0, nullptr, nullptr);
        attn_kernel<<<NW, 256, SM_ATTN>>>(q, k, v, tgt2, tgt3);
        gn_kernel<<<NW, 256, SM_GN>>>(tgt3, tgt2, gn1w + lC, gn1b + lC, ls2 + lC, tgt3, 1);
        gn_kernel<<<NW, 256, SM_GN>>>(tgt3, nullptr, gn2w + lC, gn2b + lC, nullptr, hin, 0);
        conv_x_kernel<<<NW, 256, SM_CONV>>>(hin, bxhi, bxlo, 256);
        gemm_tc_kernel<<<dim3(NW,4), 256, SM_TC>>>(whi + lb + 196608, wlo + lb + 196608, bxhi, bxlo, fc1b + (size_t)l*512, h, 512, 256, 1, nullptr, nullptr);
        conv_x_kernel<<<NW, 256, SM_CONV>>>(h, bxhi, bxlo, 512);
        gemm_tc_kernel<<<dim3(NW,2), 256, SM_TC>>>(whi + lb + 327680, wlo + lb + 327680, bxhi, bxlo, fc2b + lC, tgt, 256, 512, 2, tgt3, ls3 + lC);
    }

    gn_kernel<<<NW, 256, SM_GN>>>(tgt, nullptr, gnfw, gnfb, nullptr, fin, 0);
    scatter_kernel<<<65536, 256>>>(fin, out);
}

// round 5
// speedup vs baseline: 2.9952x; 1.3969x over previous
#include <cuda_runtime.h>
#include <cuda_bf16.h>
#include <math.h>
#include <stdint.h>

#define NW   512
#define CDIM 256
#define PDIM 128
#define WSZ  (CDIM*PDIM)

// ---------------- scratch (static device globals; no allocations) ----------
__device__ float g_tgt [NW*WSZ];
__device__ float g_tgt2[NW*WSZ];
__device__ float g_tgt3[NW*WSZ];
__device__ float g_fin [NW*WSZ];
__device__ __nv_bfloat16 g_memhi[NW*WSZ], g_memlo[NW*WSZ];
__device__ __nv_bfloat16 g_tgthi[NW*WSZ], g_tgtlo[NW*WSZ];
__device__ __nv_bfloat16 g_qhi [NW*WSZ], g_qlo [NW*WSZ];
__device__ __nv_bfloat16 g_khi [NW*WSZ], g_klo [NW*WSZ];
__device__ __nv_bfloat16 g_vhi [NW*WSZ], g_vlo [NW*WSZ];
__device__ __nv_bfloat16 g_hinhi[NW*WSZ], g_hinlo[NW*WSZ];
__device__ __nv_bfloat16 g_hhi [NW*2*WSZ], g_hlo [NW*2*WSZ];
__device__ __nv_bfloat16 g_whi[2*458752], g_wlo[2*458752];

// ================= helpers =================================================
__device__ __forceinline__ uint32_t smem_u32(const void* p) {
    uint32_t a;
    asm("{ .reg .u64 t; cvta.to.shared.u64 t, %1; cvt.u32.u64 %0, t; }" : "=r"(a) : "l"(p));
    return a;
}
#define LDSM_X4(r0,r1,r2,r3,addr) \
    asm volatile("ldmatrix.sync.aligned.m8n8.x4.shared.b16 {%0,%1,%2,%3}, [%4];" \
        : "=r"(r0),"=r"(r1),"=r"(r2),"=r"(r3) : "r"(addr))
#define LDSM_X4_T(r0,r1,r2,r3,addr) \
    asm volatile("ldmatrix.sync.aligned.m8n8.x4.trans.shared.b16 {%0,%1,%2,%3}, [%4];" \
        : "=r"(r0),"=r"(r1),"=r"(r2),"=r"(r3) : "r"(addr))
__device__ __forceinline__ void mma_bf16(float* d, const unsigned* a, const unsigned* b) {
    asm volatile("mma.sync.aligned.m16n8k16.row.col.f32.bf16.bf16.f32 "
        "{%0,%1,%2,%3}, {%4,%5,%6,%7}, {%8,%9}, {%0,%1,%2,%3};"
        : "+f"(d[0]),"+f"(d[1]),"+f"(d[2]),"+f"(d[3])
        : "r"(a[0]),"r"(a[1]),"r"(a[2]),"r"(a[3]), "r"(b[0]),"r"(b[1]));
}
__device__ __forceinline__ void split2(float a, float b, unsigned& h, unsigned& l) {
    __nv_bfloat16 ah = __float2bfloat16(a);
    __nv_bfloat16 bh = __float2bfloat16(b);
    __nv_bfloat16 al = __float2bfloat16(a - __bfloat162float(ah));
    __nv_bfloat16 bl = __float2bfloat16(b - __bfloat162float(bh));
    h = (unsigned)__bfloat16_as_ushort(ah) | ((unsigned)__bfloat16_as_ushort(bh) << 16);
    l = (unsigned)__bfloat16_as_ushort(al) | ((unsigned)__bfloat16_as_ushort(bl) << 16);
}

// ---------------- partition: [B,C,H,W] -> flat window layout ---------------
__global__ void partition_kernel(const float* __restrict__ src, __nv_bfloat16* __restrict__ hi,
                                 __nv_bfloat16* __restrict__ lo, float* __restrict__ fout) {
    int g = blockIdx.x * 256 + threadIdx.x;     // pair index
    int idx = g * 2;
    int p = idx & 127, c = (idx >> 7) & 255, bw = idx >> 15;
    int b = bw >> 7, wblk = bw & 127;
    int h = (wblk >> 3) * 8 + (p >> 4), w = (wblk & 7) * 16 + (p & 15);
    const float* s = src + (((size_t)b * 256 + c) * 128 + h) * 128 + w;
    float a0 = s[0], a1 = s[1];
    unsigned hh, ll; split2(a0, a1, hh, ll);
    *(unsigned*)(hi + idx) = hh;
    *(unsigned*)(lo + idx) = ll;
    if (fout) *(float2*)(fout + idx) = make_float2(a0, a1);
}

// final gather: out[1,N,B,C] <- fin windows
__global__ void scatter_kernel(const float* __restrict__ fin, float* __restrict__ out) {
    int idx = blockIdx.x * 256 + threadIdx.x;
    int c = idx & 255, b = (idx >> 8) & 3, n = idx >> 10;
    int h = n >> 7, w = n & 127;
    int win = b * 128 + (h >> 3) * 8 + (w >> 4);
    int p = (h & 7) * 16 + (w & 15);
    out[idx] = fin[(size_t)win * WSZ + c * 128 + p];
}

// ---------------- weights: W[O,CIN] fp32 -> hi/lo bf16 same layout ----------
__global__ void conv_w_kernel(const float* __restrict__ W, __nv_bfloat16* __restrict__ hi,
                              __nv_bfloat16* __restrict__ lo, int total8) {
    int g = blockIdx.x * 256 + threadIdx.x;
    if (g >= total8) return;
    const float* src = W + (size_t)g * 8;
    unsigned hh[4], ll[4];
#pragma unroll
    for (int j = 0; j < 4; ++j) split2(src[2*j], src[2*j+1], hh[j], ll[j]);
    uint4 vh = {hh[0], hh[1], hh[2], hh[3]};
    uint4 vl = {ll[0], ll[1], ll[2], ll[3]};
    ((uint4*)hi)[g] = vh;
    ((uint4*)lo)[g] = vl;
}

// ---------------- tensor-core GEMM -----------------------------------------
// Y[win,o,p] = sum_c W[o][c] * X[win][c][p]; X consumed flat via ldmatrix.trans.
// mode 0: bf16 out (+bias)  1: bf16 out gelu(.+bias)  2: fp32+bf16 out, base+ls*(.)
__global__ __launch_bounds__(256, 2)
void gemm_tc_kernel(const __nv_bfloat16* __restrict__ Whi, const __nv_bfloat16* __restrict__ Wlo,
                    const __nv_bfloat16* __restrict__ Xhi, const __nv_bfloat16* __restrict__ Xlo,
                    const float* __restrict__ bias,
                    float* __restrict__ Yf, __nv_bfloat16* __restrict__ Yhi,
                    __nv_bfloat16* __restrict__ Ylo,
                    int O, int CIN, int mode,
                    const float* __restrict__ base, const float* __restrict__ ls) {
    extern __shared__ __nv_bfloat16 sb[];
    __nv_bfloat16* sWhi = sb;                 // [128][72]
    __nv_bfloat16* sWlo = sb + 9216;
    __nv_bfloat16* sXhi = sb + 18432;         // [64][136]
    __nv_bfloat16* sXlo = sb + 27136;
    int win = blockIdx.x, ob = blockIdx.y;
    int tid = threadIdx.x, lane = tid & 31, wid = tid >> 5;
    int wr = wid >> 1, wc = wid & 1;

    const __nv_bfloat16* gWhi = Whi + (size_t)ob * 128 * CIN;
    const __nv_bfloat16* gWlo = Wlo + (size_t)ob * 128 * CIN;
    const uint4* gXhi4 = (const uint4*)Xhi + (size_t)win * CIN * 16;
    const uint4* gXlo4 = (const uint4*)Xlo + (size_t)win * CIN * 16;

    float acc[2][8][4];
#pragma unroll
    for (int mt = 0; mt < 2; ++mt)
#pragma unroll
        for (int nt = 0; nt < 8; ++nt)
#pragma unroll
            for (int e = 0; e < 4; ++e) acc[mt][nt][e] = 0.f;

    int aRow = (lane & 15), aCol = (lane >> 4) * 8;
    int brbase = ((lane >> 3) & 1) * 8 + (lane & 7);
    int bcofs  = (lane >> 4) * 8;

    for (int kc = 0; kc < CIN; kc += 64) {
        __syncthreads();
#pragma unroll
        for (int i = tid; i < 1024; i += 256) {      // W tiles: 128 rows x 8 uint4
            int r = i >> 3, c4 = i & 7;
            size_t go = (size_t)r * CIN + kc + c4 * 8;
            int so = r * 72 + c4 * 8;
            *(uint4*)(sWhi + so) = *(const uint4*)(gWhi + go);
            *(uint4*)(sWlo + so) = *(const uint4*)(gWlo + go);
        }
#pragma unroll
        for (int i = tid; i < 1024; i += 256) {      // X tiles: 64 rows x 16 uint4
            int r = i >> 4, c4 = i & 15;
            int gi = (kc + r) * 16 + c4;
            int so = r * 136 + c4 * 8;
            *(uint4*)(sXhi + so) = gXhi4[gi];
            *(uint4*)(sXlo + so) = gXlo4[gi];
        }
        __syncthreads();
#pragma unroll
        for (int ks = 0; ks < 4; ++ks) {
            unsigned aHi[2][4], aLo[2][4];
#pragma unroll
            for (int mt = 0; mt < 2; ++mt) {
                int ro = (wr * 32 + mt * 16 + aRow) * 72 + ks * 16 + aCol;
                LDSM_X4(aHi[mt][0], aHi[mt][1], aHi[mt][2], aHi[mt][3], smem_u32(sWhi + ro));
                LDSM_X4(aLo[mt][0], aLo[mt][1], aLo[mt][2], aLo[mt][3], smem_u32(sWlo + ro));
            }
#pragma unroll
            for (int np = 0; np < 4; ++np) {
                int bo = (ks * 16 + brbase) * 136 + wc * 64 + np * 16 + bcofs;
                unsigned bHi[4], bLo[4];
                LDSM_X4_T(bHi[0], bHi[1], bHi[2], bHi[3], smem_u32(sXhi + bo));
                LDSM_X4_T(bLo[0], bLo[1], bLo[2], bLo[3], smem_u32(sXlo + bo));
#pragma unroll
                for (int mt = 0; mt < 2; ++mt) {
                    mma_bf16(acc[mt][np*2],   aHi[mt], bHi);
                    mma_bf16(acc[mt][np*2+1], aHi[mt], bHi + 2);
                    mma_bf16(acc[mt][np*2],   aHi[mt], bLo);
                    mma_bf16(acc[mt][np*2+1], aHi[mt], bLo + 2);
                    mma_bf16(acc[mt][np*2],   aLo[mt], bHi);
                    mma_bf16(acc[mt][np*2+1], aLo[mt], bHi + 2);
                }
            }
        }
    }

    int O0 = ob * 128;
#pragma unroll
    for (int mt = 0; mt < 2; ++mt)
#pragma unroll
        for (int nt = 0; nt < 8; ++nt) {
            int p = wc * 64 + nt * 8 + (lane & 3) * 2;
#pragma unroll
            for (int half = 0; half < 2; ++half) {
                int o = O0 + wr * 32 + mt * 16 + (lane >> 2) + half * 8;
                float bv = bias[o];
                float2 v;
                v.x = acc[mt][nt][half * 2]     + bv;
                v.y = acc[mt][nt][half * 2 + 1] + bv;
                size_t gi = ((size_t)win * O + o) * 128 + p;
                if (mode == 1) {
                    v.x = 0.5f * v.x * (1.f + erff(v.x * 0.70710678118654752f));
                    v.y = 0.5f * v.y * (1.f + erff(v.y * 0.70710678118654752f));
                } else if (mode == 2) {
                    float lsv = ls[o];
                    float2 b2 = *(const float2*)(base + gi);
                    v.x = b2.x + lsv * v.x;
                    v.y = b2.y + lsv * v.y;
                    *(float2*)(Yf + gi) = v;
                }
                unsigned hh, ll; split2(v.x, v.y, hh, ll);
                *(unsigned*)(Yhi + gi) = hh;
                *(unsigned*)(Ylo + gi) = ll;
            }
        }
}

// ---------------- attention: tensor-core, raw-reshape semantics -------------
__global__ __launch_bounds__(256, 1)
void attn_kernel(const __nv_bfloat16* __restrict__ Qhi, const __nv_bfloat16* __restrict__ Qlo,
                 const __nv_bfloat16* __restrict__ Khi, const __nv_bfloat16* __restrict__ Klo,
                 const __nv_bfloat16* __restrict__ Vhi, const __nv_bfloat16* __restrict__ Vlo,
                 const float* __restrict__ tgt2, float* __restrict__ tgt3) {
    extern __shared__ __nv_bfloat16 sat[];
    __nv_bfloat16* sQh = sat;                 // [128][136]
    __nv_bfloat16* sQl = sat + 17408;
    __nv_bfloat16* sKh = sat + 34816;
    __nv_bfloat16* sKl = sat + 52224;
    int win = blockIdx.x, tid = threadIdx.x, lane = tid & 31, wid = tid >> 5;

    const uint4* gQh = (const uint4*)Qhi + (size_t)win * 4096;
    const uint4* gQl = (const uint4*)Qlo + (size_t)win * 4096;
    const uint4* gKh = (const uint4*)Khi + (size_t)win * 4096;
    const uint4* gKl = (const uint4*)Klo + (size_t)win * 4096;
    const uint4* gVh = (const uint4*)Vhi + (size_t)win * 4096;
    const uint4* gVl = (const uint4*)Vlo + (size_t)win * 4096;

    float acc[16][4];
#pragma unroll
    for (int j = 0; j < 16; ++j)
#pragma unroll
        for (int e = 0; e < 4; ++e) acc[j][e] = 0.f;

    int aRow = lane & 15, aCol = (lane >> 4) * 8;
    int kRow = (lane & 7) + ((lane >> 4) & 1) * 8;
    int kCol = ((lane >> 3) & 1) * 8;
    int tRow = ((lane >> 3) & 1) * 8 + (lane & 7);
    int tCol = (lane >> 4) * 8;

    // ---- S = Qv @ Kv^T over 2 cq chunks (each 128 rows x 16 uint4) ----
    for (int ch = 0; ch < 2; ++ch) {
        __syncthreads();
#pragma unroll
        for (int i = tid; i < 2048; i += 256) {
            int r = i >> 4, c4 = i & 15;
            int gi = r * 32 + ch * 16 + c4;
            int so = r * 136 + c4 * 8;
            *(uint4*)(sQh + so) = gQh[gi];
            *(uint4*)(sQl + so) = gQl[gi];
            *(uint4*)(sKh + so) = gKh[gi];
            *(uint4*)(sKl + so) = gKl[gi];
        }
        __syncthreads();
#pragma unroll
        for (int ks = 0; ks < 8; ++ks) {
            unsigned aHi[4], aLo[4];
            int ro = (wid * 16 + aRow) * 136 + ks * 16 + aCol;
            LDSM_X4(aHi[0], aHi[1], aHi[2], aHi[3], smem_u32(sQh + ro));
            LDSM_X4(aLo[0], aLo[1], aLo[2], aLo[3], smem_u32(sQl + ro));
#pragma unroll
            for (int ng = 0; ng < 8; ++ng) {
                int bo = (ng * 16 + kRow) * 136 + ks * 16 + kCol;
                unsigned bHi[4], bLo[4];
                LDSM_X4(bHi[0], bHi[1], bHi[2], bHi[3], smem_u32(sKh + bo));
                LDSM_X4(bLo[0], bLo[1], bLo[2], bLo[3], smem_u32(sKl + bo));
                mma_bf16(acc[ng*2],   aHi, bHi);
                mma_bf16(acc[ng*2+1], aHi, bHi + 2);
                mma_bf16(acc[ng*2],   aHi, bLo);
                mma_bf16(acc[ng*2+1], aHi, bLo + 2);
                mma_bf16(acc[ng*2],   aLo, bHi);
                mma_bf16(acc[ng*2+1], aLo, bHi + 2);
            }
        }
    }

    // ---- softmax ----
    float mx0 = -1e30f, mx1 = -1e30f;
#pragma unroll
    for (int j = 0; j < 16; ++j) {
        mx0 = fmaxf(mx0, fmaxf(acc[j][0], acc[j][1]));
        mx1 = fmaxf(mx1, fmaxf(acc[j][2], acc[j][3]));
    }
#pragma unroll
    for (int off = 1; off <= 2; off <<= 1) {
        mx0 = fmaxf(mx0, __shfl_xor_sync(0xffffffffu, mx0, off));
        mx1 = fmaxf(mx1, __shfl_xor_sync(0xffffffffu, mx1, off));
    }
    float s0 = 0.f, s1 = 0.f;
#pragma unroll
    for (int j = 0; j < 16; ++j) {
        acc[j][0] = expf(acc[j][0] - mx0); s0 += acc[j][0];
        acc[j][1] = expf(acc[j][1] - mx0); s0 += acc[j][1];
        acc[j][2] = expf(acc[j][2] - mx1); s1 += acc[j][2];
        acc[j][3] = expf(acc[j][3] - mx1); s1 += acc[j][3];
    }
#pragma unroll
    for (int off = 1; off <= 2; off <<= 1) {
        s0 += __shfl_xor_sync(0xffffffffu, s0, off);
        s1 += __shfl_xor_sync(0xffffffffu, s1, off);
    }
    float i0 = 1.f / s0, i1 = 1.f / s1;
#pragma unroll
    for (int j = 0; j < 16; ++j) {
        acc[j][0] *= i0; acc[j][1] *= i0;
        acc[j][2] *= i1; acc[j][3] *= i1;
    }

    // ---- pack P into bf16 hi/lo a-fragments ----
    unsigned phi[8][4], plo[8][4];
#pragma unroll
    for (int t = 0; t < 8; ++t) {
        split2(acc[2*t][0],   acc[2*t][1],   phi[t][0], plo[t][0]);
        split2(acc[2*t][2],   acc[2*t][3],   phi[t][1], plo[t][1]);
        split2(acc[2*t+1][0], acc[2*t+1][1], phi[t][2], plo[t][2]);
        split2(acc[2*t+1][2], acc[2*t+1][3], phi[t][3], plo[t][3]);
    }

    // ---- O = P @ Vv over 2 cv chunks ----
    __nv_bfloat16* sVh = sat;
    __nv_bfloat16* sVl = sat + 17408;
    for (int cv = 0; cv < 2; ++cv) {
        __syncthreads();
#pragma unroll
        for (int i = tid; i < 2048; i += 256) {
            int r = i >> 4, c4 = i & 15;
            int gi = r * 32 + cv * 16 + c4;
            int so = r * 136 + c4 * 8;
            *(uint4*)(sVh + so) = gVh[gi];
            *(uint4*)(sVl + so) = gVl[gi];
        }
        __syncthreads();
        float oacc[16][4];
#pragma unroll
        for (int j = 0; j < 16; ++j)
#pragma unroll
            for (int e = 0; e < 4; ++e) oacc[j][e] = 0.f;
#pragma unroll
        for (int mk = 0; mk < 8; ++mk) {
#pragma unroll
            for (int ng = 0; ng < 8; ++ng) {
                int bo = (mk * 16 + tRow) * 136 + ng * 16 + tCol;
                unsigned vH[4], vL[4];
                LDSM_X4_T(vH[0], vH[1], vH[2], vH[3], smem_u32(sVh + bo));
                LDSM_X4_T(vL[0], vL[1], vL[2], vL[3], smem_u32(sVl + bo));
                mma_bf16(oacc[ng*2],   phi[mk], vH);
                mma_bf16(oacc[ng*2+1], phi[mk], vH + 2);
                mma_bf16(oacc[ng*2],   phi[mk], vL);
                mma_bf16(oacc[ng*2+1], phi[mk], vL + 2);
                mma_bf16(oacc[ng*2],   plo[mk], vH);
                mma_bf16(oacc[ng*2+1], plo[mk], vH + 2);
            }
        }
#pragma unroll
        for (int j = 0; j < 16; ++j) {
            int col = cv * 128 + j * 8 + (lane & 3) * 2;
            int n0 = wid * 16 + (lane >> 2);
            size_t gi = (size_t)win * WSZ + n0 * 256 + col;
            float2 b0 = *(const float2*)(tgt2 + gi);
            float2 r0 = {b0.x + oacc[j][0], b0.y + oacc[j][1]};
            *(float2*)(tgt3 + gi) = r0;
            size_t gi1 = gi + 8 * 256;
            float2 b1 = *(const float2*)(tgt2 + gi1);
            float2 r1 = {b1.x + oacc[j][2], b1.y + oacc[j][3]};
            *(float2*)(tgt3 + gi1) = r1;
        }
    }
}

// ---------------- GroupNorm(1 group) ---------------------------------------
// mode 0: plain -> fp32   mode 1: mix+residual -> fp32   mode 2: plain -> bf16 hi/lo
__global__ __launch_bounds__(256)
void gn_kernel(const float* __restrict__ in, const float* __restrict__ base,
               const float* __restrict__ gw, const float* __restrict__ gb,
               const float* __restrict__ ls, float* __restrict__ outf,
               __nv_bfloat16* __restrict__ outhi, __nv_bfloat16* __restrict__ outlo,
               int mode) {
    extern __shared__ float sm[];
    __shared__ float red[16];
    __shared__ float stats[2];
    int win = blockIdx.x, tid = threadIdx.x;
    const float4* xin = (const float4*)(in + (size_t)win * WSZ);
    float4* s4 = (float4*)sm;

    float s = 0.f, sq = 0.f;
#pragma unroll
    for (int k = 0; k < 32; ++k) {
        float4 v = xin[tid + k * 256];
        s4[tid + k * 256] = v;
        s  += v.x + v.y + v.z + v.w;
        sq += v.x*v.x + v.y*v.y + v.z*v.z + v.w*v.w;
    }
#pragma unroll
    for (int off = 16; off; off >>= 1) {
        s  += __shfl_down_sync(0xffffffffu, s,  off);
        sq += __shfl_down_sync(0xffffffffu, sq, off);
    }
    if ((tid & 31) == 0) { red[tid >> 5] = s; red[8 + (tid >> 5)] = sq; }
    __syncthreads();
    if (tid == 0) {
        float ts = 0.f, tq = 0.f;
        for (int i = 0; i < 8; ++i) { ts += red[i]; tq += red[8 + i]; }
        float mean = ts * (1.f / 32768.f);
        float var  = tq * (1.f / 32768.f) - mean * mean;
        stats[0] = mean; stats[1] = rsqrtf(var + 1e-5f);
    }
    __syncthreads();
    float mean = stats[0], rstd = stats[1];

#pragma unroll
    for (int k = 0; k < 32; ++k) {
        int f = tid + k * 256;
        int c = f >> 5;
        float w = gw[c], bb = gb[c];
        float4 v = s4[f];
        v.x = (v.x - mean) * rstd * w + bb;
        v.y = (v.y - mean) * rstd * w + bb;
        v.z = (v.z - mean) * rstd * w + bb;
        v.w = (v.w - mean) * rstd * w + bb;
        s4[f] = v;
    }
    __syncthreads();

    if (mode == 0) {
#pragma unroll
        for (int k = 0; k < 32; ++k) {
            int f = tid + k * 256;
            ((float4*)(outf + (size_t)win * WSZ))[f] = s4[f];
        }
    } else if (mode == 2) {
#pragma unroll
        for (int k = 0; k < 32; ++k) {
            int f = tid + k * 256;
            float4 v = s4[f];
            unsigned h0, l0, h1, l1;
            split2(v.x, v.y, h0, l0);
            split2(v.z, v.w, h1, l1);
            uint2 vh = {h0, h1}, vl = {l0, l1};
            *(uint2*)(outhi + (size_t)win * WSZ + f * 4) = vh;
            *(uint2*)(outlo + (size_t)win * WSZ + f * 4) = vl;
        }
    } else {
        const float4* bs4 = (const float4*)(base + (size_t)win * WSZ);
#pragma unroll 8
        for (int k = 0; k < 32; ++k) {
            int f = tid + k * 256;
            int c = f >> 5;
            int p0 = (f & 31) * 4;
            float lsv = ls[c];
            const float* ch = sm + c * 128;
            float4 bv = bs4[f];
            float o[4];
#pragma unroll
            for (int e = 0; e < 4; ++e) {
                int p = p0 + e, y = p >> 4, x = p & 15;
                float sum = 0.f; int cnt = 0;
#pragma unroll
                for (int dy = -1; dy <= 1; ++dy) {
                    int ny = y + dy;
                    if (ny < 0 || ny > 7) continue;
#pragma unroll
                    for (int dx = -1; dx <= 1; ++dx) {
                        int nx = x + dx;
                        if (nx < 0 || nx > 15) continue;
                        sum += ch[ny * 16 + nx]; cnt++;
                    }
                }
                o[e] = sum / (float)cnt - ch[p];
            }
            float4 ov;
            ov.x = bv.x + lsv * o[0];
            ov.y = bv.y + lsv * o[1];
            ov.z = bv.z + lsv * o[2];
            ov.w = bv.w + lsv * o[3];
            ((float4*)(outf + (size_t)win * WSZ))[f] = ov;
        }
    }
}

// ---------------- host orchestration ---------------------------------------
extern "C" void kernel_launch(void* const* d_in, const int* in_sizes, int n_in,
                              void* d_out, int out_size) {
    const float* src  = (const float*)d_in[0];
    const float* qf   = (const float*)d_in[1];
    const float* gn1w = (const float*)d_in[2];
    const float* gn1b = (const float*)d_in[3];
    const float* gn2w = (const float*)d_in[4];
    const float* gn2b = (const float*)d_in[5];
    const float* ls1  = (const float*)d_in[6];
    const float* ls2  = (const float*)d_in[7];
    const float* ls3  = (const float*)d_in[8];
    const float* qw   = (const float*)d_in[9];
    const float* qb   = (const float*)d_in[10];
    const float* kw   = (const float*)d_in[11];
    const float* kb   = (const float*)d_in[12];
    const float* vw   = (const float*)d_in[13];
    const float* vb   = (const float*)d_in[14];
    const float* fc1w = (const float*)d_in[15];
    const float* fc1b = (const float*)d_in[16];
    const float* fc2w = (const float*)d_in[17];
    const float* fc2b = (const float*)d_in[18];
    const float* gnfw = (const float*)d_in[19];
    const float* gnfb = (const float*)d_in[20];
    float* out = (float*)d_out;

    float *tgt, *tgt2, *tgt3, *fin;
    __nv_bfloat16 *memhi, *memlo, *tgthi, *tgtlo, *qhi, *qlo, *khi, *klo, *vhi, *vlo;
    __nv_bfloat16 *hinhi, *hinlo, *hhi, *hlo, *whi, *wlo;
    cudaGetSymbolAddress((void**)&tgt,  g_tgt);
    cudaGetSymbolAddress((void**)&tgt2, g_tgt2);
    cudaGetSymbolAddress((void**)&tgt3, g_tgt3);
    cudaGetSymbolAddress((void**)&fin,  g_fin);
    cudaGetSymbolAddress((void**)&memhi,g_memhi);
    cudaGetSymbolAddress((void**)&memlo,g_memlo);
    cudaGetSymbolAddress((void**)&tgthi,g_tgthi);
    cudaGetSymbolAddress((void**)&tgtlo,g_tgtlo);
    cudaGetSymbolAddress((void**)&qhi,  g_qhi);
    cudaGetSymbolAddress((void**)&qlo,  g_qlo);
    cudaGetSymbolAddress((void**)&khi,  g_khi);
    cudaGetSymbolAddress((void**)&klo,  g_klo);
    cudaGetSymbolAddress((void**)&vhi,  g_vhi);
    cudaGetSymbolAddress((void**)&vlo,  g_vlo);
    cudaGetSymbolAddress((void**)&hinhi,g_hinhi);
    cudaGetSymbolAddress((void**)&hinlo,g_hinlo);
    cudaGetSymbolAddress((void**)&hhi,  g_hhi);
    cudaGetSymbolAddress((void**)&hlo,  g_hlo);
    cudaGetSymbolAddress((void**)&whi,  g_whi);
    cudaGetSymbolAddress((void**)&wlo,  g_wlo);

    const int SM_GN   = 131072;
    const int SM_ATTN = 139264;
    const int SM_TC   = 71680;
    cudaFuncSetAttribute(gn_kernel,      cudaFuncAttributeMaxDynamicSharedMemorySize, SM_GN);
    cudaFuncSetAttribute(attn_kernel,    cudaFuncAttributeMaxDynamicSharedMemorySize, SM_ATTN);
    cudaFuncSetAttribute(gemm_tc_kernel, cudaFuncAttributeMaxDynamicSharedMemorySize, SM_TC);

    partition_kernel<<<32768, 256>>>(src, memhi, memlo, nullptr);
    partition_kernel<<<32768, 256>>>(qf, tgthi, tgtlo, tgt);

    for (int l = 0; l < 2; ++l) {
        size_t lb = (size_t)l * 458752;
        conv_w_kernel<<<32, 256>>>(qw  + (size_t)l*65536,  whi + lb,          wlo + lb,          8192);
        conv_w_kernel<<<32, 256>>>(kw  + (size_t)l*65536,  whi + lb + 65536,  wlo + lb + 65536,  8192);
        conv_w_kernel<<<32, 256>>>(vw  + (size_t)l*65536,  whi + lb + 131072, wlo + lb + 131072, 8192);
        conv_w_kernel<<<64, 256>>>(fc1w+ (size_t)l*131072, whi + lb + 196608, wlo + lb + 196608, 16384);
        conv_w_kernel<<<64, 256>>>(fc2w+ (size_t)l*131072, whi + lb + 327680, wlo + lb + 327680, 16384);
    }

    for (int l = 0; l < 2; ++l) {
        int lC = l * CDIM;
        size_t lb = (size_t)l * 458752;
        gn_kernel<<<NW, 256, SM_GN>>>(tgt, tgt, gn1w + lC, gn1b + lC, ls1 + lC, tgt2, nullptr, nullptr, 1);
        gemm_tc_kernel<<<dim3(NW,2), 256, SM_TC>>>(whi + lb,          wlo + lb,          tgthi, tgtlo, qb + lC, nullptr, qhi, qlo, 256, 256, 0, nullptr, nullptr);
        gemm_tc_kernel<<<dim3(NW,2), 256, SM_TC>>>(whi + lb + 65536,  wlo + lb + 65536,  memhi, memlo, kb + lC, nullptr, khi, klo, 256, 256, 0, nullptr, nullptr);
        gemm_tc_kernel<<<dim3(NW,2), 256, SM_TC>>>(whi + lb + 131072, wlo + lb + 131072, memhi, memlo, vb + lC, nullptr, vhi, vlo, 256, 256, 0, nullptr, nullptr);
        attn_kernel<<<NW, 256, SM_ATTN>>>(qhi, qlo, khi, klo, vhi, vlo, tgt2, tgt3);
        gn_kernel<<<NW, 256, SM_GN>>>(tgt3, tgt2, gn1w + lC, gn1b + lC, ls2 + lC, tgt3, nullptr, nullptr, 1);
        gn_kernel<<<NW, 256, SM_GN>>>(tgt3, nullptr, gn2w + lC, gn2b + lC, nullptr, nullptr, hinhi, hinlo, 2);
        gemm_tc_kernel<<<dim3(NW,4), 256, SM_TC>>>(whi + lb + 196608, wlo + lb + 196608, hinhi, hinlo, fc1b + (size_t)l*512, nullptr, hhi, hlo, 512, 256, 1, nullptr, nullptr);
        gemm_tc_kernel<<<dim3(NW,2), 256, SM_TC>>>(whi + lb + 327680, wlo + lb + 327680, hhi, hlo, fc2b + lC, tgt, tgthi, tgtlo, 256, 512, 2, tgt3, ls3 + lC);
    }

    gn_kernel<<<NW, 256, SM_GN>>>(tgt, nullptr, gnfw, gnfb, nullptr, fin, nullptr, nullptr, 0);
    scatter_kernel<<<65536, 256>>>(fin, out);
}

// round 6
// speedup vs baseline: 3.3305x; 1.1119x over previous
#include <cuda_runtime.h>
#include <cuda_bf16.h>
#include <math.h>
#include <stdint.h>

#define NW   512
#define CDIM 256
#define PDIM 128
#define WSZ  (CDIM*PDIM)

// ---------------- scratch (static device globals; no allocations) ----------
__device__ float g_tgt [NW*WSZ];
__device__ float g_tgt2[NW*WSZ];
__device__ float g_tgt3[NW*WSZ];
__device__ float g_fin [NW*WSZ];
__device__ __nv_bfloat16 g_memhi[NW*WSZ], g_memlo[NW*WSZ];
__device__ __nv_bfloat16 g_tgthi[NW*WSZ], g_tgtlo[NW*WSZ];
__device__ __nv_bfloat16 g_qhi [NW*WSZ], g_qlo [NW*WSZ];
__device__ __nv_bfloat16 g_khi [NW*WSZ], g_klo [NW*WSZ];
__device__ __nv_bfloat16 g_vhi [NW*WSZ], g_vlo [NW*WSZ];
__device__ __nv_bfloat16 g_hinhi[NW*WSZ], g_hinlo[NW*WSZ];
__device__ __nv_bfloat16 g_hhi [NW*2*WSZ], g_hlo [NW*2*WSZ];
__device__ __nv_bfloat16 g_whi[2*458752], g_wlo[2*458752];

// ================= helpers =================================================
__device__ __forceinline__ uint32_t smem_u32(const void* p) {
    uint32_t a;
    asm("{ .reg .u64 t; cvta.to.shared.u64 t, %1; cvt.u32.u64 %0, t; }" : "=r"(a) : "l"(p));
    return a;
}
#define LDSM_X4(r0,r1,r2,r3,addr) \
    asm volatile("ldmatrix.sync.aligned.m8n8.x4.shared.b16 {%0,%1,%2,%3}, [%4];" \
        : "=r"(r0),"=r"(r1),"=r"(r2),"=r"(r3) : "r"(addr))
#define LDSM_X4_T(r0,r1,r2,r3,addr) \
    asm volatile("ldmatrix.sync.aligned.m8n8.x4.trans.shared.b16 {%0,%1,%2,%3}, [%4];" \
        : "=r"(r0),"=r"(r1),"=r"(r2),"=r"(r3) : "r"(addr))
__device__ __forceinline__ void mma_bf16(float* d, const unsigned* a, const unsigned* b) {
    asm volatile("mma.sync.aligned.m16n8k16.row.col.f32.bf16.bf16.f32 "
        "{%0,%1,%2,%3}, {%4,%5,%6,%7}, {%8,%9}, {%0,%1,%2,%3};"
        : "+f"(d[0]),"+f"(d[1]),"+f"(d[2]),"+f"(d[3])
        : "r"(a[0]),"r"(a[1]),"r"(a[2]),"r"(a[3]), "r"(b[0]),"r"(b[1]));
}
__device__ __forceinline__ void split2(float a, float b, unsigned& h, unsigned& l) {
    __nv_bfloat16 ah = __float2bfloat16(a);
    __nv_bfloat16 bh = __float2bfloat16(b);
    __nv_bfloat16 al = __float2bfloat16(a - __bfloat162float(ah));
    __nv_bfloat16 bl = __float2bfloat16(b - __bfloat162float(bh));
    h = (unsigned)__bfloat16_as_ushort(ah) | ((unsigned)__bfloat16_as_ushort(bh) << 16);
    l = (unsigned)__bfloat16_as_ushort(al) | ((unsigned)__bfloat16_as_ushort(bl) << 16);
}

// block reduce (512 threads) -> stats[0]=mean, stats[1]=rstd
__device__ __forceinline__ void gn_reduce(float s, float sq, float* red, float* stats,
                                          int lane, int wid, int tid) {
#pragma unroll
    for (int off = 16; off; off >>= 1) {
        s  += __shfl_down_sync(0xffffffffu, s,  off);
        sq += __shfl_down_sync(0xffffffffu, sq, off);
    }
    if (lane == 0) { red[wid] = s; red[16 + wid] = sq; }
    __syncthreads();
    if (tid == 0) {
        float ts = 0.f, tq = 0.f;
#pragma unroll
        for (int i = 0; i < 16; ++i) { ts += red[i]; tq += red[16 + i]; }
        float mean = ts * (1.f / 32768.f);
        float var  = tq * (1.f / 32768.f) - mean * mean;
        stats[0] = mean; stats[1] = rsqrtf(var + 1e-5f);
    }
    __syncthreads();
}

// avgpool3(count_include_pad=False) - x on an 8x16 channel image in smem
__device__ __forceinline__ void mix4(const float* ch, int p0, float* o) {
#pragma unroll
    for (int e = 0; e < 4; ++e) {
        int p = p0 + e, y = p >> 4, x = p & 15;
        float sum = 0.f; int cnt = 0;
#pragma unroll
        for (int dy = -1; dy <= 1; ++dy) {
            int ny = y + dy;
            if (ny < 0 || ny > 7) continue;
#pragma unroll
            for (int dx = -1; dx <= 1; ++dx) {
                int nx = x + dx;
                if (nx < 0 || nx > 15) continue;
                sum += ch[ny * 16 + nx]; cnt++;
            }
        }
        o[e] = sum / (float)cnt - ch[p];
    }
}

// ---------------- partition: [B,C,H,W] -> flat window layout ---------------
__global__ void partition_kernel(const float* __restrict__ src, __nv_bfloat16* __restrict__ hi,
                                 __nv_bfloat16* __restrict__ lo, float* __restrict__ fout) {
    int g = blockIdx.x * 256 + threadIdx.x;
    int idx = g * 2;
    int p = idx & 127, c = (idx >> 7) & 255, bw = idx >> 15;
    int b = bw >> 7, wblk = bw & 127;
    int h = (wblk >> 3) * 8 + (p >> 4), w = (wblk & 7) * 16 + (p & 15);
    const float* s = src + (((size_t)b * 256 + c) * 128 + h) * 128 + w;
    float a0 = s[0], a1 = s[1];
    unsigned hh, ll; split2(a0, a1, hh, ll);
    *(unsigned*)(hi + idx) = hh;
    *(unsigned*)(lo + idx) = ll;
    if (fout) *(float2*)(fout + idx) = make_float2(a0, a1);
}

__global__ void scatter_kernel(const float* __restrict__ fin, float* __restrict__ out) {
    int idx = blockIdx.x * 256 + threadIdx.x;
    int c = idx & 255, b = (idx >> 8) & 3, n = idx >> 10;
    int h = n >> 7, w = n & 127;
    int win = b * 128 + (h >> 3) * 8 + (w >> 4);
    int p = (h & 7) * 16 + (w & 15);
    out[idx] = fin[(size_t)win * WSZ + c * 128 + p];
}

// ---------------- weights: W[O,CIN] fp32 -> hi/lo bf16 ----------------------
__global__ void conv_w_kernel(const float* __restrict__ W, __nv_bfloat16* __restrict__ hi,
                              __nv_bfloat16* __restrict__ lo, int total8) {
    int g = blockIdx.x * 256 + threadIdx.x;
    if (g >= total8) return;
    const float* src = W + (size_t)g * 8;
    unsigned hh[4], ll[4];
#pragma unroll
    for (int j = 0; j < 4; ++j) split2(src[2*j], src[2*j+1], hh[j], ll[j]);
    uint4 vh = {hh[0], hh[1], hh[2], hh[3]};
    uint4 vl = {ll[0], ll[1], ll[2], ll[3]};
    ((uint4*)hi)[g] = vh;
    ((uint4*)lo)[g] = vl;
}

// ---------------- tensor-core GEMM (unchanged from R5) ----------------------
__global__ __launch_bounds__(256, 2)
void gemm_tc_kernel(const __nv_bfloat16* __restrict__ Whi, const __nv_bfloat16* __restrict__ Wlo,
                    const __nv_bfloat16* __restrict__ Xhi, const __nv_bfloat16* __restrict__ Xlo,
                    const float* __restrict__ bias,
                    float* __restrict__ Yf, __nv_bfloat16* __restrict__ Yhi,
                    __nv_bfloat16* __restrict__ Ylo,
                    int O, int CIN, int mode,
                    const float* __restrict__ base, const float* __restrict__ ls) {
    extern __shared__ __nv_bfloat16 sb[];
    __nv_bfloat16* sWhi = sb;                 // [128][72]
    __nv_bfloat16* sWlo = sb + 9216;
    __nv_bfloat16* sXhi = sb + 18432;         // [64][136]
    __nv_bfloat16* sXlo = sb + 27136;
    int win = blockIdx.x, ob = blockIdx.y;
    int tid = threadIdx.x, lane = tid & 31, wid = tid >> 5;
    int wr = wid >> 1, wc = wid & 1;

    const __nv_bfloat16* gWhi = Whi + (size_t)ob * 128 * CIN;
    const __nv_bfloat16* gWlo = Wlo + (size_t)ob * 128 * CIN;
    const uint4* gXhi4 = (const uint4*)Xhi + (size_t)win * CIN * 16;
    const uint4* gXlo4 = (const uint4*)Xlo + (size_t)win * CIN * 16;

    float acc[2][8][4];
#pragma unroll
    for (int mt = 0; mt < 2; ++mt)
#pragma unroll
        for (int nt = 0; nt < 8; ++nt)
#pragma unroll
            for (int e = 0; e < 4; ++e) acc[mt][nt][e] = 0.f;

    int aRow = (lane & 15), aCol = (lane >> 4) * 8;
    int brbase = ((lane >> 3) & 1) * 8 + (lane & 7);
    int bcofs  = (lane >> 4) * 8;

    for (int kc = 0; kc < CIN; kc += 64) {
        __syncthreads();
#pragma unroll
        for (int i = tid; i < 1024; i += 256) {
            int r = i >> 3, c4 = i & 7;
            size_t go = (size_t)r * CIN + kc + c4 * 8;
            int so = r * 72 + c4 * 8;
            *(uint4*)(sWhi + so) = *(const uint4*)(gWhi + go);
            *(uint4*)(sWlo + so) = *(const uint4*)(gWlo + go);
        }
#pragma unroll
        for (int i = tid; i < 1024; i += 256) {
            int r = i >> 4, c4 = i & 15;
            int gi = (kc + r) * 16 + c4;
            int so = r * 136 + c4 * 8;
            *(uint4*)(sXhi + so) = gXhi4[gi];
            *(uint4*)(sXlo + so) = gXlo4[gi];
        }
        __syncthreads();
#pragma unroll
        for (int ks = 0; ks < 4; ++ks) {
            unsigned aHi[2][4], aLo[2][4];
#pragma unroll
            for (int mt = 0; mt < 2; ++mt) {
                int ro = (wr * 32 + mt * 16 + aRow) * 72 + ks * 16 + aCol;
                LDSM_X4(aHi[mt][0], aHi[mt][1], aHi[mt][2], aHi[mt][3], smem_u32(sWhi + ro));
                LDSM_X4(aLo[mt][0], aLo[mt][1], aLo[mt][2], aLo[mt][3], smem_u32(sWlo + ro));
            }
#pragma unroll
            for (int np = 0; np < 4; ++np) {
                int bo = (ks * 16 + brbase) * 136 + wc * 64 + np * 16 + bcofs;
                unsigned bHi[4], bLo[4];
                LDSM_X4_T(bHi[0], bHi[1], bHi[2], bHi[3], smem_u32(sXhi + bo));
                LDSM_X4_T(bLo[0], bLo[1], bLo[2], bLo[3], smem_u32(sXlo + bo));
#pragma unroll
                for (int mt = 0; mt < 2; ++mt) {
                    mma_bf16(acc[mt][np*2],   aHi[mt], bHi);
                    mma_bf16(acc[mt][np*2+1], aHi[mt], bHi + 2);
                    mma_bf16(acc[mt][np*2],   aHi[mt], bLo);
                    mma_bf16(acc[mt][np*2+1], aHi[mt], bLo + 2);
                    mma_bf16(acc[mt][np*2],   aLo[mt], bHi);
                    mma_bf16(acc[mt][np*2+1], aLo[mt], bHi + 2);
                }
            }
        }
    }

    int O0 = ob * 128;
#pragma unroll
    for (int mt = 0; mt < 2; ++mt)
#pragma unroll
        for (int nt = 0; nt < 8; ++nt) {
            int p = wc * 64 + nt * 8 + (lane & 3) * 2;
#pragma unroll
            for (int half = 0; half < 2; ++half) {
                int o = O0 + wr * 32 + mt * 16 + (lane >> 2) + half * 8;
                float bv = bias[o];
                float2 v;
                v.x = acc[mt][nt][half * 2]     + bv;
                v.y = acc[mt][nt][half * 2 + 1] + bv;
                size_t gi = ((size_t)win * O + o) * 128 + p;
                if (mode == 1) {
                    v.x = 0.5f * v.x * (1.f + erff(v.x * 0.70710678118654752f));
                    v.y = 0.5f * v.y * (1.f + erff(v.y * 0.70710678118654752f));
                } else if (mode == 2) {
                    float lsv = ls[o];
                    float2 b2 = *(const float2*)(base + gi);
                    v.x = b2.x + lsv * v.x;
                    v.y = b2.y + lsv * v.y;
                    *(float2*)(Yf + gi) = v;
                }
                unsigned hh, ll; split2(v.x, v.y, hh, ll);
                *(unsigned*)(Yhi + gi) = hh;
                *(unsigned*)(Ylo + gi) = ll;
            }
        }
}

// ---------------- attention (72KB smem -> 2 CTA/SM) -------------------------
__global__ __launch_bounds__(256, 2)
void attn_kernel(const __nv_bfloat16* __restrict__ Qhi, const __nv_bfloat16* __restrict__ Qlo,
                 const __nv_bfloat16* __restrict__ Khi, const __nv_bfloat16* __restrict__ Klo,
                 const __nv_bfloat16* __restrict__ Vhi, const __nv_bfloat16* __restrict__ Vlo,
                 const float* __restrict__ tgt2, float* __restrict__ tgt3) {
    extern __shared__ __nv_bfloat16 sat[];
    // S phase: 4 buffers of [128][72]
    __nv_bfloat16* sQh = sat;
    __nv_bfloat16* sQl = sat + 9216;
    __nv_bfloat16* sKh = sat + 18432;
    __nv_bfloat16* sKl = sat + 27648;
    int win = blockIdx.x, tid = threadIdx.x, lane = tid & 31, wid = tid >> 5;

    const uint4* gQh = (const uint4*)Qhi + (size_t)win * 4096;
    const uint4* gQl = (const uint4*)Qlo + (size_t)win * 4096;
    const uint4* gKh = (const uint4*)Khi + (size_t)win * 4096;
    const uint4* gKl = (const uint4*)Klo + (size_t)win * 4096;
    const uint4* gVh = (const uint4*)Vhi + (size_t)win * 4096;
    const uint4* gVl = (const uint4*)Vlo + (size_t)win * 4096;

    float acc[16][4];
#pragma unroll
    for (int j = 0; j < 16; ++j)
#pragma unroll
        for (int e = 0; e < 4; ++e) acc[j][e] = 0.f;

    int aRow = lane & 15, aCol = (lane >> 4) * 8;
    int kRow = (lane & 7) + ((lane >> 4) & 1) * 8;
    int kCol = ((lane >> 3) & 1) * 8;
    int tRow = ((lane >> 3) & 1) * 8 + (lane & 7);
    int tCol = (lane >> 4) * 8;

    // ---- S = Qv @ Kv^T over 4 chunks of 64 channels ----
    for (int ch = 0; ch < 4; ++ch) {
        __syncthreads();
#pragma unroll
        for (int i = tid; i < 1024; i += 256) {
            int r = i >> 3, c4 = i & 7;
            int gi = r * 32 + ch * 8 + c4;
            int so = r * 72 + c4 * 8;
            *(uint4*)(sQh + so) = gQh[gi];
            *(uint4*)(sQl + so) = gQl[gi];
            *(uint4*)(sKh + so) = gKh[gi];
            *(uint4*)(sKl + so) = gKl[gi];
        }
        __syncthreads();
#pragma unroll
        for (int ks = 0; ks < 4; ++ks) {
            unsigned aHi[4], aLo[4];
            int ro = (wid * 16 + aRow) * 72 + ks * 16 + aCol;
            LDSM_X4(aHi[0], aHi[1], aHi[2], aHi[3], smem_u32(sQh + ro));
            LDSM_X4(aLo[0], aLo[1], aLo[2], aLo[3], smem_u32(sQl + ro));
#pragma unroll
            for (int ng = 0; ng < 8; ++ng) {
                int bo = (ng * 16 + kRow) * 72 + ks * 16 + kCol;
                unsigned bHi[4], bLo[4];
                LDSM_X4(bHi[0], bHi[1], bHi[2], bHi[3], smem_u32(sKh + bo));
                LDSM_X4(bLo[0], bLo[1], bLo[2], bLo[3], smem_u32(sKl + bo));
                mma_bf16(acc[ng*2],   aHi, bHi);
                mma_bf16(acc[ng*2+1], aHi, bHi + 2);
                mma_bf16(acc[ng*2],   aHi, bLo);
                mma_bf16(acc[ng*2+1], aHi, bLo + 2);
                mma_bf16(acc[ng*2],   aLo, bHi);
                mma_bf16(acc[ng*2+1], aLo, bHi + 2);
            }
        }
    }

    // ---- softmax ----
    float mx0 = -1e30f, mx1 = -1e30f;
#pragma unroll
    for (int j = 0; j < 16; ++j) {
        mx0 = fmaxf(mx0, fmaxf(acc[j][0], acc[j][1]));
        mx1 = fmaxf(mx1, fmaxf(acc[j][2], acc[j][3]));
    }
#pragma unroll
    for (int off = 1; off <= 2; off <<= 1) {
        mx0 = fmaxf(mx0, __shfl_xor_sync(0xffffffffu, mx0, off));
        mx1 = fmaxf(mx1, __shfl_xor_sync(0xffffffffu, mx1, off));
    }
    float s0 = 0.f, s1 = 0.f;
#pragma unroll
    for (int j = 0; j < 16; ++j) {
        acc[j][0] = expf(acc[j][0] - mx0); s0 += acc[j][0];
        acc[j][1] = expf(acc[j][1] - mx0); s0 += acc[j][1];
        acc[j][2] = expf(acc[j][2] - mx1); s1 += acc[j][2];
        acc[j][3] = expf(acc[j][3] - mx1); s1 += acc[j][3];
    }
#pragma unroll
    for (int off = 1; off <= 2; off <<= 1) {
        s0 += __shfl_xor_sync(0xffffffffu, s0, off);
        s1 += __shfl_xor_sync(0xffffffffu, s1, off);
    }
    float i0 = 1.f / s0, i1 = 1.f / s1;
#pragma unroll
    for (int j = 0; j < 16; ++j) {
        acc[j][0] *= i0; acc[j][1] *= i0;
        acc[j][2] *= i1; acc[j][3] *= i1;
    }

    // ---- pack P into bf16 hi/lo a-fragments ----
    unsigned phi[8][4], plo[8][4];
#pragma unroll
    for (int t = 0; t < 8; ++t) {
        split2(acc[2*t][0],   acc[2*t][1],   phi[t][0], plo[t][0]);
        split2(acc[2*t][2],   acc[2*t][3],   phi[t][1], plo[t][1]);
        split2(acc[2*t+1][0], acc[2*t+1][1], phi[t][2], plo[t][2]);
        split2(acc[2*t+1][2], acc[2*t+1][3], phi[t][3], plo[t][3]);
    }

    // ---- O = P @ Vv over 2 cv chunks ([128][136] x2 buffers) ----
    __nv_bfloat16* sVh = sat;
    __nv_bfloat16* sVl = sat + 17408;
    for (int cv = 0; cv < 2; ++cv) {
        __syncthreads();
#pragma unroll
        for (int i = tid; i < 2048; i += 256) {
            int r = i >> 4, c4 = i & 15;
            int gi = r * 32 + cv * 16 + c4;
            int so = r * 136 + c4 * 8;
            *(uint4*)(sVh + so) = gVh[gi];
            *(uint4*)(sVl + so) = gVl[gi];
        }
        __syncthreads();
        float oacc[16][4];
#pragma unroll
        for (int j = 0; j < 16; ++j)
#pragma unroll
            for (int e = 0; e < 4; ++e) oacc[j][e] = 0.f;
#pragma unroll
        for (int mk = 0; mk < 8; ++mk) {
#pragma unroll
            for (int ng = 0; ng < 8; ++ng) {
                int bo = (mk * 16 + tRow) * 136 + ng * 16 + tCol;
                unsigned vH[4], vL[4];
                LDSM_X4_T(vH[0], vH[1], vH[2], vH[3], smem_u32(sVh + bo));
                LDSM_X4_T(vL[0], vL[1], vL[2], vL[3], smem_u32(sVl + bo));
                mma_bf16(oacc[ng*2],   phi[mk], vH);
                mma_bf16(oacc[ng*2+1], phi[mk], vH + 2);
                mma_bf16(oacc[ng*2],   phi[mk], vL);
                mma_bf16(oacc[ng*2+1], phi[mk], vL + 2);
                mma_bf16(oacc[ng*2],   plo[mk], vH);
                mma_bf16(oacc[ng*2+1], plo[mk], vH + 2);
            }
        }
#pragma unroll
        for (int j = 0; j < 16; ++j) {
            int col = cv * 128 + j * 8 + (lane & 3) * 2;
            int n0 = wid * 16 + (lane >> 2);
            size_t gi = (size_t)win * WSZ + n0 * 256 + col;
            float2 b0 = *(const float2*)(tgt2 + gi);
            float2 r0 = {b0.x + oacc[j][0], b0.y + oacc[j][1]};
            *(float2*)(tgt3 + gi) = r0;
            size_t gi1 = gi + 8 * 256;
            float2 b1 = *(const float2*)(tgt2 + gi1);
            float2 r1 = {b1.x + oacc[j][2], b1.y + oacc[j][3]};
            *(float2*)(tgt3 + gi1) = r1;
        }
    }
}

// ---------------- GroupNorm (512 threads) -----------------------------------
// mode 0: plain -> fp32   mode 1: out = base + ls*mix(gn(in)) -> fp32
__global__ __launch_bounds__(512)
void gn_kernel(const float* __restrict__ in, const float* __restrict__ base,
               const float* __restrict__ gw, const float* __restrict__ gb,
               const float* __restrict__ ls, float* __restrict__ outf, int mode) {
    extern __shared__ float sm[];
    __shared__ float red[32];
    __shared__ float stats[2];
    int win = blockIdx.x, tid = threadIdx.x, lane = tid & 31, wid = tid >> 5;
    const float4* xin = (const float4*)(in + (size_t)win * WSZ);
    float4* s4 = (float4*)sm;

    float s = 0.f, sq = 0.f;
#pragma unroll
    for (int k = 0; k < 16; ++k) {
        float4 v = xin[tid + k * 512];
        s4[tid + k * 512] = v;
        s  += v.x + v.y + v.z + v.w;
        sq += v.x*v.x + v.y*v.y + v.z*v.z + v.w*v.w;
    }
    gn_reduce(s, sq, red, stats, lane, wid, tid);
    float mean = stats[0], rstd = stats[1];

#pragma unroll
    for (int k = 0; k < 16; ++k) {
        int f = tid + k * 512;
        int c = f >> 5;
        float w = gw[c], bb = gb[c];
        float4 v = s4[f];
        v.x = (v.x - mean) * rstd * w + bb;
        v.y = (v.y - mean) * rstd * w + bb;
        v.z = (v.z - mean) * rstd * w + bb;
        v.w = (v.w - mean) * rstd * w + bb;
        s4[f] = v;
    }
    __syncthreads();

    if (mode == 0) {
#pragma unroll
        for (int k = 0; k < 16; ++k) {
            int f = tid + k * 512;
            ((float4*)(outf + (size_t)win * WSZ))[f] = s4[f];
        }
    } else {
        int p0 = lane * 4;
#pragma unroll 2
        for (int ci = 0; ci < 16; ++ci) {
            int c = wid * 16 + ci;
            const float* ch = sm + c * 128;
            float o[4];
            mix4(ch, p0, o);
            size_t gi = (size_t)win * WSZ + c * 128 + p0;
            float4 bv = *(const float4*)(base + gi);
            float lsv = ls[c];
            float4 ov = {bv.x + lsv * o[0], bv.y + lsv * o[1],
                         bv.z + lsv * o[2], bv.w + lsv * o[3]};
            *(float4*)(outf + gi) = ov;
        }
    }
}

// ---------------- fused: tgt3 = tgt2 + ls2*mix(gn1(tgt3)); hin = gn2(tgt3) --
__global__ __launch_bounds__(512)
void gn_fused_kernel(const float* __restrict__ in, const float* __restrict__ base,
                     const float* __restrict__ g1w, const float* __restrict__ g1b,
                     const float* __restrict__ ls2,
                     const float* __restrict__ g2w, const float* __restrict__ g2b,
                     float* __restrict__ outf,
                     __nv_bfloat16* __restrict__ outhi, __nv_bfloat16* __restrict__ outlo) {
    extern __shared__ float sm[];
    __shared__ float red[32];
    __shared__ float stats[2];
    int win = blockIdx.x, tid = threadIdx.x, lane = tid & 31, wid = tid >> 5;
    const float4* xin = (const float4*)(in + (size_t)win * WSZ);
    float4* s4 = (float4*)sm;

    // pass 1: stats of tgt3
    float s = 0.f, sq = 0.f;
#pragma unroll
    for (int k = 0; k < 16; ++k) {
        float4 v = xin[tid + k * 512];
        s4[tid + k * 512] = v;
        s  += v.x + v.y + v.z + v.w;
        sq += v.x*v.x + v.y*v.y + v.z*v.z + v.w*v.w;
    }
    gn_reduce(s, sq, red, stats, lane, wid, tid);
    float mean = stats[0], rstd = stats[1];

    // gn1 normalize in smem
#pragma unroll
    for (int k = 0; k < 16; ++k) {
        int f = tid + k * 512;
        int c = f >> 5;
        float w = g1w[c], bb = g1b[c];
        float4 v = s4[f];
        v.x = (v.x - mean) * rstd * w + bb;
        v.y = (v.y - mean) * rstd * w + bb;
        v.z = (v.z - mean) * rstd * w + bb;
        v.w = (v.w - mean) * rstd * w + bb;
        s4[f] = v;
    }
    __syncthreads();

    // per-channel mix + residual; overwrite smem with new tgt3; accumulate stats2
    float s2 = 0.f, sq2 = 0.f;
    int p0 = lane * 4;
#pragma unroll 2
    for (int ci = 0; ci < 16; ++ci) {
        int c = wid * 16 + ci;
        float* ch = sm + c * 128;
        float o[4];
        mix4(ch, p0, o);
        __syncwarp();                                  // all reads before writes
        size_t gi = (size_t)win * WSZ + c * 128 + p0;
        float4 bv = *(const float4*)(base + gi);
        float lsv = ls2[c];
        float4 nv = {bv.x + lsv * o[0], bv.y + lsv * o[1],
                     bv.z + lsv * o[2], bv.w + lsv * o[3]};
        *(float4*)(outf + gi) = nv;
        *(float4*)(ch + p0) = nv;
        s2  += nv.x + nv.y + nv.z + nv.w;
        sq2 += nv.x*nv.x + nv.y*nv.y + nv.z*nv.z + nv.w*nv.w;
    }
    __syncthreads();
    gn_reduce(s2, sq2, red, stats, lane, wid, tid);
    float mean2 = stats[0], rstd2 = stats[1];

    // gn2 -> bf16 hi/lo
#pragma unroll
    for (int k = 0; k < 16; ++k) {
        int f = tid + k * 512;
        int c = f >> 5;
        float w = g2w[c], bb = g2b[c];
        float4 v = s4[f];
        v.x = (v.x - mean2) * rstd2 * w + bb;
        v.y = (v.y - mean2) * rstd2 * w + bb;
        v.z = (v.z - mean2) * rstd2 * w + bb;
        v.w = (v.w - mean2) * rstd2 * w + bb;
        unsigned h0, l0, h1, l1;
        split2(v.x, v.y, h0, l0);
        split2(v.z, v.w, h1, l1);
        uint2 vh = {h0, h1}, vl = {l0, l1};
        *(uint2*)(outhi + (size_t)win * WSZ + f * 4) = vh;
        *(uint2*)(outlo + (size_t)win * WSZ + f * 4) = vl;
    }
}

// ---------------- host orchestration ---------------------------------------
extern "C" void kernel_launch(void* const* d_in, const int* in_sizes, int n_in,
                              void* d_out, int out_size) {
    const float* src  = (const float*)d_in[0];
    const float* qf   = (const float*)d_in[1];
    const float* gn1w = (const float*)d_in[2];
    const float* gn1b = (const float*)d_in[3];
    const float* gn2w = (const float*)d_in[4];
    const float* gn2b = (const float*)d_in[5];
    const float* ls1  = (const float*)d_in[6];
    const float* ls2  = (const float*)d_in[7];
    const float* ls3  = (const float*)d_in[8];
    const float* qw   = (const float*)d_in[9];
    const float* qb   = (const float*)d_in[10];
    const float* kw   = (const float*)d_in[11];
    const float* kb   = (const float*)d_in[12];
    const float* vw   = (const float*)d_in[13];
    const float* vb   = (const float*)d_in[14];
    const float* fc1w = (const float*)d_in[15];
    const float* fc1b = (const float*)d_in[16];
    const float* fc2w = (const float*)d_in[17];
    const float* fc2b = (const float*)d_in[18];
    const float* gnfw = (const float*)d_in[19];
    const float* gnfb = (const float*)d_in[20];
    float* out = (float*)d_out;

    float *tgt, *tgt2, *tgt3, *fin;
    __nv_bfloat16 *memhi, *memlo, *tgthi, *tgtlo, *qhi, *qlo, *khi, *klo, *vhi, *vlo;
    __nv_bfloat16 *hinhi, *hinlo, *hhi, *hlo, *whi, *wlo;
    cudaGetSymbolAddress((void**)&tgt,  g_tgt);
    cudaGetSymbolAddress((void**)&tgt2, g_tgt2);
    cudaGetSymbolAddress((void**)&tgt3, g_tgt3);
    cudaGetSymbolAddress((void**)&fin,  g_fin);
    cudaGetSymbolAddress((void**)&memhi,g_memhi);
    cudaGetSymbolAddress((void**)&memlo,g_memlo);
    cudaGetSymbolAddress((void**)&tgthi,g_tgthi);
    cudaGetSymbolAddress((void**)&tgtlo,g_tgtlo);
    cudaGetSymbolAddress((void**)&qhi,  g_qhi);
    cudaGetSymbolAddress((void**)&qlo,  g_qlo);
    cudaGetSymbolAddress((void**)&khi,  g_khi);
    cudaGetSymbolAddress((void**)&klo,  g_klo);
    cudaGetSymbolAddress((void**)&vhi,  g_vhi);
    cudaGetSymbolAddress((void**)&vlo,  g_vlo);
    cudaGetSymbolAddress((void**)&hinhi,g_hinhi);
    cudaGetSymbolAddress((void**)&hinlo,g_hinlo);
    cudaGetSymbolAddress((void**)&hhi,  g_hhi);
    cudaGetSymbolAddress((void**)&hlo,  g_hlo);
    cudaGetSymbolAddress((void**)&whi,  g_whi);
    cudaGetSymbolAddress((void**)&wlo,  g_wlo);

    const int SM_GN   = 131072;
    const int SM_ATTN = 73728;
    const int SM_TC   = 71680;
    cudaFuncSetAttribute(gn_kernel,       cudaFuncAttributeMaxDynamicSharedMemorySize, SM_GN);
    cudaFuncSetAttribute(gn_fused_kernel, cudaFuncAttributeMaxDynamicSharedMemorySize, SM_GN);
    cudaFuncSetAttribute(attn_kernel,     cudaFuncAttributeMaxDynamicSharedMemorySize, SM_ATTN);
    cudaFuncSetAttribute(gemm_tc_kernel,  cudaFuncAttributeMaxDynamicSharedMemorySize, SM_TC);

    partition_kernel<<<32768, 256>>>(src, memhi, memlo, nullptr);
    partition_kernel<<<32768, 256>>>(qf, tgthi, tgtlo, tgt);

    for (int l = 0; l < 2; ++l) {
        size_t lb = (size_t)l * 458752;
        conv_w_kernel<<<32, 256>>>(qw  + (size_t)l*65536,  whi + lb,          wlo + lb,          8192);
        conv_w_kernel<<<32, 256>>>(kw  + (size_t)l*65536,  whi + lb + 65536,  wlo + lb + 65536,  8192);
        conv_w_kernel<<<32, 256>>>(vw  + (size_t)l*65536,  whi + lb + 131072, wlo + lb + 131072, 8192);
        conv_w_kernel<<<64, 256>>>(fc1w+ (size_t)l*131072, whi + lb + 196608, wlo + lb + 196608, 16384);
        conv_w_kernel<<<64, 256>>>(fc2w+ (size_t)l*131072, whi + lb + 327680, wlo + lb + 327680, 16384);
    }

    for (int l = 0; l < 2; ++l) {
        int lC = l * CDIM;
        size_t lb = (size_t)l * 458752;
        // tgt2 = tgt + ls1 * mix(gn1(tgt))
        gn_kernel<<<NW, 512, SM_GN>>>(tgt, tgt, gn1w + lC, gn1b + lC, ls1 + lC, tgt2, 1);
        gemm_tc_kernel<<<dim3(NW,2), 256, SM_TC>>>(whi + lb,          wlo + lb,          tgthi, tgtlo, qb + lC, nullptr, qhi, qlo, 256, 256, 0, nullptr, nullptr);
        gemm_tc_kernel<<<dim3(NW,2), 256, SM_TC>>>(whi + lb + 65536,  wlo + lb + 65536,  memhi, memlo, kb + lC, nullptr, khi, klo, 256, 256, 0, nullptr, nullptr);
        gemm_tc_kernel<<<dim3(NW,2), 256, SM_TC>>>(whi + lb + 131072, wlo + lb + 131072, memhi, memlo, vb + lC, nullptr, vhi, vlo, 256, 256, 0, nullptr, nullptr);
        attn_kernel<<<NW, 256, SM_ATTN>>>(qhi, qlo, khi, klo, vhi, vlo, tgt2, tgt3);
        // fused: tgt3 = tgt2 + ls2*mix(gn1(tgt3)); hin = gn2(tgt3) -> bf16
        gn_fused_kernel<<<NW, 512, SM_GN>>>(tgt3, tgt2, gn1w + lC, gn1b + lC, ls2 + lC,
                                            gn2w + lC, gn2b + lC, tgt3, hinhi, hinlo);
        gemm_tc_kernel<<<dim3(NW,4), 256, SM_TC>>>(whi + lb + 196608, wlo + lb + 196608, hinhi, hinlo, fc1b + (size_t)l*512, nullptr, hhi, hlo, 512, 256, 1, nullptr, nullptr);
        gemm_tc_kernel<<<dim3(NW,2), 256, SM_TC>>>(whi + lb + 327680, wlo + lb + 327680, hhi, hlo, fc2b + lC, tgt, tgthi, tgtlo, 256, 512, 2, tgt3, ls3 + lC);
    }

    gn_kernel<<<NW, 512, SM_GN>>>(tgt, nullptr, gnfw, gnfb, nullptr, fin, 0);
    scatter_kernel<<<65536, 256>>>(fin, out);
}

// round 7
// speedup vs baseline: 3.4804x; 1.0450x over previous
#include <cuda_runtime.h>
#include <cuda_bf16.h>
#include <math.h>
#include <stdint.h>

#define NW   512
#define CDIM 256
#define PDIM 128
#define WSZ  (CDIM*PDIM)

// ---------------- scratch (static device globals; no allocations) ----------
__device__ float g_tgt [NW*WSZ];
__device__ float g_tgt2[NW*WSZ];
__device__ float g_tgt3[NW*WSZ];
__device__ float g_fin [NW*WSZ];
__device__ __nv_bfloat16 g_memhi[NW*WSZ], g_memlo[NW*WSZ];
__device__ __nv_bfloat16 g_tgthi[NW*WSZ], g_tgtlo[NW*WSZ];
__device__ __nv_bfloat16 g_qkvhi[3*NW*WSZ], g_qkvlo[3*NW*WSZ];
__device__ __nv_bfloat16 g_hinhi[NW*WSZ], g_hinlo[NW*WSZ];
__device__ __nv_bfloat16 g_hhi [NW*2*WSZ], g_hlo [NW*2*WSZ];
__device__ __nv_bfloat16 g_whi[2*458752], g_wlo[2*458752];
// partial stats buffers: [NW][8 slots][2]
__device__ float g_p1[NW*16];
__device__ float g_p2[NW*16];
__device__ float g_p3[NW*16];

// ================= helpers =================================================
__device__ __forceinline__ uint32_t smem_u32(const void* p) {
    uint32_t a;
    asm("{ .reg .u64 t; cvta.to.shared.u64 t, %1; cvt.u32.u64 %0, t; }" : "=r"(a) : "l"(p));
    return a;
}
#define LDSM_X4(r0,r1,r2,r3,addr) \
    asm volatile("ldmatrix.sync.aligned.m8n8.x4.shared.b16 {%0,%1,%2,%3}, [%4];" \
        : "=r"(r0),"=r"(r1),"=r"(r2),"=r"(r3) : "r"(addr))
#define LDSM_X4_T(r0,r1,r2,r3,addr) \
    asm volatile("ldmatrix.sync.aligned.m8n8.x4.trans.shared.b16 {%0,%1,%2,%3}, [%4];" \
        : "=r"(r0),"=r"(r1),"=r"(r2),"=r"(r3) : "r"(addr))
__device__ __forceinline__ void mma_bf16(float* d, const unsigned* a, const unsigned* b) {
    asm volatile("mma.sync.aligned.m16n8k16.row.col.f32.bf16.bf16.f32 "
        "{%0,%1,%2,%3}, {%4,%5,%6,%7}, {%8,%9}, {%0,%1,%2,%3};"
        : "+f"(d[0]),"+f"(d[1]),"+f"(d[2]),"+f"(d[3])
        : "r"(a[0]),"r"(a[1]),"r"(a[2]),"r"(a[3]), "r"(b[0]),"r"(b[1]));
}
__device__ __forceinline__ void split2(float a, float b, unsigned& h, unsigned& l) {
    __nv_bfloat16 ah = __float2bfloat16(a);
    __nv_bfloat16 bh = __float2bfloat16(b);
    __nv_bfloat16 al = __float2bfloat16(a - __bfloat162float(ah));
    __nv_bfloat16 bl = __float2bfloat16(b - __bfloat162float(bh));
    h = (unsigned)__bfloat16_as_ushort(ah) | ((unsigned)__bfloat16_as_ushort(bh) << 16);
    l = (unsigned)__bfloat16_as_ushort(al) | ((unsigned)__bfloat16_as_ushort(bl) << 16);
}
__device__ __forceinline__ void mix4(const float* ch, int p0, float* o) {
#pragma unroll
    for (int e = 0; e < 4; ++e) {
        int p = p0 + e, y = p >> 4, x = p & 15;
        float sum = 0.f; int cnt = 0;
#pragma unroll
        for (int dy = -1; dy <= 1; ++dy) {
            int ny = y + dy;
            if (ny < 0 || ny > 7) continue;
#pragma unroll
            for (int dx = -1; dx <= 1; ++dx) {
                int nx = x + dx;
                if (nx < 0 || nx > 15) continue;
                sum += ch[ny * 16 + nx]; cnt++;
            }
        }
        o[e] = sum / (float)cnt - ch[p];
    }
}
// mean/rstd from partial slots
__device__ __forceinline__ void read_stats(const float* part, int win, int nparts,
                                           float& mean, float& rstd) {
    float S = 0.f, Q = 0.f;
    for (int i = 0; i < nparts; ++i) { S += part[win*16 + i*2]; Q += part[win*16 + i*2 + 1]; }
    mean = S * (1.f / 32768.f);
    float var = Q * (1.f / 32768.f) - mean * mean;
    rstd = rsqrtf(var + 1e-5f);
}

// ---------------- partition (merged src + qf) -------------------------------
__global__ void partition_kernel(const float* __restrict__ src, const float* __restrict__ qf,
                                 __nv_bfloat16* __restrict__ memhi, __nv_bfloat16* __restrict__ memlo,
                                 __nv_bfloat16* __restrict__ tgthi, __nv_bfloat16* __restrict__ tgtlo,
                                 float* __restrict__ tgt) {
    int gb = blockIdx.x;
    bool isq = gb >= 32768;
    int g = (isq ? gb - 32768 : gb) * 256 + threadIdx.x;
    int idx = g * 2;
    int p = idx & 127, c = (idx >> 7) & 255, bw = idx >> 15;
    int b = bw >> 7, wblk = bw & 127;
    int h = (wblk >> 3) * 8 + (p >> 4), w = (wblk & 7) * 16 + (p & 15);
    const float* s = (isq ? qf : src) + (((size_t)b * 256 + c) * 128 + h) * 128 + w;
    float a0 = s[0], a1 = s[1];
    unsigned hh, ll; split2(a0, a1, hh, ll);
    if (isq) {
        *(unsigned*)(tgthi + idx) = hh;
        *(unsigned*)(tgtlo + idx) = ll;
        *(float2*)(tgt + idx) = make_float2(a0, a1);
    } else {
        *(unsigned*)(memhi + idx) = hh;
        *(unsigned*)(memlo + idx) = ll;
    }
}

__global__ void scatter_kernel(const float* __restrict__ fin, float* __restrict__ out) {
    int idx = blockIdx.x * 256 + threadIdx.x;
    int c = idx & 255, b = (idx >> 8) & 3, n = idx >> 10;
    int h = n >> 7, w = n & 127;
    int win = b * 128 + (h >> 3) * 8 + (w >> 4);
    int p = (h & 7) * 16 + (w & 15);
    out[idx] = fin[(size_t)win * WSZ + c * 128 + p];
}

// ---------------- all weights fp32 -> hi/lo bf16 (one launch) ---------------
__global__ void conv_w_all(const float* __restrict__ qw, const float* __restrict__ kw,
                           const float* __restrict__ vw, const float* __restrict__ fc1w,
                           const float* __restrict__ fc2w,
                           __nv_bfloat16* __restrict__ hi, __nv_bfloat16* __restrict__ lo) {
    int g = blockIdx.x * 256 + threadIdx.x;          // 0 .. 114688
    int l = g / 57344, r = g - l * 57344;
    const float* srcp;
    size_t oo;
    if (r < 8192)        { srcp = qw  + (size_t)l*65536  + (size_t)r*8;          oo = (size_t)l*458752 + (size_t)r*8; }
    else if (r < 16384)  { srcp = kw  + (size_t)l*65536  + (size_t)(r-8192)*8;   oo = (size_t)l*458752 + 65536  + (size_t)(r-8192)*8; }
    else if (r < 24576)  { srcp = vw  + (size_t)l*65536  + (size_t)(r-16384)*8;  oo = (size_t)l*458752 + 131072 + (size_t)(r-16384)*8; }
    else if (r < 40960)  { srcp = fc1w+ (size_t)l*131072 + (size_t)(r-24576)*8;  oo = (size_t)l*458752 + 196608 + (size_t)(r-24576)*8; }
    else                 { srcp = fc2w+ (size_t)l*131072 + (size_t)(r-40960)*8;  oo = (size_t)l*458752 + 327680 + (size_t)(r-40960)*8; }
    unsigned hh[4], ll[4];
#pragma unroll
    for (int j = 0; j < 4; ++j) split2(srcp[2*j], srcp[2*j+1], hh[j], ll[j]);
    uint4 vh = {hh[0], hh[1], hh[2], hh[3]};
    uint4 vl = {ll[0], ll[1], ll[2], ll[3]};
    *(uint4*)(hi + oo) = vh;
    *(uint4*)(lo + oo) = vl;
}

// ---------------- GN stats (one CTA per window) ------------------------------
__global__ __launch_bounds__(256)
void gn_stats(const float* __restrict__ in, float* __restrict__ part) {
    __shared__ float red[16];
    int win = blockIdx.x, tid = threadIdx.x, lane = tid & 31, wid = tid >> 5;
    const float4* x = (const float4*)(in + (size_t)win * WSZ);
    float s = 0.f, q = 0.f;
#pragma unroll
    for (int k = 0; k < 32; ++k) {
        float4 v = x[tid + k * 256];
        s += v.x + v.y + v.z + v.w;
        q += v.x*v.x + v.y*v.y + v.z*v.z + v.w*v.w;
    }
#pragma unroll
    for (int off = 16; off; off >>= 1) {
        s += __shfl_down_sync(0xffffffffu, s, off);
        q += __shfl_down_sync(0xffffffffu, q, off);
    }
    if (lane == 0) { red[wid] = s; red[8 + wid] = q; }
    __syncthreads();
    if (tid == 0) {
        float ts = 0.f, tq = 0.f;
#pragma unroll
        for (int i = 0; i < 8; ++i) { ts += red[i]; tq += red[8 + i]; }
        part[win*16 + 0] = ts; part[win*16 + 1] = tq;
        part[win*16 + 2] = 0.f; part[win*16 + 3] = 0.f;
    }
}

// ---------------- GN apply + poolformer mix + residual -----------------------
// out = base + ls * mix(gn(in));  optional partial stats of OUT -> out_part slot yb
__global__ __launch_bounds__(256)
void gn_mix_apply(const float* __restrict__ in, const float* __restrict__ basep,
                  const float* __restrict__ part, int nparts,
                  const float* __restrict__ gw, const float* __restrict__ gb,
                  const float* __restrict__ ls, float* __restrict__ outf,
                  float* __restrict__ out_part) {
    __shared__ float sm[32 * 132];
    __shared__ float red[16];
    int win = blockIdx.x, yb = blockIdx.y, tid = threadIdx.x, lane = tid & 31, wid = tid >> 5;
    float mean, rstd;
    read_stats(part, win, nparts, mean, rstd);

    const float4* src = (const float4*)(in + (size_t)win * WSZ + yb * 4096);
#pragma unroll
    for (int k = 0; k < 4; ++k) {
        int idx = tid + k * 256;
        int cl = idx >> 5, p4 = idx & 31;
        int c = yb * 32 + cl;
        float w = gw[c], bb = gb[c];
        float4 v = src[idx];
        v.x = (v.x - mean) * rstd * w + bb;
        v.y = (v.y - mean) * rstd * w + bb;
        v.z = (v.z - mean) * rstd * w + bb;
        v.w = (v.w - mean) * rstd * w + bb;
        *(float4*)(sm + cl * 132 + p4 * 4) = v;
    }
    __syncthreads();

    float s2 = 0.f, q2 = 0.f;
    int p0 = lane * 4;
#pragma unroll
    for (int ci = 0; ci < 4; ++ci) {
        int cl = wid * 4 + ci;
        int c = yb * 32 + cl;
        const float* ch = sm + cl * 132;
        float o[4];
        mix4(ch, p0, o);
        size_t gi = (size_t)win * WSZ + c * 128 + p0;
        float4 bv = *(const float4*)(basep + gi);
        float lsv = ls[c];
        float4 ov = {bv.x + lsv * o[0], bv.y + lsv * o[1],
                     bv.z + lsv * o[2], bv.w + lsv * o[3]};
        *(float4*)(outf + gi) = ov;
        if (out_part) {
            s2 += ov.x + ov.y + ov.z + ov.w;
            q2 += ov.x*ov.x + ov.y*ov.y + ov.z*ov.z + ov.w*ov.w;
        }
    }
    if (out_part) {
#pragma unroll
        for (int off = 16; off; off >>= 1) {
            s2 += __shfl_down_sync(0xffffffffu, s2, off);
            q2 += __shfl_down_sync(0xffffffffu, q2, off);
        }
        if (lane == 0) { red[wid] = s2; red[8 + wid] = q2; }
        __syncthreads();
        if (tid == 0) {
            float ts = 0.f, tq = 0.f;
#pragma unroll
            for (int i = 0; i < 8; ++i) { ts += red[i]; tq += red[8 + i]; }
            out_part[win*16 + yb*2] = ts; out_part[win*16 + yb*2 + 1] = tq;
        }
    }
}

// ---------------- elementwise GN apply (fp32 OR bf16 hi/lo out) --------------
__global__ __launch_bounds__(256)
void gn_elem_apply(const float* __restrict__ in, const float* __restrict__ part, int nparts,
                   const float* __restrict__ gw, const float* __restrict__ gb,
                   float* __restrict__ outf,
                   __nv_bfloat16* __restrict__ outhi, __nv_bfloat16* __restrict__ outlo) {
    int win = blockIdx.x, yb = blockIdx.y, tid = threadIdx.x;
    float mean, rstd;
    read_stats(part, win, nparts, mean, rstd);
    size_t b0 = (size_t)win * WSZ + yb * 4096;
    const float4* src = (const float4*)(in + b0);
#pragma unroll
    for (int k = 0; k < 4; ++k) {
        int idx = tid + k * 256;
        int c = yb * 32 + (idx >> 5);
        float w = gw[c], bb = gb[c];
        float4 v = src[idx];
        v.x = (v.x - mean) * rstd * w + bb;
        v.y = (v.y - mean) * rstd * w + bb;
        v.z = (v.z - mean) * rstd * w + bb;
        v.w = (v.w - mean) * rstd * w + bb;
        if (outf) {
            *(float4*)(outf + b0 + idx * 4) = v;
        } else {
            unsigned h0, l0, h1, l1;
            split2(v.x, v.y, h0, l0);
            split2(v.z, v.w, h1, l1);
            uint2 vh = {h0, h1}, vl = {l0, l1};
            *(uint2*)(outhi + b0 + idx * 4) = vh;
            *(uint2*)(outlo + b0 + idx * 4) = vl;
        }
    }
}

// ---------------- tensor-core GEMM (mode 0 merged QKV / 1 fc1 / 2 fc2) -------
__global__ __launch_bounds__(256, 2)
void gemm_tc_kernel(const __nv_bfloat16* __restrict__ Wb_hi, const __nv_bfloat16* __restrict__ Wb_lo,
                    const __nv_bfloat16* __restrict__ Xa_hi, const __nv_bfloat16* __restrict__ Xa_lo,
                    const __nv_bfloat16* __restrict__ Xb_hi, const __nv_bfloat16* __restrict__ Xb_lo,
                    const float* __restrict__ b0p, const float* __restrict__ b1p,
                    const float* __restrict__ b2p,
                    float* __restrict__ Yf, __nv_bfloat16* __restrict__ Yhi,
                    __nv_bfloat16* __restrict__ Ylo,
                    int CIN, int mode,
                    const float* __restrict__ base, const float* __restrict__ ls,
                    float* __restrict__ partials) {
    extern __shared__ __nv_bfloat16 sb[];
    __nv_bfloat16* sWhi = sb;                 // [128][72]
    __nv_bfloat16* sWlo = sb + 9216;
    __nv_bfloat16* sXhi = sb + 18432;         // [64][136]
    __nv_bfloat16* sXlo = sb + 27136;
    int win = blockIdx.x, ob = blockIdx.y;
    int tid = threadIdx.x, lane = tid & 31, wid = tid >> 5;
    int wr = wid >> 1, wc = wid & 1;

    const __nv_bfloat16* gWhi = Wb_hi + (size_t)ob * 128 * CIN;
    const __nv_bfloat16* gWlo = Wb_lo + (size_t)ob * 128 * CIN;
    const __nv_bfloat16 *Xhi, *Xlo;
    const float* bias;
    int O, O0;
    size_t ybase = 0;
    if (mode == 0) {
        int mat = ob >> 1;
        Xhi = mat ? Xb_hi : Xa_hi;
        Xlo = mat ? Xb_lo : Xa_lo;
        bias = (mat == 0) ? b0p : (mat == 1 ? b1p : b2p);
        O = 256; O0 = (ob & 1) * 128;
        ybase = (size_t)mat * NW * WSZ;
    } else {
        Xhi = Xa_hi; Xlo = Xa_lo; bias = b0p;
        O = (mode == 1) ? 512 : 256; O0 = ob * 128;
    }
    const uint4* gXhi4 = (const uint4*)Xhi + (size_t)win * CIN * 16;
    const uint4* gXlo4 = (const uint4*)Xlo + (size_t)win * CIN * 16;

    float acc[2][8][4];
#pragma unroll
    for (int mt = 0; mt < 2; ++mt)
#pragma unroll
        for (int nt = 0; nt < 8; ++nt)
#pragma unroll
            for (int e = 0; e < 4; ++e) acc[mt][nt][e] = 0.f;

    int aRow = (lane & 15), aCol = (lane >> 4) * 8;
    int brbase = ((lane >> 3) & 1) * 8 + (lane & 7);
    int bcofs  = (lane >> 4) * 8;

    for (int kc = 0; kc < CIN; kc += 64) {
        __syncthreads();
#pragma unroll
        for (int i = tid; i < 1024; i += 256) {
            int r = i >> 3, c4 = i & 7;
            size_t go = (size_t)r * CIN + kc + c4 * 8;
            int so = r * 72 + c4 * 8;
            *(uint4*)(sWhi + so) = *(const uint4*)(gWhi + go);
            *(uint4*)(sWlo + so) = *(const uint4*)(gWlo + go);
        }
#pragma unroll
        for (int i = tid; i < 1024; i += 256) {
            int r = i >> 4, c4 = i & 15;
            int gi = (kc + r) * 16 + c4;
            int so = r * 136 + c4 * 8;
            *(uint4*)(sXhi + so) = gXhi4[gi];
            *(uint4*)(sXlo + so) = gXlo4[gi];
        }
        __syncthreads();
#pragma unroll
        for (int ks = 0; ks < 4; ++ks) {
            unsigned aHi[2][4], aLo[2][4];
#pragma unroll
            for (int mt = 0; mt < 2; ++mt) {
                int ro = (wr * 32 + mt * 16 + aRow) * 72 + ks * 16 + aCol;
                LDSM_X4(aHi[mt][0], aHi[mt][1], aHi[mt][2], aHi[mt][3], smem_u32(sWhi + ro));
                LDSM_X4(aLo[mt][0], aLo[mt][1], aLo[mt][2], aLo[mt][3], smem_u32(sWlo + ro));
            }
#pragma unroll
            for (int np = 0; np < 4; ++np) {
                int bo = (ks * 16 + brbase) * 136 + wc * 64 + np * 16 + bcofs;
                unsigned bHi[4], bLo[4];
                LDSM_X4_T(bHi[0], bHi[1], bHi[2], bHi[3], smem_u32(sXhi + bo));
                LDSM_X4_T(bLo[0], bLo[1], bLo[2], bLo[3], smem_u32(sXlo + bo));
#pragma unroll
                for (int mt = 0; mt < 2; ++mt) {
                    mma_bf16(acc[mt][np*2],   aHi[mt], bHi);
                    mma_bf16(acc[mt][np*2+1], aHi[mt], bHi + 2);
                    mma_bf16(acc[mt][np*2],   aHi[mt], bLo);
                    mma_bf16(acc[mt][np*2+1], aHi[mt], bLo + 2);
                    mma_bf16(acc[mt][np*2],   aLo[mt], bHi);
                    mma_bf16(acc[mt][np*2+1], aLo[mt], bHi + 2);
                }
            }
        }
    }

    float ssum = 0.f, ssq = 0.f;
#pragma unroll
    for (int mt = 0; mt < 2; ++mt)
#pragma unroll
        for (int nt = 0; nt < 8; ++nt) {
            int p = wc * 64 + nt * 8 + (lane & 3) * 2;
#pragma unroll
            for (int half = 0; half < 2; ++half) {
                int o = O0 + wr * 32 + mt * 16 + (lane >> 2) + half * 8;
                float bv = bias[o];
                float2 v;
                v.x = acc[mt][nt][half * 2]     + bv;
                v.y = acc[mt][nt][half * 2 + 1] + bv;
                size_t gi = ybase + ((size_t)win * O + o) * 128 + p;
                if (mode == 1) {
                    v.x = 0.5f * v.x * (1.f + erff(v.x * 0.70710678118654752f));
                    v.y = 0.5f * v.y * (1.f + erff(v.y * 0.70710678118654752f));
                } else if (mode == 2) {
                    float lsv = ls[o];
                    float2 b2 = *(const float2*)(base + gi);
                    v.x = b2.x + lsv * v.x;
                    v.y = b2.y + lsv * v.y;
                    *(float2*)(Yf + gi) = v;
                    ssum += v.x + v.y;
                    ssq  += v.x*v.x + v.y*v.y;
                }
                unsigned hh, ll; split2(v.x, v.y, hh, ll);
                *(unsigned*)(Yhi + gi) = hh;
                *(unsigned*)(Ylo + gi) = ll;
            }
        }

    if (mode == 2) {
        __syncthreads();
        float* red = (float*)sb;
#pragma unroll
        for (int off = 16; off; off >>= 1) {
            ssum += __shfl_down_sync(0xffffffffu, ssum, off);
            ssq  += __shfl_down_sync(0xffffffffu, ssq,  off);
        }
        if (lane == 0) { red[wid] = ssum; red[8 + wid] = ssq; }
        __syncthreads();
        if (tid == 0) {
            float ts = 0.f, tq = 0.f;
#pragma unroll
            for (int i = 0; i < 8; ++i) { ts += red[i]; tq += red[8 + i]; }
            partials[win*16 + ob*2] = ts; partials[win*16 + ob*2 + 1] = tq;
        }
    }
}

// ---------------- attention (+inline stats of tgt3) --------------------------
__global__ __launch_bounds__(256, 2)
void attn_kernel(const __nv_bfloat16* __restrict__ Qhi, const __nv_bfloat16* __restrict__ Qlo,
                 const __nv_bfloat16* __restrict__ Khi, const __nv_bfloat16* __restrict__ Klo,
                 const __nv_bfloat16* __restrict__ Vhi, const __nv_bfloat16* __restrict__ Vlo,
                 const float* __restrict__ tgt2, float* __restrict__ tgt3,
                 float* __restrict__ out_part) {
    extern __shared__ __nv_bfloat16 sat[];
    __nv_bfloat16* sQh = sat;                 // [128][72] x4
    __nv_bfloat16* sQl = sat + 9216;
    __nv_bfloat16* sKh = sat + 18432;
    __nv_bfloat16* sKl = sat + 27648;
    __shared__ float ared[16];
    int win = blockIdx.x, tid = threadIdx.x, lane = tid & 31, wid = tid >> 5;

    const uint4* gQh = (const uint4*)Qhi + (size_t)win * 4096;
    const uint4* gQl = (const uint4*)Qlo + (size_t)win * 4096;
    const uint4* gKh = (const uint4*)Khi + (size_t)win * 4096;
    const uint4* gKl = (const uint4*)Klo + (size_t)win * 4096;
    const uint4* gVh = (const uint4*)Vhi + (size_t)win * 4096;
    const uint4* gVl = (const uint4*)Vlo + (size_t)win * 4096;

    float acc[16][4];
#pragma unroll
    for (int j = 0; j < 16; ++j)
#pragma unroll
        for (int e = 0; e < 4; ++e) acc[j][e] = 0.f;

    int aRow = lane & 15, aCol = (lane >> 4) * 8;
    int kRow = (lane & 7) + ((lane >> 4) & 1) * 8;
    int kCol = ((lane >> 3) & 1) * 8;
    int tRow = ((lane >> 3) & 1) * 8 + (lane & 7);
    int tCol = (lane >> 4) * 8;

    for (int ch = 0; ch < 4; ++ch) {
        __syncthreads();
#pragma unroll
        for (int i = tid; i < 1024; i += 256) {
            int r = i >> 3, c4 = i & 7;
            int gi = r * 32 + ch * 8 + c4;
            int so = r * 72 + c4 * 8;
            *(uint4*)(sQh + so) = gQh[gi];
            *(uint4*)(sQl + so) = gQl[gi];
            *(uint4*)(sKh + so) = gKh[gi];
            *(uint4*)(sKl + so) = gKl[gi];
        }
        __syncthreads();
#pragma unroll
        for (int ks = 0; ks < 4; ++ks) {
            unsigned aHi[4], aLo[4];
            int ro = (wid * 16 + aRow) * 72 + ks * 16 + aCol;
            LDSM_X4(aHi[0], aHi[1], aHi[2], aHi[3], smem_u32(sQh + ro));
            LDSM_X4(aLo[0], aLo[1], aLo[2], aLo[3], smem_u32(sQl + ro));
#pragma unroll
            for (int ng = 0; ng < 8; ++ng) {
                int bo = (ng * 16 + kRow) * 72 + ks * 16 + kCol;
                unsigned bHi[4], bLo[4];
                LDSM_X4(bHi[0], bHi[1], bHi[2], bHi[3], smem_u32(sKh + bo));
                LDSM_X4(bLo[0], bLo[1], bLo[2], bLo[3], smem_u32(sKl + bo));
                mma_bf16(acc[ng*2],   aHi, bHi);
                mma_bf16(acc[ng*2+1], aHi, bHi + 2);
                mma_bf16(acc[ng*2],   aHi, bLo);
                mma_bf16(acc[ng*2+1], aHi, bLo + 2);
                mma_bf16(acc[ng*2],   aLo, bHi);
                mma_bf16(acc[ng*2+1], aLo, bHi + 2);
            }
        }
    }

    // softmax
    float mx0 = -1e30f, mx1 = -1e30f;
#pragma unroll
    for (int j = 0; j < 16; ++j) {
        mx0 = fmaxf(mx0, fmaxf(acc[j][0], acc[j][1]));
        mx1 = fmaxf(mx1, fmaxf(acc[j][2], acc[j][3]));
    }
#pragma unroll
    for (int off = 1; off <= 2; off <<= 1) {
        mx0 = fmaxf(mx0, __shfl_xor_sync(0xffffffffu, mx0, off));
        mx1 = fmaxf(mx1, __shfl_xor_sync(0xffffffffu, mx1, off));
    }
    float s0 = 0.f, s1 = 0.f;
#pragma unroll
    for (int j = 0; j < 16; ++j) {
        acc[j][0] = expf(acc[j][0] - mx0); s0 += acc[j][0];
        acc[j][1] = expf(acc[j][1] - mx0); s0 += acc[j][1];
        acc[j][2] = expf(acc[j][2] - mx1); s1 += acc[j][2];
        acc[j][3] = expf(acc[j][3] - mx1); s1 += acc[j][3];
    }
#pragma unroll
    for (int off = 1; off <= 2; off <<= 1) {
        s0 += __shfl_xor_sync(0xffffffffu, s0, off);
        s1 += __shfl_xor_sync(0xffffffffu, s1, off);
    }
    float i0 = 1.f / s0, i1 = 1.f / s1;
#pragma unroll
    for (int j = 0; j < 16; ++j) {
        acc[j][0] *= i0; acc[j][1] *= i0;
        acc[j][2] *= i1; acc[j][3] *= i1;
    }

    unsigned phi[8][4], plo[8][4];
#pragma unroll
    for (int t = 0; t < 8; ++t) {
        split2(acc[2*t][0],   acc[2*t][1],   phi[t][0], plo[t][0]);
        split2(acc[2*t][2],   acc[2*t][3],   phi[t][1], plo[t][1]);
        split2(acc[2*t+1][0], acc[2*t+1][1], phi[t][2], plo[t][2]);
        split2(acc[2*t+1][2], acc[2*t+1][3], phi[t][3], plo[t][3]);
    }

    float ssum = 0.f, ssq = 0.f;
    __nv_bfloat16* sVh = sat;
    __nv_bfloat16* sVl = sat + 17408;
    for (int cv = 0; cv < 2; ++cv) {
        __syncthreads();
#pragma unroll
        for (int i = tid; i < 2048; i += 256) {
            int r = i >> 4, c4 = i & 15;
            int gi = r * 32 + cv * 16 + c4;
            int so = r * 136 + c4 * 8;
            *(uint4*)(sVh + so) = gVh[gi];
            *(uint4*)(sVl + so) = gVl[gi];
        }
        __syncthreads();
        float oacc[16][4];
#pragma unroll
        for (int j = 0; j < 16; ++j)
#pragma unroll
            for (int e = 0; e < 4; ++e) oacc[j][e] = 0.f;
#pragma unroll
        for (int mk = 0; mk < 8; ++mk) {
#pragma unroll
            for (int ng = 0; ng < 8; ++ng) {
                int bo = (mk * 16 + tRow) * 136 + ng * 16 + tCol;
                unsigned vH[4], vL[4];
                LDSM_X4_T(vH[0], vH[1], vH[2], vH[3], smem_u32(sVh + bo));
                LDSM_X4_T(vL[0], vL[1], vL[2], vL[3], smem_u32(sVl + bo));
                mma_bf16(oacc[ng*2],   phi[mk], vH);
                mma_bf16(oacc[ng*2+1], phi[mk], vH + 2);
                mma_bf16(oacc[ng*2],   phi[mk], vL);
                mma_bf16(oacc[ng*2+1], phi[mk], vL + 2);
                mma_bf16(oacc[ng*2],   plo[mk], vH);
                mma_bf16(oacc[ng*2+1], plo[mk], vH + 2);
            }
        }
#pragma unroll
        for (int j = 0; j < 16; ++j) {
            int col = cv * 128 + j * 8 + (lane & 3) * 2;
            int n0 = wid * 16 + (lane >> 2);
            size_t gi = (size_t)win * WSZ + n0 * 256 + col;
            float2 b0 = *(const float2*)(tgt2 + gi);
            float2 r0 = {b0.x + oacc[j][0], b0.y + oacc[j][1]};
            *(float2*)(tgt3 + gi) = r0;
            size_t gi1 = gi + 8 * 256;
            float2 b1 = *(const float2*)(tgt2 + gi1);
            float2 r1 = {b1.x + oacc[j][2], b1.y + oacc[j][3]};
            *(float2*)(tgt3 + gi1) = r1;
            ssum += r0.x + r0.y + r1.x + r1.y;
            ssq  += r0.x*r0.x + r0.y*r0.y + r1.x*r1.x + r1.y*r1.y;
        }
    }

    // inline stats of tgt3
#pragma unroll
    for (int off = 16; off; off >>= 1) {
        ssum += __shfl_down_sync(0xffffffffu, ssum, off);
        ssq  += __shfl_down_sync(0xffffffffu, ssq,  off);
    }
    if (lane == 0) { ared[wid] = ssum; ared[8 + wid] = ssq; }
    __syncthreads();
    if (tid == 0) {
        float ts = 0.f, tq = 0.f;
#pragma unroll
        for (int i = 0; i < 8; ++i) { ts += ared[i]; tq += ared[8 + i]; }
        out_part[win*16 + 0] = ts; out_part[win*16 + 1] = tq;
    }
}

// ---------------- host orchestration ---------------------------------------
extern "C" void kernel_launch(void* const* d_in, const int* in_sizes, int n_in,
                              void* d_out, int out_size) {
    const float* src  = (const float*)d_in[0];
    const float* qf   = (const float*)d_in[1];
    const float* gn1w = (const float*)d_in[2];
    const float* gn1b = (const float*)d_in[3];
    const float* gn2w = (const float*)d_in[4];
    const float* gn2b = (const float*)d_in[5];
    const float* ls1  = (const float*)d_in[6];
    const float* ls2  = (const float*)d_in[7];
    const float* ls3  = (const float*)d_in[8];
    const float* qw   = (const float*)d_in[9];
    const float* qb   = (const float*)d_in[10];
    const float* kw   = (const float*)d_in[11];
    const float* kb   = (const float*)d_in[12];
    const float* vw   = (const float*)d_in[13];
    const float* vb   = (const float*)d_in[14];
    const float* fc1w = (const float*)d_in[15];
    const float* fc1b = (const float*)d_in[16];
    const float* fc2w = (const float*)d_in[17];
    const float* fc2b = (const float*)d_in[18];
    const float* gnfw = (const float*)d_in[19];
    const float* gnfb = (const float*)d_in[20];
    float* out = (float*)d_out;

    float *tgt, *tgt2, *tgt3, *fin, *p1, *p2, *p3;
    __nv_bfloat16 *memhi, *memlo, *tgthi, *tgtlo, *qkvhi, *qkvlo;
    __nv_bfloat16 *hinhi, *hinlo, *hhi, *hlo, *whi, *wlo;
    cudaGetSymbolAddress((void**)&tgt,  g_tgt);
    cudaGetSymbolAddress((void**)&tgt2, g_tgt2);
    cudaGetSymbolAddress((void**)&tgt3, g_tgt3);
    cudaGetSymbolAddress((void**)&fin,  g_fin);
    cudaGetSymbolAddress((void**)&p1,   g_p1);
    cudaGetSymbolAddress((void**)&p2,   g_p2);
    cudaGetSymbolAddress((void**)&p3,   g_p3);
    cudaGetSymbolAddress((void**)&memhi,g_memhi);
    cudaGetSymbolAddress((void**)&memlo,g_memlo);
    cudaGetSymbolAddress((void**)&tgthi,g_tgthi);
    cudaGetSymbolAddress((void**)&tgtlo,g_tgtlo);
    cudaGetSymbolAddress((void**)&qkvhi,g_qkvhi);
    cudaGetSymbolAddress((void**)&qkvlo,g_qkvlo);
    cudaGetSymbolAddress((void**)&hinhi,g_hinhi);
    cudaGetSymbolAddress((void**)&hinlo,g_hinlo);
    cudaGetSymbolAddress((void**)&hhi,  g_hhi);
    cudaGetSymbolAddress((void**)&hlo,  g_hlo);
    cudaGetSymbolAddress((void**)&whi,  g_whi);
    cudaGetSymbolAddress((void**)&wlo,  g_wlo);

    const int SM_ATTN = 73728;
    const int SM_TC   = 71680;
    cudaFuncSetAttribute(attn_kernel,    cudaFuncAttributeMaxDynamicSharedMemorySize, SM_ATTN);
    cudaFuncSetAttribute(gemm_tc_kernel, cudaFuncAttributeMaxDynamicSharedMemorySize, SM_TC);

    partition_kernel<<<65536, 256>>>(src, qf, memhi, memlo, tgthi, tgtlo, tgt);
    conv_w_all<<<448, 256>>>(qw, kw, vw, fc1w, fc2w, whi, wlo);
    gn_stats<<<NW, 256>>>(tgt, p1);               // stats for layer-0 gn1

    __nv_bfloat16 *khi = qkvhi + (size_t)NW*WSZ,  *klo = qkvlo + (size_t)NW*WSZ;
    __nv_bfloat16 *vhi = qkvhi + (size_t)2*NW*WSZ,*vlo = qkvlo + (size_t)2*NW*WSZ;

    for (int l = 0; l < 2; ++l) {
        int lC = l * CDIM;
        size_t lb = (size_t)l * 458752;
        // tgt2 = tgt + ls1 * mix(gn1(tgt))   (stats from p1)
        gn_mix_apply<<<dim3(NW,8), 256>>>(tgt, tgt, p1, 2, gn1w + lC, gn1b + lC, ls1 + lC, tgt2, nullptr);
        // merged Q/K/V
        gemm_tc_kernel<<<dim3(NW,6), 256, SM_TC>>>(whi + lb, wlo + lb,
            tgthi, tgtlo, memhi, memlo, qb + lC, kb + lC, vb + lC,
            nullptr, qkvhi, qkvlo, 256, 0, nullptr, nullptr, nullptr);
        // tgt3 = tgt2 + attention  (+stats -> p2)
        attn_kernel<<<NW, 256, SM_ATTN>>>(qkvhi, qkvlo, khi, klo, vhi, vlo, tgt2, tgt3, p2);
        // tgt3 = tgt2 + ls2*mix(gn1(tgt3))  (stats p2, partials -> p3)
        gn_mix_apply<<<dim3(NW,8), 256>>>(tgt3, tgt2, p2, 1, gn1w + lC, gn1b + lC, ls2 + lC, tgt3, p3);
        // hin = gn2(tgt3) -> bf16   (stats from p3, 8 slots)
        gn_elem_apply<<<dim3(NW,8), 256>>>(tgt3, p3, 8, gn2w + lC, gn2b + lC, nullptr, hinhi, hinlo);
        // h = gelu(fc1(hin))
        gemm_tc_kernel<<<dim3(NW,4), 256, SM_TC>>>(whi + lb + 196608, wlo + lb + 196608,
            hinhi, hinlo, nullptr, nullptr, fc1b + (size_t)l*512, nullptr, nullptr,
            nullptr, hhi, hlo, 256, 1, nullptr, nullptr, nullptr);
        // tgt = tgt3 + ls3*fc2(h)   (+stats -> p1 for next gn)
        gemm_tc_kernel<<<dim3(NW,2), 256, SM_TC>>>(whi + lb + 327680, wlo + lb + 327680,
            hhi, hlo, nullptr, nullptr, fc2b + lC, nullptr, nullptr,
            tgt, tgthi, tgtlo, 512, 2, tgt3, ls3 + lC, p1);
    }

    // final GN (stats from p1, 2 slots) + scatter
    gn_elem_apply<<<dim3(NW,8), 256>>>(tgt, p1, 2, gnfw, gnfb, fin, nullptr, nullptr);
    scatter_kernel<<<65536, 256>>>(fin, out);
}

// round 8
// speedup vs baseline: 3.6728x; 1.0553x over previous
#include <cuda_runtime.h>
#include <cuda_bf16.h>
#include <math.h>
#include <stdint.h>

#define NW   512
#define CDIM 256
#define PDIM 128
#define WSZ  (CDIM*PDIM)

// ---------------- scratch (static device globals; no allocations) ----------
__device__ float g_tgt [NW*WSZ];
__device__ float g_tgt2[NW*WSZ];
__device__ float g_tgt3[NW*WSZ];
__device__ float g_fin [NW*WSZ];
__device__ __nv_bfloat16 g_memhi[NW*WSZ], g_memlo[NW*WSZ];
__device__ __nv_bfloat16 g_tgthi[NW*WSZ], g_tgtlo[NW*WSZ];
__device__ __nv_bfloat16 g_qkvhi[3*NW*WSZ], g_qkvlo[3*NW*WSZ];
__device__ __nv_bfloat16 g_hhi [NW*2*WSZ], g_hlo [NW*2*WSZ];
__device__ __nv_bfloat16 g_whi[2*458752], g_wlo[2*458752];
__device__ float g_p1[NW*16];
__device__ float g_p2[NW*16];
__device__ float g_p3[NW*16];

// ================= helpers =================================================
__device__ __forceinline__ uint32_t smem_u32(const void* p) {
    uint32_t a;
    asm("{ .reg .u64 t; cvta.to.shared.u64 t, %1; cvt.u32.u64 %0, t; }" : "=r"(a) : "l"(p));
    return a;
}
#define LDSM_X4(r0,r1,r2,r3,addr) \
    asm volatile("ldmatrix.sync.aligned.m8n8.x4.shared.b16 {%0,%1,%2,%3}, [%4];" \
        : "=r"(r0),"=r"(r1),"=r"(r2),"=r"(r3) : "r"(addr))
#define LDSM_X4_T(r0,r1,r2,r3,addr) \
    asm volatile("ldmatrix.sync.aligned.m8n8.x4.trans.shared.b16 {%0,%1,%2,%3}, [%4];" \
        : "=r"(r0),"=r"(r1),"=r"(r2),"=r"(r3) : "r"(addr))
__device__ __forceinline__ void mma_bf16(float* d, const unsigned* a, const unsigned* b) {
    asm volatile("mma.sync.aligned.m16n8k16.row.col.f32.bf16.bf16.f32 "
        "{%0,%1,%2,%3}, {%4,%5,%6,%7}, {%8,%9}, {%0,%1,%2,%3};"
        : "+f"(d[0]),"+f"(d[1]),"+f"(d[2]),"+f"(d[3])
        : "r"(a[0]),"r"(a[1]),"r"(a[2]),"r"(a[3]), "r"(b[0]),"r"(b[1]));
}
__device__ __forceinline__ void split2(float a, float b, unsigned& h, unsigned& l) {
    __nv_bfloat16 ah = __float2bfloat16(a);
    __nv_bfloat16 bh = __float2bfloat16(b);
    __nv_bfloat16 al = __float2bfloat16(a - __bfloat162float(ah));
    __nv_bfloat16 bl = __float2bfloat16(b - __bfloat162float(bh));
    h = (unsigned)__bfloat16_as_ushort(ah) | ((unsigned)__bfloat16_as_ushort(bh) << 16);
    l = (unsigned)__bfloat16_as_ushort(al) | ((unsigned)__bfloat16_as_ushort(bl) << 16);
}
__device__ __forceinline__ void read_stats(const float* part, int win, int nparts,
                                           float& mean, float& rstd) {
    float S = 0.f, Q = 0.f;
    for (int i = 0; i < nparts; ++i) { S += part[win*16 + i*2]; Q += part[win*16 + i*2 + 1]; }
    mean = S * (1.f / 32768.f);
    float var = Q * (1.f / 32768.f) - mean * mean;
    rstd = rsqrtf(var + 1e-5f);
}

// ---------------- partition (merged src + qf) -------------------------------
__global__ void partition_kernel(const float* __restrict__ src, const float* __restrict__ qf,
                                 __nv_bfloat16* __restrict__ memhi, __nv_bfloat16* __restrict__ memlo,
                                 __nv_bfloat16* __restrict__ tgthi, __nv_bfloat16* __restrict__ tgtlo,
                                 float* __restrict__ tgt) {
    int gb = blockIdx.x;
    bool isq = gb >= 32768;
    int g = (isq ? gb - 32768 : gb) * 256 + threadIdx.x;
    int idx = g * 2;
    int p = idx & 127, c = (idx >> 7) & 255, bw = idx >> 15;
    int b = bw >> 7, wblk = bw & 127;
    int h = (wblk >> 3) * 8 + (p >> 4), w = (wblk & 7) * 16 + (p & 15);
    const float* s = (isq ? qf : src) + (((size_t)b * 256 + c) * 128 + h) * 128 + w;
    float a0 = s[0], a1 = s[1];
    unsigned hh, ll; split2(a0, a1, hh, ll);
    if (isq) {
        *(unsigned*)(tgthi + idx) = hh;
        *(unsigned*)(tgtlo + idx) = ll;
        *(float2*)(tgt + idx) = make_float2(a0, a1);
    } else {
        *(unsigned*)(memhi + idx) = hh;
        *(unsigned*)(memlo + idx) = ll;
    }
}

__global__ void scatter_kernel(const float* __restrict__ fin, float* __restrict__ out) {
    int idx = blockIdx.x * 256 + threadIdx.x;
    int c = idx & 255, b = (idx >> 8) & 3, n = idx >> 10;
    int h = n >> 7, w = n & 127;
    int win = b * 128 + (h >> 3) * 8 + (w >> 4);
    int p = (h & 7) * 16 + (w & 15);
    out[idx] = fin[(size_t)win * WSZ + c * 128 + p];
}

// ---------------- all weights fp32 -> hi/lo bf16 (one launch) ---------------
__global__ void conv_w_all(const float* __restrict__ qw, const float* __restrict__ kw,
                           const float* __restrict__ vw, const float* __restrict__ fc1w,
                           const float* __restrict__ fc2w,
                           __nv_bfloat16* __restrict__ hi, __nv_bfloat16* __restrict__ lo) {
    int g = blockIdx.x * 256 + threadIdx.x;
    int l = g / 57344, r = g - l * 57344;
    const float* srcp;
    size_t oo;
    if (r < 8192)        { srcp = qw  + (size_t)l*65536  + (size_t)r*8;          oo = (size_t)l*458752 + (size_t)r*8; }
    else if (r < 16384)  { srcp = kw  + (size_t)l*65536  + (size_t)(r-8192)*8;   oo = (size_t)l*458752 + 65536  + (size_t)(r-8192)*8; }
    else if (r < 24576)  { srcp = vw  + (size_t)l*65536  + (size_t)(r-16384)*8;  oo = (size_t)l*458752 + 131072 + (size_t)(r-16384)*8; }
    else if (r < 40960)  { srcp = fc1w+ (size_t)l*131072 + (size_t)(r-24576)*8;  oo = (size_t)l*458752 + 196608 + (size_t)(r-24576)*8; }
    else                 { srcp = fc2w+ (size_t)l*131072 + (size_t)(r-40960)*8;  oo = (size_t)l*458752 + 327680 + (size_t)(r-40960)*8; }
    unsigned hh[4], ll[4];
#pragma unroll
    for (int j = 0; j < 4; ++j) split2(srcp[2*j], srcp[2*j+1], hh[j], ll[j]);
    uint4 vh = {hh[0], hh[1], hh[2], hh[3]};
    uint4 vl = {ll[0], ll[1], ll[2], ll[3]};
    *(uint4*)(hi + oo) = vh;
    *(uint4*)(lo + oo) = vl;
}

// ---------------- GN stats (one CTA per window) ------------------------------
__global__ __launch_bounds__(256)
void gn_stats(const float* __restrict__ in, float* __restrict__ part) {
    __shared__ float red[16];
    int win = blockIdx.x, tid = threadIdx.x, lane = tid & 31, wid = tid >> 5;
    const float4* x = (const float4*)(in + (size_t)win * WSZ);
    float s = 0.f, q = 0.f;
#pragma unroll
    for (int k = 0; k < 32; ++k) {
        float4 v = x[tid + k * 256];
        s += v.x + v.y + v.z + v.w;
        q += v.x*v.x + v.y*v.y + v.z*v.z + v.w*v.w;
    }
#pragma unroll
    for (int off = 16; off; off >>= 1) {
        s += __shfl_down_sync(0xffffffffu, s, off);
        q += __shfl_down_sync(0xffffffffu, q, off);
    }
    if (lane == 0) { red[wid] = s; red[8 + wid] = q; }
    __syncthreads();
    if (tid == 0) {
        float ts = 0.f, tq = 0.f;
#pragma unroll
        for (int i = 0; i < 8; ++i) { ts += red[i]; tq += red[8 + i]; }
        part[win*16 + 0] = ts; part[win*16 + 1] = tq;
        part[win*16 + 2] = 0.f; part[win*16 + 3] = 0.f;
    }
}

// ---------------- GN apply + separable poolformer mix + residual -------------
__global__ __launch_bounds__(256)
void gn_mix_apply(const float* __restrict__ in, const float* __restrict__ basep,
                  const float* __restrict__ part, int nparts,
                  const float* __restrict__ gw, const float* __restrict__ gb,
                  const float* __restrict__ ls, float* __restrict__ outf,
                  float* __restrict__ out_part) {
    __shared__ float sm[32 * 132];
    __shared__ float hsb[32 * 132];
    __shared__ float red[16];
    int win = blockIdx.x, yb = blockIdx.y, tid = threadIdx.x, lane = tid & 31, wid = tid >> 5;
    float mean, rstd;
    read_stats(part, win, nparts, mean, rstd);

    const float4* src = (const float4*)(in + (size_t)win * WSZ + yb * 4096);
#pragma unroll
    for (int k = 0; k < 4; ++k) {
        int idx = tid + k * 256;
        int cl = idx >> 5, p4 = idx & 31;
        int c = yb * 32 + cl;
        float w = gw[c], bb = gb[c];
        float4 v = src[idx];
        v.x = (v.x - mean) * rstd * w + bb;
        v.y = (v.y - mean) * rstd * w + bb;
        v.z = (v.z - mean) * rstd * w + bb;
        v.w = (v.w - mean) * rstd * w + bb;
        *(float4*)(sm + cl * 132 + p4 * 4) = v;
    }
    __syncthreads();

    int p0 = lane * 4;
    int y = p0 >> 4, x0 = p0 & 15;
    float vcnt = 3.f - (y == 0 ? 1.f : 0.f) - (y == 7 ? 1.f : 0.f);
    float rinv[4];
#pragma unroll
    for (int j = 0; j < 4; ++j) {
        int x = x0 + j;
        float hc = 3.f - (x == 0 ? 1.f : 0.f) - (x == 15 ? 1.f : 0.f);
        rinv[j] = 1.f / (hc * vcnt);
    }
    bool le = (x0 == 0), re = (x0 == 12);

    // pass1: horizontal sums (each warp owns 4 whole channels)
#pragma unroll
    for (int ci = 0; ci < 4; ++ci) {
        int cl = wid * 4 + ci;
        const float* ch = sm + cl * 132;
        float4 v = *(const float4*)(ch + p0);
        float L = le ? 0.f : ch[p0 - 1];
        float R = re ? 0.f : ch[p0 + 4];
        float4 h;
        h.x = L + v.x + v.y;
        h.y = v.x + v.y + v.z;
        h.z = v.y + v.z + v.w;
        h.w = v.z + v.w + R;
        *(float4*)(hsb + cl * 132 + p0) = h;
    }
    __syncwarp();

    // pass2: vertical sums + mix + residual
    float s2 = 0.f, q2 = 0.f;
#pragma unroll
    for (int ci = 0; ci < 4; ++ci) {
        int cl = wid * 4 + ci;
        int c = yb * 32 + cl;
        const float* ch = sm + cl * 132;
        const float* hs = hsb + cl * 132;
        float4 mid = *(const float4*)(hs + p0);
        float4 up = (y > 0) ? *(const float4*)(hs + p0 - 16) : make_float4(0,0,0,0);
        float4 dn = (y < 7) ? *(const float4*)(hs + p0 + 16) : make_float4(0,0,0,0);
        float4 v = *(const float4*)(ch + p0);
        float o0 = (up.x + mid.x + dn.x) * rinv[0] - v.x;
        float o1 = (up.y + mid.y + dn.y) * rinv[1] - v.y;
        float o2 = (up.z + mid.z + dn.z) * rinv[2] - v.z;
        float o3 = (up.w + mid.w + dn.w) * rinv[3] - v.w;
        size_t gi = (size_t)win * WSZ + c * 128 + p0;
        float4 bv = *(const float4*)(basep + gi);
        float lsv = ls[c];
        float4 ov = {bv.x + lsv * o0, bv.y + lsv * o1,
                     bv.z + lsv * o2, bv.w + lsv * o3};
        *(float4*)(outf + gi) = ov;
        if (out_part) {
            s2 += ov.x + ov.y + ov.z + ov.w;
            q2 += ov.x*ov.x + ov.y*ov.y + ov.z*ov.z + ov.w*ov.w;
        }
    }
    if (out_part) {
#pragma unroll
        for (int off = 16; off; off >>= 1) {
            s2 += __shfl_down_sync(0xffffffffu, s2, off);
            q2 += __shfl_down_sync(0xffffffffu, q2, off);
        }
        if (lane == 0) { red[wid] = s2; red[8 + wid] = q2; }
        __syncthreads();
        if (tid == 0) {
            float ts = 0.f, tq = 0.f;
#pragma unroll
            for (int i = 0; i < 8; ++i) { ts += red[i]; tq += red[8 + i]; }
            out_part[win*16 + yb*2] = ts; out_part[win*16 + yb*2 + 1] = tq;
        }
    }
}

// ---------------- elementwise GN apply (final) -------------------------------
__global__ __launch_bounds__(256)
void gn_elem_apply(const float* __restrict__ in, const float* __restrict__ part, int nparts,
                   const float* __restrict__ gw, const float* __restrict__ gb,
                   float* __restrict__ outf) {
    int win = blockIdx.x, yb = blockIdx.y, tid = threadIdx.x;
    float mean, rstd;
    read_stats(part, win, nparts, mean, rstd);
    size_t b0 = (size_t)win * WSZ + yb * 4096;
    const float4* src = (const float4*)(in + b0);
#pragma unroll
    for (int k = 0; k < 4; ++k) {
        int idx = tid + k * 256;
        int c = yb * 32 + (idx >> 5);
        float w = gw[c], bb = gb[c];
        float4 v = src[idx];
        v.x = (v.x - mean) * rstd * w + bb;
        v.y = (v.y - mean) * rstd * w + bb;
        v.z = (v.z - mean) * rstd * w + bb;
        v.w = (v.w - mean) * rstd * w + bb;
        *(float4*)(outf + b0 + idx * 4) = v;
    }
}

// ---------------- tensor-core GEMM ------------------------------------------
// mode 0: merged QKV (bf16 X)   mode 1: fc1, X = gn2(tgt3 fp32) fused in staging
// mode 2: fc2 (bf16 X), out = base + ls*(.), fp32+bf16 out + partial stats
__global__ __launch_bounds__(256, 2)
void gemm_tc_kernel(const __nv_bfloat16* __restrict__ Wb_hi, const __nv_bfloat16* __restrict__ Wb_lo,
                    const __nv_bfloat16* __restrict__ Xa_hi, const __nv_bfloat16* __restrict__ Xa_lo,
                    const __nv_bfloat16* __restrict__ Xb_hi, const __nv_bfloat16* __restrict__ Xb_lo,
                    const float* __restrict__ Xf, const float* __restrict__ g2w,
                    const float* __restrict__ g2b, const float* __restrict__ statsp,
                    const float* __restrict__ b0p, const float* __restrict__ b1p,
                    const float* __restrict__ b2p,
                    float* __restrict__ Yf, __nv_bfloat16* __restrict__ Yhi,
                    __nv_bfloat16* __restrict__ Ylo,
                    int CIN, int mode,
                    const float* __restrict__ base, const float* __restrict__ ls,
                    float* __restrict__ partials) {
    extern __shared__ __nv_bfloat16 sb[];
    __nv_bfloat16* sWhi = sb;                 // [128][72]
    __nv_bfloat16* sWlo = sb + 9216;
    __nv_bfloat16* sXhi = sb + 18432;         // [64][136]
    __nv_bfloat16* sXlo = sb + 27136;
    int win = blockIdx.x, ob = blockIdx.y;
    int tid = threadIdx.x, lane = tid & 31, wid = tid >> 5;
    int wr = wid >> 1, wc = wid & 1;

    const __nv_bfloat16* gWhi = Wb_hi + (size_t)ob * 128 * CIN;
    const __nv_bfloat16* gWlo = Wb_lo + (size_t)ob * 128 * CIN;
    const __nv_bfloat16 *Xhi = nullptr, *Xlo = nullptr;
    const float* bias;
    int O, O0;
    size_t ybase = 0;
    float gmean = 0.f, grstd = 0.f;
    if (mode == 0) {
        int mat = ob >> 1;
        Xhi = mat ? Xb_hi : Xa_hi;
        Xlo = mat ? Xb_lo : Xa_lo;
        bias = (mat == 0) ? b0p : (mat == 1 ? b1p : b2p);
        O = 256; O0 = (ob & 1) * 128;
        ybase = (size_t)mat * NW * WSZ;
    } else if (mode == 1) {
        bias = b0p;
        O = 512; O0 = ob * 128;
        read_stats(statsp, win, 8, gmean, grstd);
    } else {
        Xhi = Xa_hi; Xlo = Xa_lo; bias = b0p;
        O = 256; O0 = ob * 128;
    }
    const uint4* gXhi4 = (mode != 1) ? (const uint4*)Xhi + (size_t)win * CIN * 16 : nullptr;
    const uint4* gXlo4 = (mode != 1) ? (const uint4*)Xlo + (size_t)win * CIN * 16 : nullptr;
    const float* gXf = (mode == 1) ? Xf + (size_t)win * WSZ : nullptr;

    float acc[2][8][4];
#pragma unroll
    for (int mt = 0; mt < 2; ++mt)
#pragma unroll
        for (int nt = 0; nt < 8; ++nt)
#pragma unroll
            for (int e = 0; e < 4; ++e) acc[mt][nt][e] = 0.f;

    int aRow = (lane & 15), aCol = (lane >> 4) * 8;
    int brbase = ((lane >> 3) & 1) * 8 + (lane & 7);
    int bcofs  = (lane >> 4) * 8;

    for (int kc = 0; kc < CIN; kc += 64) {
        __syncthreads();
#pragma unroll
        for (int i = tid; i < 1024; i += 256) {
            int r = i >> 3, c4 = i & 7;
            size_t go = (size_t)r * CIN + kc + c4 * 8;
            int so = r * 72 + c4 * 8;
            *(uint4*)(sWhi + so) = *(const uint4*)(gWhi + go);
            *(uint4*)(sWlo + so) = *(const uint4*)(gWlo + go);
        }
        if (mode == 1) {
#pragma unroll
            for (int i = tid; i < 2048; i += 256) {
                int r = i >> 5, p4 = i & 31;
                int c = kc + r;
                float4 v = *(const float4*)(gXf + (size_t)c * 128 + p4 * 4);
                float w = g2w[c], bb = g2b[c];
                v.x = (v.x - gmean) * grstd * w + bb;
                v.y = (v.y - gmean) * grstd * w + bb;
                v.z = (v.z - gmean) * grstd * w + bb;
                v.w = (v.w - gmean) * grstd * w + bb;
                unsigned h0, l0, h1, l1;
                split2(v.x, v.y, h0, l0);
                split2(v.z, v.w, h1, l1);
                uint2 vh = {h0, h1}, vl = {l0, l1};
                *(uint2*)(sXhi + r * 136 + p4 * 4) = vh;
                *(uint2*)(sXlo + r * 136 + p4 * 4) = vl;
            }
        } else {
#pragma unroll
            for (int i = tid; i < 1024; i += 256) {
                int r = i >> 4, c4 = i & 15;
                int gi = (kc + r) * 16 + c4;
                int so = r * 136 + c4 * 8;
                *(uint4*)(sXhi + so) = gXhi4[gi];
                *(uint4*)(sXlo + so) = gXlo4[gi];
            }
        }
        __syncthreads();
#pragma unroll
        for (int ks = 0; ks < 4; ++ks) {
            unsigned aHi[2][4], aLo[2][4];
#pragma unroll
            for (int mt = 0; mt < 2; ++mt) {
                int ro = (wr * 32 + mt * 16 + aRow) * 72 + ks * 16 + aCol;
                LDSM_X4(aHi[mt][0], aHi[mt][1], aHi[mt][2], aHi[mt][3], smem_u32(sWhi + ro));
                LDSM_X4(aLo[mt][0], aLo[mt][1], aLo[mt][2], aLo[mt][3], smem_u32(sWlo + ro));
            }
#pragma unroll
            for (int np = 0; np < 4; ++np) {
                int bo = (ks * 16 + brbase) * 136 + wc * 64 + np * 16 + bcofs;
                unsigned bHi[4], bLo[4];
                LDSM_X4_T(bHi[0], bHi[1], bHi[2], bHi[3], smem_u32(sXhi + bo));
                LDSM_X4_T(bLo[0], bLo[1], bLo[2], bLo[3], smem_u32(sXlo + bo));
#pragma unroll
                for (int mt = 0; mt < 2; ++mt) {
                    mma_bf16(acc[mt][np*2],   aHi[mt], bHi);
                    mma_bf16(acc[mt][np*2+1], aHi[mt], bHi + 2);
                    mma_bf16(acc[mt][np*2],   aHi[mt], bLo);
                    mma_bf16(acc[mt][np*2+1], aHi[mt], bLo + 2);
                    mma_bf16(acc[mt][np*2],   aLo[mt], bHi);
                    mma_bf16(acc[mt][np*2+1], aLo[mt], bHi + 2);
                }
            }
        }
    }

    float ssum = 0.f, ssq = 0.f;
#pragma unroll
    for (int mt = 0; mt < 2; ++mt)
#pragma unroll
        for (int nt = 0; nt < 8; ++nt) {
            int p = wc * 64 + nt * 8 + (lane & 3) * 2;
#pragma unroll
            for (int half = 0; half < 2; ++half) {
                int o = O0 + wr * 32 + mt * 16 + (lane >> 2) + half * 8;
                float bv = bias[o];
                float2 v;
                v.x = acc[mt][nt][half * 2]     + bv;
                v.y = acc[mt][nt][half * 2 + 1] + bv;
                size_t gi = ybase + ((size_t)win * O + o) * 128 + p;
                if (mode == 1) {
                    v.x = 0.5f * v.x * (1.f + erff(v.x * 0.70710678118654752f));
                    v.y = 0.5f * v.y * (1.f + erff(v.y * 0.70710678118654752f));
                } else if (mode == 2) {
                    float lsv = ls[o];
                    float2 b2 = *(const float2*)(base + gi);
                    v.x = b2.x + lsv * v.x;
                    v.y = b2.y + lsv * v.y;
                    *(float2*)(Yf + gi) = v;
                    ssum += v.x + v.y;
                    ssq  += v.x*v.x + v.y*v.y;
                }
                unsigned hh, ll; split2(v.x, v.y, hh, ll);
                *(unsigned*)(Yhi + gi) = hh;
                *(unsigned*)(Ylo + gi) = ll;
            }
        }

    if (mode == 2) {
        __syncthreads();
        float* red = (float*)sb;
#pragma unroll
        for (int off = 16; off; off >>= 1) {
            ssum += __shfl_down_sync(0xffffffffu, ssum, off);
            ssq  += __shfl_down_sync(0xffffffffu, ssq,  off);
        }
        if (lane == 0) { red[wid] = ssum; red[8 + wid] = ssq; }
        __syncthreads();
        if (tid == 0) {
            float ts = 0.f, tq = 0.f;
#pragma unroll
            for (int i = 0; i < 8; ++i) { ts += red[i]; tq += red[8 + i]; }
            partials[win*16 + ob*2] = ts; partials[win*16 + ob*2 + 1] = tq;
        }
    }
}

// ---------------- attention (+inline stats of tgt3) --------------------------
__global__ __launch_bounds__(256, 2)
void attn_kernel(const __nv_bfloat16* __restrict__ Qhi, const __nv_bfloat16* __restrict__ Qlo,
                 const __nv_bfloat16* __restrict__ Khi, const __nv_bfloat16* __restrict__ Klo,
                 const __nv_bfloat16* __restrict__ Vhi, const __nv_bfloat16* __restrict__ Vlo,
                 const float* __restrict__ tgt2, float* __restrict__ tgt3,
                 float* __restrict__ out_part) {
    extern __shared__ __nv_bfloat16 sat[];
    __nv_bfloat16* sQh = sat;
    __nv_bfloat16* sQl = sat + 9216;
    __nv_bfloat16* sKh = sat + 18432;
    __nv_bfloat16* sKl = sat + 27648;
    __shared__ float ared[16];
    int win = blockIdx.x, tid = threadIdx.x, lane = tid & 31, wid = tid >> 5;

    const uint4* gQh = (const uint4*)Qhi + (size_t)win * 4096;
    const uint4* gQl = (const uint4*)Qlo + (size_t)win * 4096;
    const uint4* gKh = (const uint4*)Khi + (size_t)win * 4096;
    const uint4* gKl = (const uint4*)Klo + (size_t)win * 4096;
    const uint4* gVh = (const uint4*)Vhi + (size_t)win * 4096;
    const uint4* gVl = (const uint4*)Vlo + (size_t)win * 4096;

    float acc[16][4];
#pragma unroll
    for (int j = 0; j < 16; ++j)
#pragma unroll
        for (int e = 0; e < 4; ++e) acc[j][e] = 0.f;

    int aRow = lane & 15, aCol = (lane >> 4) * 8;
    int kRow = (lane & 7) + ((lane >> 4) & 1) * 8;
    int kCol = ((lane >> 3) & 1) * 8;
    int tRow = ((lane >> 3) & 1) * 8 + (lane & 7);
    int tCol = (lane >> 4) * 8;

    for (int ch = 0; ch < 4; ++ch) {
        __syncthreads();
#pragma unroll
        for (int i = tid; i < 1024; i += 256) {
            int r = i >> 3, c4 = i & 7;
            int gi = r * 32 + ch * 8 + c4;
            int so = r * 72 + c4 * 8;
            *(uint4*)(sQh + so) = gQh[gi];
            *(uint4*)(sQl + so) = gQl[gi];
            *(uint4*)(sKh + so) = gKh[gi];
            *(uint4*)(sKl + so) = gKl[gi];
        }
        __syncthreads();
#pragma unroll
        for (int ks = 0; ks < 4; ++ks) {
            unsigned aHi[4], aLo[4];
            int ro = (wid * 16 + aRow) * 72 + ks * 16 + aCol;
            LDSM_X4(aHi[0], aHi[1], aHi[2], aHi[3], smem_u32(sQh + ro));
            LDSM_X4(aLo[0], aLo[1], aLo[2], aLo[3], smem_u32(sQl + ro));
#pragma unroll
            for (int ng = 0; ng < 8; ++ng) {
                int bo = (ng * 16 + kRow) * 72 + ks * 16 + kCol;
                unsigned bHi[4], bLo[4];
                LDSM_X4(bHi[0], bHi[1], bHi[2], bHi[3], smem_u32(sKh + bo));
                LDSM_X4(bLo[0], bLo[1], bLo[2], bLo[3], smem_u32(sKl + bo));
                mma_bf16(acc[ng*2],   aHi, bHi);
                mma_bf16(acc[ng*2+1], aHi, bHi + 2);
                mma_bf16(acc[ng*2],   aHi, bLo);
                mma_bf16(acc[ng*2+1], aHi, bLo + 2);
                mma_bf16(acc[ng*2],   aLo, bHi);
                mma_bf16(acc[ng*2+1], aLo, bHi + 2);
            }
        }
    }

    float mx0 = -1e30f, mx1 = -1e30f;
#pragma unroll
    for (int j = 0; j < 16; ++j) {
        mx0 = fmaxf(mx0, fmaxf(acc[j][0], acc[j][1]));
        mx1 = fmaxf(mx1, fmaxf(acc[j][2], acc[j][3]));
    }
#pragma unroll
    for (int off = 1; off <= 2; off <<= 1) {
        mx0 = fmaxf(mx0, __shfl_xor_sync(0xffffffffu, mx0, off));
        mx1 = fmaxf(mx1, __shfl_xor_sync(0xffffffffu, mx1, off));
    }
    float s0 = 0.f, s1 = 0.f;
#pragma unroll
    for (int j = 0; j < 16; ++j) {
        acc[j][0] = expf(acc[j][0] - mx0); s0 += acc[j][0];
        acc[j][1] = expf(acc[j][1] - mx0); s0 += acc[j][1];
        acc[j][2] = expf(acc[j][2] - mx1); s1 += acc[j][2];
        acc[j][3] = expf(acc[j][3] - mx1); s1 += acc[j][3];
    }
#pragma unroll
    for (int off = 1; off <= 2; off <<= 1) {
        s0 += __shfl_xor_sync(0xffffffffu, s0, off);
        s1 += __shfl_xor_sync(0xffffffffu, s1, off);
    }
    float i0 = 1.f / s0, i1 = 1.f / s1;
#pragma unroll
    for (int j = 0; j < 16; ++j) {
        acc[j][0] *= i0; acc[j][1] *= i0;
        acc[j][2] *= i1; acc[j][3] *= i1;
    }

    unsigned phi[8][4], plo[8][4];
#pragma unroll
    for (int t = 0; t < 8; ++t) {
        split2(acc[2*t][0],   acc[2*t][1],   phi[t][0], plo[t][0]);
        split2(acc[2*t][2],   acc[2*t][3],   phi[t][1], plo[t][1]);
        split2(acc[2*t+1][0], acc[2*t+1][1], phi[t][2], plo[t][2]);
        split2(acc[2*t+1][2], acc[2*t+1][3], phi[t][3], plo[t][3]);
    }

    float ssum = 0.f, ssq = 0.f;
    __nv_bfloat16* sVh = sat;
    __nv_bfloat16* sVl = sat + 17408;
    for (int cv = 0; cv < 2; ++cv) {
        __syncthreads();
#pragma unroll
        for (int i = tid; i < 2048; i += 256) {
            int r = i >> 4, c4 = i & 15;
            int gi = r * 32 + cv * 16 + c4;
            int so = r * 136 + c4 * 8;
            *(uint4*)(sVh + so) = gVh[gi];
            *(uint4*)(sVl + so) = gVl[gi];
        }
        __syncthreads();
        float oacc[16][4];
#pragma unroll
        for (int j = 0; j < 16; ++j)
#pragma unroll
            for (int e = 0; e < 4; ++e) oacc[j][e] = 0.f;
#pragma unroll
        for (int mk = 0; mk < 8; ++mk) {
#pragma unroll
            for (int ng = 0; ng < 8; ++ng) {
                int bo = (mk * 16 + tRow) * 136 + ng * 16 + tCol;
                unsigned vH[4], vL[4];
                LDSM_X4_T(vH[0], vH[1], vH[2], vH[3], smem_u32(sVh + bo));
                LDSM_X4_T(vL[0], vL[1], vL[2], vL[3], smem_u32(sVl + bo));
                mma_bf16(oacc[ng*2],   phi[mk], vH);
                mma_bf16(oacc[ng*2+1], phi[mk], vH + 2);
                mma_bf16(oacc[ng*2],   phi[mk], vL);
                mma_bf16(oacc[ng*2+1], phi[mk], vL + 2);
                mma_bf16(oacc[ng*2],   plo[mk], vH);
                mma_bf16(oacc[ng*2+1], plo[mk], vH + 2);
            }
        }
#pragma unroll
        for (int j = 0; j < 16; ++j) {
            int col = cv * 128 + j * 8 + (lane & 3) * 2;
            int n0 = wid * 16 + (lane >> 2);
            size_t gi = (size_t)win * WSZ + n0 * 256 + col;
            float2 b0 = *(const float2*)(tgt2 + gi);
            float2 r0 = {b0.x + oacc[j][0], b0.y + oacc[j][1]};
            *(float2*)(tgt3 + gi) = r0;
            size_t gi1 = gi + 8 * 256;
            float2 b1 = *(const float2*)(tgt2 + gi1);
            float2 r1 = {b1.x + oacc[j][2], b1.y + oacc[j][3]};
            *(float2*)(tgt3 + gi1) = r1;
            ssum += r0.x + r0.y + r1.x + r1.y;
            ssq  += r0.x*r0.x + r0.y*r0.y + r1.x*r1.x + r1.y*r1.y;
        }
    }

#pragma unroll
    for (int off = 16; off; off >>= 1) {
        ssum += __shfl_down_sync(0xffffffffu, ssum, off);
        ssq  += __shfl_down_sync(0xffffffffu, ssq,  off);
    }
    if (lane == 0) { ared[wid] = ssum; ared[8 + wid] = ssq; }
    __syncthreads();
    if (tid == 0) {
        float ts = 0.f, tq = 0.f;
#pragma unroll
        for (int i = 0; i < 8; ++i) { ts += ared[i]; tq += ared[8 + i]; }
        out_part[win*16 + 0] = ts; out_part[win*16 + 1] = tq;
    }
}

// ---------------- host orchestration ---------------------------------------
extern "C" void kernel_launch(void* const* d_in, const int* in_sizes, int n_in,
                              void* d_out, int out_size) {
    const float* src  = (const float*)d_in[0];
    const float* qf   = (const float*)d_in[1];
    const float* gn1w = (const float*)d_in[2];
    const float* gn1b = (const float*)d_in[3];
    const float* gn2w = (const float*)d_in[4];
    const float* gn2b = (const float*)d_in[5];
    const float* ls1  = (const float*)d_in[6];
    const float* ls2  = (const float*)d_in[7];
    const float* ls3  = (const float*)d_in[8];
    const float* qw   = (const float*)d_in[9];
    const float* qb   = (const float*)d_in[10];
    const float* kw   = (const float*)d_in[11];
    const float* kb   = (const float*)d_in[12];
    const float* vw   = (const float*)d_in[13];
    const float* vb   = (const float*)d_in[14];
    const float* fc1w = (const float*)d_in[15];
    const float* fc1b = (const float*)d_in[16];
    const float* fc2w = (const float*)d_in[17];
    const float* fc2b = (const float*)d_in[18];
    const float* gnfw = (const float*)d_in[19];
    const float* gnfb = (const float*)d_in[20];
    float* out = (float*)d_out;

    float *tgt, *tgt2, *tgt3, *fin, *p1, *p2, *p3;
    __nv_bfloat16 *memhi, *memlo, *tgthi, *tgtlo, *qkvhi, *qkvlo;
    __nv_bfloat16 *hhi, *hlo, *whi, *wlo;
    cudaGetSymbolAddress((void**)&tgt,  g_tgt);
    cudaGetSymbolAddress((void**)&tgt2, g_tgt2);
    cudaGetSymbolAddress((void**)&tgt3, g_tgt3);
    cudaGetSymbolAddress((void**)&fin,  g_fin);
    cudaGetSymbolAddress((void**)&p1,   g_p1);
    cudaGetSymbolAddress((void**)&p2,   g_p2);
    cudaGetSymbolAddress((void**)&p3,   g_p3);
    cudaGetSymbolAddress((void**)&memhi,g_memhi);
    cudaGetSymbolAddress((void**)&memlo,g_memlo);
    cudaGetSymbolAddress((void**)&tgthi,g_tgthi);
    cudaGetSymbolAddress((void**)&tgtlo,g_tgtlo);
    cudaGetSymbolAddress((void**)&qkvhi,g_qkvhi);
    cudaGetSymbolAddress((void**)&qkvlo,g_qkvlo);
    cudaGetSymbolAddress((void**)&hhi,  g_hhi);
    cudaGetSymbolAddress((void**)&hlo,  g_hlo);
    cudaGetSymbolAddress((void**)&whi,  g_whi);
    cudaGetSymbolAddress((void**)&wlo,  g_wlo);

    const int SM_ATTN = 73728;
    const int SM_TC   = 71680;
    cudaFuncSetAttribute(attn_kernel,    cudaFuncAttributeMaxDynamicSharedMemorySize, SM_ATTN);
    cudaFuncSetAttribute(gemm_tc_kernel, cudaFuncAttributeMaxDynamicSharedMemorySize, SM_TC);

    partition_kernel<<<65536, 256>>>(src, qf, memhi, memlo, tgthi, tgtlo, tgt);
    conv_w_all<<<448, 256>>>(qw, kw, vw, fc1w, fc2w, whi, wlo);
    gn_stats<<<NW, 256>>>(tgt, p1);

    __nv_bfloat16 *khi = qkvhi + (size_t)NW*WSZ,  *klo = qkvlo + (size_t)NW*WSZ;
    __nv_bfloat16 *vhi = qkvhi + (size_t)2*NW*WSZ,*vlo = qkvlo + (size_t)2*NW*WSZ;

    for (int l = 0; l < 2; ++l) {
        int lC = l * CDIM;
        size_t lb = (size_t)l * 458752;
        // tgt2 = tgt + ls1 * mix(gn1(tgt))
        gn_mix_apply<<<dim3(NW,8), 256>>>(tgt, tgt, p1, 2, gn1w + lC, gn1b + lC, ls1 + lC, tgt2, nullptr);
        // merged Q/K/V
        gemm_tc_kernel<<<dim3(NW,6), 256, SM_TC>>>(whi + lb, wlo + lb,
            tgthi, tgtlo, memhi, memlo, nullptr, nullptr, nullptr, nullptr,
            qb + lC, kb + lC, vb + lC,
            nullptr, qkvhi, qkvlo, 256, 0, nullptr, nullptr, nullptr);
        // tgt3 = tgt2 + attention  (+stats -> p2)
        attn_kernel<<<NW, 256, SM_ATTN>>>(qkvhi, qkvlo, khi, klo, vhi, vlo, tgt2, tgt3, p2);
        // tgt3 = tgt2 + ls2*mix(gn1(tgt3))  (stats p2, partials -> p3)
        gn_mix_apply<<<dim3(NW,8), 256>>>(tgt3, tgt2, p2, 1, gn1w + lC, gn1b + lC, ls2 + lC, tgt3, p3);
        // h = gelu(fc1(gn2(tgt3)))  (gn2 fused into staging; stats p3)
        gemm_tc_kernel<<<dim3(NW,4), 256, SM_TC>>>(whi + lb + 196608, wlo + lb + 196608,
            nullptr, nullptr, nullptr, nullptr, tgt3, gn2w + lC, gn2b + lC, p3,
            fc1b + (size_t)l*512, nullptr, nullptr,
            nullptr, hhi, hlo, 256, 1, nullptr, nullptr, nullptr);
        // tgt = tgt3 + ls3*fc2(h)  (+stats -> p1)
        gemm_tc_kernel<<<dim3(NW,2), 256, SM_TC>>>(whi + lb + 327680, wlo + lb + 327680,
            hhi, hlo, nullptr, nullptr, nullptr, nullptr, nullptr, nullptr,
            fc2b + lC, nullptr, nullptr,
            tgt, tgthi, tgtlo, 512, 2, tgt3, ls3 + lC, p1);
    }

    gn_elem_apply<<<dim3(NW,8), 256>>>(tgt, p1, 2, gnfw, gnfb, fin);
    scatter_kernel<<<65536, 256>>>(fin, out);
}

// round 9
// speedup vs baseline: 4.0726x; 1.1089x over previous
#include <cuda_runtime.h>
#include <cuda_fp16.h>
#include <math.h>
#include <stdint.h>

#define NW   512
#define CDIM 256
#define PDIM 128
#define WSZ  (CDIM*PDIM)

// ---------------- scratch (static device globals; no allocations) ----------
__device__ float g_tgt [NW*WSZ];
__device__ float g_tgt2[NW*WSZ];
__device__ float g_tgt3[NW*WSZ];
__device__ float g_fin [NW*WSZ];
__device__ __half g_memh[NW*WSZ];          // mem single fp16
__device__ __half g_tgth[NW*WSZ];          // tgt single fp16
__device__ __half g_qh [NW*WSZ], g_ql [NW*WSZ];   // Q hi/lo (A-operand in attn)
__device__ __half g_kh [NW*WSZ];           // K single
__device__ __half g_vh [NW*WSZ];           // V single
__device__ __half g_hh [NW*2*WSZ];         // FFN hidden single
__device__ __half g_wh[2*458752], g_wl[2*458752]; // weights hi/lo
__device__ float g_p1[NW*16];
__device__ float g_p2[NW*16];
__device__ float g_p3[NW*16];

// ================= helpers =================================================
__device__ __forceinline__ uint32_t smem_u32(const void* p) {
    uint32_t a;
    asm("{ .reg .u64 t; cvta.to.shared.u64 t, %1; cvt.u32.u64 %0, t; }" : "=r"(a) : "l"(p));
    return a;
}
#define LDSM_X4(r0,r1,r2,r3,addr) \
    asm volatile("ldmatrix.sync.aligned.m8n8.x4.shared.b16 {%0,%1,%2,%3}, [%4];" \
        : "=r"(r0),"=r"(r1),"=r"(r2),"=r"(r3) : "r"(addr))
#define LDSM_X4_T(r0,r1,r2,r3,addr) \
    asm volatile("ldmatrix.sync.aligned.m8n8.x4.trans.shared.b16 {%0,%1,%2,%3}, [%4];" \
        : "=r"(r0),"=r"(r1),"=r"(r2),"=r"(r3) : "r"(addr))
__device__ __forceinline__ void mma_f16(float* d, const unsigned* a, const unsigned* b) {
    asm volatile("mma.sync.aligned.m16n8k16.row.col.f32.f16.f16.f32 "
        "{%0,%1,%2,%3}, {%4,%5,%6,%7}, {%8,%9}, {%0,%1,%2,%3};"
        : "+f"(d[0]),"+f"(d[1]),"+f"(d[2]),"+f"(d[3])
        : "r"(a[0]),"r"(a[1]),"r"(a[2]),"r"(a[3]), "r"(b[0]),"r"(b[1]));
}
__device__ __forceinline__ unsigned pack2h(float a, float b) {
    __half ah = __float2half_rn(a), bh = __float2half_rn(b);
    return (unsigned)__half_as_ushort(ah) | ((unsigned)__half_as_ushort(bh) << 16);
}
__device__ __forceinline__ void split2h(float a, float b, unsigned& h, unsigned& l) {
    __half ah = __float2half_rn(a), bh = __float2half_rn(b);
    __half al = __float2half_rn(a - __half2float(ah));
    __half bl = __float2half_rn(b - __half2float(bh));
    h = (unsigned)__half_as_ushort(ah) | ((unsigned)__half_as_ushort(bh) << 16);
    l = (unsigned)__half_as_ushort(al) | ((unsigned)__half_as_ushort(bl) << 16);
}
__device__ __forceinline__ void read_stats(const float* part, int win, int nparts,
                                           float& mean, float& rstd) {
    float S = 0.f, Q = 0.f;
    for (int i = 0; i < nparts; ++i) { S += part[win*16 + i*2]; Q += part[win*16 + i*2 + 1]; }
    mean = S * (1.f / 32768.f);
    float var = Q * (1.f / 32768.f) - mean * mean;
    rstd = rsqrtf(var + 1e-5f);
}

// ---------------- partition (merged src + qf) -------------------------------
__global__ void partition_kernel(const float* __restrict__ src, const float* __restrict__ qf,
                                 __half* __restrict__ memh, __half* __restrict__ tgth,
                                 float* __restrict__ tgt) {
    int gb = blockIdx.x;
    bool isq = gb >= 32768;
    int g = (isq ? gb - 32768 : gb) * 256 + threadIdx.x;
    int idx = g * 2;
    int p = idx & 127, c = (idx >> 7) & 255, bw = idx >> 15;
    int b = bw >> 7, wblk = bw & 127;
    int h = (wblk >> 3) * 8 + (p >> 4), w = (wblk & 7) * 16 + (p & 15);
    const float* s = (isq ? qf : src) + (((size_t)b * 256 + c) * 128 + h) * 128 + w;
    float a0 = s[0], a1 = s[1];
    unsigned u = pack2h(a0, a1);
    if (isq) {
        *(unsigned*)(tgth + idx) = u;
        *(float2*)(tgt + idx) = make_float2(a0, a1);
    } else {
        *(unsigned*)(memh + idx) = u;
    }
}

__global__ void scatter_kernel(const float* __restrict__ fin, float* __restrict__ out) {
    int idx = blockIdx.x * 256 + threadIdx.x;
    int c = idx & 255, b = (idx >> 8) & 3, n = idx >> 10;
    int h = n >> 7, w = n & 127;
    int win = b * 128 + (h >> 3) * 8 + (w >> 4);
    int p = (h & 7) * 16 + (w & 15);
    out[idx] = fin[(size_t)win * WSZ + c * 128 + p];
}

// ---------------- all weights fp32 -> hi/lo fp16 (one launch) ---------------
__global__ void conv_w_all(const float* __restrict__ qw, const float* __restrict__ kw,
                           const float* __restrict__ vw, const float* __restrict__ fc1w,
                           const float* __restrict__ fc2w,
                           __half* __restrict__ hi, __half* __restrict__ lo) {
    int g = blockIdx.x * 256 + threadIdx.x;
    int l = g / 57344, r = g - l * 57344;
    const float* srcp;
    size_t oo;
    if (r < 8192)        { srcp = qw  + (size_t)l*65536  + (size_t)r*8;          oo = (size_t)l*458752 + (size_t)r*8; }
    else if (r < 16384)  { srcp = kw  + (size_t)l*65536  + (size_t)(r-8192)*8;   oo = (size_t)l*458752 + 65536  + (size_t)(r-8192)*8; }
    else if (r < 24576)  { srcp = vw  + (size_t)l*65536  + (size_t)(r-16384)*8;  oo = (size_t)l*458752 + 131072 + (size_t)(r-16384)*8; }
    else if (r < 40960)  { srcp = fc1w+ (size_t)l*131072 + (size_t)(r-24576)*8;  oo = (size_t)l*458752 + 196608 + (size_t)(r-24576)*8; }
    else                 { srcp = fc2w+ (size_t)l*131072 + (size_t)(r-40960)*8;  oo = (size_t)l*458752 + 327680 + (size_t)(r-40960)*8; }
    unsigned hh[4], ll[4];
#pragma unroll
    for (int j = 0; j < 4; ++j) split2h(srcp[2*j], srcp[2*j+1], hh[j], ll[j]);
    uint4 vh = {hh[0], hh[1], hh[2], hh[3]};
    uint4 vl = {ll[0], ll[1], ll[2], ll[3]};
    *(uint4*)(hi + oo) = vh;
    *(uint4*)(lo + oo) = vl;
}

// ---------------- GN stats ---------------------------------------------------
__global__ __launch_bounds__(256)
void gn_stats(const float* __restrict__ in, float* __restrict__ part) {
    __shared__ float red[16];
    int win = blockIdx.x, tid = threadIdx.x, lane = tid & 31, wid = tid >> 5;
    const float4* x = (const float4*)(in + (size_t)win * WSZ);
    float s = 0.f, q = 0.f;
#pragma unroll
    for (int k = 0; k < 32; ++k) {
        float4 v = x[tid + k * 256];
        s += v.x + v.y + v.z + v.w;
        q += v.x*v.x + v.y*v.y + v.z*v.z + v.w*v.w;
    }
#pragma unroll
    for (int off = 16; off; off >>= 1) {
        s += __shfl_down_sync(0xffffffffu, s, off);
        q += __shfl_down_sync(0xffffffffu, q, off);
    }
    if (lane == 0) { red[wid] = s; red[8 + wid] = q; }
    __syncthreads();
    if (tid == 0) {
        float ts = 0.f, tq = 0.f;
#pragma unroll
        for (int i = 0; i < 8; ++i) { ts += red[i]; tq += red[8 + i]; }
        part[win*16 + 0] = ts; part[win*16 + 1] = tq;
        part[win*16 + 2] = 0.f; part[win*16 + 3] = 0.f;
    }
}

// ---------------- GN apply + separable poolformer mix + residual -------------
__global__ __launch_bounds__(256)
void gn_mix_apply(const float* __restrict__ in, const float* __restrict__ basep,
                  const float* __restrict__ part, int nparts,
                  const float* __restrict__ gw, const float* __restrict__ gb,
                  const float* __restrict__ ls, float* __restrict__ outf,
                  float* __restrict__ out_part) {
    __shared__ float sm[32 * 132];
    __shared__ float hsb[32 * 132];
    __shared__ float red[16];
    int win = blockIdx.x, yb = blockIdx.y, tid = threadIdx.x, lane = tid & 31, wid = tid >> 5;
    float mean, rstd;
    read_stats(part, win, nparts, mean, rstd);

    const float4* src = (const float4*)(in + (size_t)win * WSZ + yb * 4096);
#pragma unroll
    for (int k = 0; k < 4; ++k) {
        int idx = tid + k * 256;
        int cl = idx >> 5, p4 = idx & 31;
        int c = yb * 32 + cl;
        float w = gw[c], bb = gb[c];
        float4 v = src[idx];
        v.x = (v.x - mean) * rstd * w + bb;
        v.y = (v.y - mean) * rstd * w + bb;
        v.z = (v.z - mean) * rstd * w + bb;
        v.w = (v.w - mean) * rstd * w + bb;
        *(float4*)(sm + cl * 132 + p4 * 4) = v;
    }
    __syncthreads();

    int p0 = lane * 4;
    int y = p0 >> 4, x0 = p0 & 15;
    float vcnt = 3.f - (y == 0 ? 1.f : 0.f) - (y == 7 ? 1.f : 0.f);
    float rinv[4];
#pragma unroll
    for (int j = 0; j < 4; ++j) {
        int x = x0 + j;
        float hc = 3.f - (x == 0 ? 1.f : 0.f) - (x == 15 ? 1.f : 0.f);
        rinv[j] = 1.f / (hc * vcnt);
    }
    bool le = (x0 == 0), re = (x0 == 12);

#pragma unroll
    for (int ci = 0; ci < 4; ++ci) {
        int cl = wid * 4 + ci;
        const float* ch = sm + cl * 132;
        float4 v = *(const float4*)(ch + p0);
        float L = le ? 0.f : ch[p0 - 1];
        float R = re ? 0.f : ch[p0 + 4];
        float4 h;
        h.x = L + v.x + v.y;
        h.y = v.x + v.y + v.z;
        h.z = v.y + v.z + v.w;
        h.w = v.z + v.w + R;
        *(float4*)(hsb + cl * 132 + p0) = h;
    }
    __syncwarp();

    float s2 = 0.f, q2 = 0.f;
#pragma unroll
    for (int ci = 0; ci < 4; ++ci) {
        int cl = wid * 4 + ci;
        int c = yb * 32 + cl;
        const float* ch = sm + cl * 132;
        const float* hs = hsb + cl * 132;
        float4 mid = *(const float4*)(hs + p0);
        float4 up = (y > 0) ? *(const float4*)(hs + p0 - 16) : make_float4(0,0,0,0);
        float4 dn = (y < 7) ? *(const float4*)(hs + p0 + 16) : make_float4(0,0,0,0);
        float4 v = *(const float4*)(ch + p0);
        float o0 = (up.x + mid.x + dn.x) * rinv[0] - v.x;
        float o1 = (up.y + mid.y + dn.y) * rinv[1] - v.y;
        float o2 = (up.z + mid.z + dn.z) * rinv[2] - v.z;
        float o3 = (up.w + mid.w + dn.w) * rinv[3] - v.w;
        size_t gi = (size_t)win * WSZ + c * 128 + p0;
        float4 bv = *(const float4*)(basep + gi);
        float lsv = ls[c];
        float4 ov = {bv.x + lsv * o0, bv.y + lsv * o1,
                     bv.z + lsv * o2, bv.w + lsv * o3};
        *(float4*)(outf + gi) = ov;
        if (out_part) {
            s2 += ov.x + ov.y + ov.z + ov.w;
            q2 += ov.x*ov.x + ov.y*ov.y + ov.z*ov.z + ov.w*ov.w;
        }
    }
    if (out_part) {
#pragma unroll
        for (int off = 16; off; off >>= 1) {
            s2 += __shfl_down_sync(0xffffffffu, s2, off);
            q2 += __shfl_down_sync(0xffffffffu, q2, off);
        }
        if (lane == 0) { red[wid] = s2; red[8 + wid] = q2; }
        __syncthreads();
        if (tid == 0) {
            float ts = 0.f, tq = 0.f;
#pragma unroll
            for (int i = 0; i < 8; ++i) { ts += red[i]; tq += red[8 + i]; }
            out_part[win*16 + yb*2] = ts; out_part[win*16 + yb*2 + 1] = tq;
        }
    }
}

// ---------------- elementwise GN apply (final) -------------------------------
__global__ __launch_bounds__(256)
void gn_elem_apply(const float* __restrict__ in, const float* __restrict__ part, int nparts,
                   const float* __restrict__ gw, const float* __restrict__ gb,
                   float* __restrict__ outf) {
    int win = blockIdx.x, yb = blockIdx.y, tid = threadIdx.x;
    float mean, rstd;
    read_stats(part, win, nparts, mean, rstd);
    size_t b0 = (size_t)win * WSZ + yb * 4096;
    const float4* src = (const float4*)(in + b0);
#pragma unroll
    for (int k = 0; k < 4; ++k) {
        int idx = tid + k * 256;
        int c = yb * 32 + (idx >> 5);
        float w = gw[c], bb = gb[c];
        float4 v = src[idx];
        v.x = (v.x - mean) * rstd * w + bb;
        v.y = (v.y - mean) * rstd * w + bb;
        v.z = (v.z - mean) * rstd * w + bb;
        v.w = (v.w - mean) * rstd * w + bb;
        *(float4*)(outf + b0 + idx * 4) = v;
    }
}

// ---------------- tensor-core GEMM ------------------------------------------
// A = W (hi/lo fp16, 2-term), B = X (single fp16).
// mode 0: merged QKV. ob/2: 0=Q(out hi/lo), 1=K(single), 2=V(single)
// mode 1: fc1; X = gn2(tgt3 fp32) fused in staging; out = gelu -> single
// mode 2: fc2; out = base + ls*(.) -> fp32 + single + partial stats
__global__ __launch_bounds__(256, 2)
void gemm_tc_kernel(const __half* __restrict__ Wh, const __half* __restrict__ Wl,
                    const __half* __restrict__ Xa, const __half* __restrict__ Xb,
                    const float* __restrict__ Xf, const float* __restrict__ g2w,
                    const float* __restrict__ g2b, const float* __restrict__ statsp,
                    const float* __restrict__ b0p, const float* __restrict__ b1p,
                    const float* __restrict__ b2p,
                    float* __restrict__ Yf,
                    __half* __restrict__ Yq, __half* __restrict__ Yql,
                    __half* __restrict__ Yk, __half* __restrict__ Yv,
                    int CIN, int mode,
                    const float* __restrict__ base, const float* __restrict__ ls,
                    float* __restrict__ partials) {
    extern __shared__ __half sb[];
    __half* sWhi = sb;                 // [128][72]
    __half* sWlo = sb + 9216;
    __half* sX   = sb + 18432;         // [64][136]
    int win = blockIdx.x, ob = blockIdx.y;
    int tid = threadIdx.x, lane = tid & 31, wid = tid >> 5;
    int wr = wid >> 1, wc = wid & 1;

    const __half* gWhi = Wh + (size_t)ob * 128 * CIN;
    const __half* gWlo = Wl + (size_t)ob * 128 * CIN;
    const __half* X = nullptr;
    __half* outH = nullptr;
    __half* outL = nullptr;
    const float* bias;
    int O, O0;
    float gmean = 0.f, grstd = 0.f;
    if (mode == 0) {
        int mat = ob >> 1;
        X = (mat == 0) ? Xa : Xb;
        bias = (mat == 0) ? b0p : (mat == 1 ? b1p : b2p);
        outH = (mat == 0) ? Yq : (mat == 1 ? Yk : Yv);
        outL = (mat == 0) ? Yql : nullptr;
        O = 256; O0 = (ob & 1) * 128;
    } else if (mode == 1) {
        bias = b0p;
        O = 512; O0 = ob * 128;
        outH = Yq;
        read_stats(statsp, win, 8, gmean, grstd);
    } else {
        X = Xa; bias = b0p;
        O = 256; O0 = ob * 128;
        outH = Yq;
    }
    const uint4* gX4 = (mode != 1) ? (const uint4*)X + (size_t)win * CIN * 16 : nullptr;
    const float* gXf = (mode == 1) ? Xf + (size_t)win * WSZ : nullptr;

    float acc[2][8][4];
#pragma unroll
    for (int mt = 0; mt < 2; ++mt)
#pragma unroll
        for (int nt = 0; nt < 8; ++nt)
#pragma unroll
            for (int e = 0; e < 4; ++e) acc[mt][nt][e] = 0.f;

    int aRow = (lane & 15), aCol = (lane >> 4) * 8;
    int brbase = ((lane >> 3) & 1) * 8 + (lane & 7);
    int bcofs  = (lane >> 4) * 8;

    for (int kc = 0; kc < CIN; kc += 64) {
        __syncthreads();
#pragma unroll
        for (int i = tid; i < 1024; i += 256) {      // W tiles
            int r = i >> 3, c4 = i & 7;
            size_t go = (size_t)r * CIN + kc + c4 * 8;
            int so = r * 72 + c4 * 8;
            *(uint4*)(sWhi + so) = *(const uint4*)(gWhi + go);
            *(uint4*)(sWlo + so) = *(const uint4*)(gWlo + go);
        }
        if (mode == 1) {
#pragma unroll
            for (int i = tid; i < 2048; i += 256) {
                int r = i >> 5, p4 = i & 31;
                int c = kc + r;
                float4 v = *(const float4*)(gXf + (size_t)c * 128 + p4 * 4);
                float w = g2w[c], bb = g2b[c];
                v.x = (v.x - gmean) * grstd * w + bb;
                v.y = (v.y - gmean) * grstd * w + bb;
                v.z = (v.z - gmean) * grstd * w + bb;
                v.w = (v.w - gmean) * grstd * w + bb;
                uint2 u = {pack2h(v.x, v.y), pack2h(v.z, v.w)};
                *(uint2*)(sX + r * 136 + p4 * 4) = u;
            }
        } else {
#pragma unroll
            for (int i = tid; i < 1024; i += 256) {
                int r = i >> 4, c4 = i & 15;
                int gi = (kc + r) * 16 + c4;
                int so = r * 136 + c4 * 8;
                *(uint4*)(sX + so) = gX4[gi];
            }
        }
        __syncthreads();
#pragma unroll
        for (int ks = 0; ks < 4; ++ks) {
            unsigned aHi[2][4], aLo[2][4];
#pragma unroll
            for (int mt = 0; mt < 2; ++mt) {
                int ro = (wr * 32 + mt * 16 + aRow) * 72 + ks * 16 + aCol;
                LDSM_X4(aHi[mt][0], aHi[mt][1], aHi[mt][2], aHi[mt][3], smem_u32(sWhi + ro));
                LDSM_X4(aLo[mt][0], aLo[mt][1], aLo[mt][2], aLo[mt][3], smem_u32(sWlo + ro));
            }
#pragma unroll
            for (int np = 0; np < 4; ++np) {
                int bo = (ks * 16 + brbase) * 136 + wc * 64 + np * 16 + bcofs;
                unsigned bX[4];
                LDSM_X4_T(bX[0], bX[1], bX[2], bX[3], smem_u32(sX + bo));
#pragma unroll
                for (int mt = 0; mt < 2; ++mt) {
                    mma_f16(acc[mt][np*2],   aHi[mt], bX);
                    mma_f16(acc[mt][np*2+1], aHi[mt], bX + 2);
                    mma_f16(acc[mt][np*2],   aLo[mt], bX);
                    mma_f16(acc[mt][np*2+1], aLo[mt], bX + 2);
                }
            }
        }
    }

    float ssum = 0.f, ssq = 0.f;
#pragma unroll
    for (int mt = 0; mt < 2; ++mt)
#pragma unroll
        for (int nt = 0; nt < 8; ++nt) {
            int p = wc * 64 + nt * 8 + (lane & 3) * 2;
#pragma unroll
            for (int half = 0; half < 2; ++half) {
                int o = O0 + wr * 32 + mt * 16 + (lane >> 2) + half * 8;
                float bv = bias[o];
                float2 v;
                v.x = acc[mt][nt][half * 2]     + bv;
                v.y = acc[mt][nt][half * 2 + 1] + bv;
                size_t gi = ((size_t)win * O + o) * 128 + p;
                if (mode == 1) {
                    v.x = 0.5f * v.x * (1.f + erff(v.x * 0.70710678118654752f));
                    v.y = 0.5f * v.y * (1.f + erff(v.y * 0.70710678118654752f));
                } else if (mode == 2) {
                    float lsv = ls[o];
                    float2 b2 = *(const float2*)(base + gi);
                    v.x = b2.x + lsv * v.x;
                    v.y = b2.y + lsv * v.y;
                    *(float2*)(Yf + gi) = v;
                    ssum += v.x + v.y;
                    ssq  += v.x*v.x + v.y*v.y;
                }
                if (outL) {
                    unsigned hh, ll; split2h(v.x, v.y, hh, ll);
                    *(unsigned*)(outH + gi) = hh;
                    *(unsigned*)(outL + gi) = ll;
                } else {
                    *(unsigned*)(outH + gi) = pack2h(v.x, v.y);
                }
            }
        }

    if (mode == 2) {
        __syncthreads();
        float* red = (float*)sb;
#pragma unroll
        for (int off = 16; off; off >>= 1) {
            ssum += __shfl_down_sync(0xffffffffu, ssum, off);
            ssq  += __shfl_down_sync(0xffffffffu, ssq,  off);
        }
        if (lane == 0) { red[wid] = ssum; red[8 + wid] = ssq; }
        __syncthreads();
        if (tid == 0) {
            float ts = 0.f, tq = 0.f;
#pragma unroll
            for (int i = 0; i < 8; ++i) { ts += red[i]; tq += red[8 + i]; }
            partials[win*16 + ob*2] = ts; partials[win*16 + ob*2 + 1] = tq;
        }
    }
}

// ---------------- attention: Q hi/lo x K single; P hi/lo x V single ----------
__global__ __launch_bounds__(256, 2)
void attn_kernel(const __half* __restrict__ Qh, const __half* __restrict__ Ql,
                 const __half* __restrict__ Kh, const __half* __restrict__ Vh,
                 const float* __restrict__ tgt2, float* __restrict__ tgt3,
                 float* __restrict__ out_part) {
    extern __shared__ __half sat[];
    __half* sQh = sat;                 // [128][72]
    __half* sQl = sat + 9216;
    __half* sKh = sat + 18432;
    __shared__ float ared[16];
    int win = blockIdx.x, tid = threadIdx.x, lane = tid & 31, wid = tid >> 5;

    const uint4* gQh = (const uint4*)Qh + (size_t)win * 4096;
    const uint4* gQl = (const uint4*)Ql + (size_t)win * 4096;
    const uint4* gKh = (const uint4*)Kh + (size_t)win * 4096;
    const uint4* gVh = (const uint4*)Vh + (size_t)win * 4096;

    float acc[16][4];
#pragma unroll
    for (int j = 0; j < 16; ++j)
#pragma unroll
        for (int e = 0; e < 4; ++e) acc[j][e] = 0.f;

    int aRow = lane & 15, aCol = (lane >> 4) * 8;
    int kRow = (lane & 7) + ((lane >> 4) & 1) * 8;
    int kCol = ((lane >> 3) & 1) * 8;
    int tRow = ((lane >> 3) & 1) * 8 + (lane & 7);
    int tCol = (lane >> 4) * 8;

    // ---- S = Qv @ Kv^T over 4 chunks of 64 channels ----
    for (int ch = 0; ch < 4; ++ch) {
        __syncthreads();
#pragma unroll
        for (int i = tid; i < 1024; i += 256) {
            int r = i >> 3, c4 = i & 7;
            int gi = r * 32 + ch * 8 + c4;
            int so = r * 72 + c4 * 8;
            *(uint4*)(sQh + so) = gQh[gi];
            *(uint4*)(sQl + so) = gQl[gi];
            *(uint4*)(sKh + so) = gKh[gi];
        }
        __syncthreads();
#pragma unroll
        for (int ks = 0; ks < 4; ++ks) {
            unsigned aHi[4], aLo[4];
            int ro = (wid * 16 + aRow) * 72 + ks * 16 + aCol;
            LDSM_X4(aHi[0], aHi[1], aHi[2], aHi[3], smem_u32(sQh + ro));
            LDSM_X4(aLo[0], aLo[1], aLo[2], aLo[3], smem_u32(sQl + ro));
#pragma unroll
            for (int ng = 0; ng < 8; ++ng) {
                int bo = (ng * 16 + kRow) * 72 + ks * 16 + kCol;
                unsigned bK[4];
                LDSM_X4(bK[0], bK[1], bK[2], bK[3], smem_u32(sKh + bo));
                mma_f16(acc[ng*2],   aHi, bK);
                mma_f16(acc[ng*2+1], aHi, bK + 2);
                mma_f16(acc[ng*2],   aLo, bK);
                mma_f16(acc[ng*2+1], aLo, bK + 2);
            }
        }
    }

    // ---- softmax ----
    float mx0 = -1e30f, mx1 = -1e30f;
#pragma unroll
    for (int j = 0; j < 16; ++j) {
        mx0 = fmaxf(mx0, fmaxf(acc[j][0], acc[j][1]));
        mx1 = fmaxf(mx1, fmaxf(acc[j][2], acc[j][3]));
    }
#pragma unroll
    for (int off = 1; off <= 2; off <<= 1) {
        mx0 = fmaxf(mx0, __shfl_xor_sync(0xffffffffu, mx0, off));
        mx1 = fmaxf(mx1, __shfl_xor_sync(0xffffffffu, mx1, off));
    }
    float s0 = 0.f, s1 = 0.f;
#pragma unroll
    for (int j = 0; j < 16; ++j) {
        acc[j][0] = expf(acc[j][0] - mx0); s0 += acc[j][0];
        acc[j][1] = expf(acc[j][1] - mx0); s0 += acc[j][1];
        acc[j][2] = expf(acc[j][2] - mx1); s1 += acc[j][2];
        acc[j][3] = expf(acc[j][3] - mx1); s1 += acc[j][3];
    }
#pragma unroll
    for (int off = 1; off <= 2; off <<= 1) {
        s0 += __shfl_xor_sync(0xffffffffu, s0, off);
        s1 += __shfl_xor_sync(0xffffffffu, s1, off);
    }
    float i0 = 1.f / s0, i1 = 1.f / s1;
#pragma unroll
    for (int j = 0; j < 16; ++j) {
        acc[j][0] *= i0; acc[j][1] *= i0;
        acc[j][2] *= i1; acc[j][3] *= i1;
    }

    // ---- pack P into fp16 hi/lo a-fragments ----
    unsigned phi[8][4], plo[8][4];
#pragma unroll
    for (int t = 0; t < 8; ++t) {
        split2h(acc[2*t][0],   acc[2*t][1],   phi[t][0], plo[t][0]);
        split2h(acc[2*t][2],   acc[2*t][3],   phi[t][1], plo[t][1]);
        split2h(acc[2*t+1][0], acc[2*t+1][1], phi[t][2], plo[t][2]);
        split2h(acc[2*t+1][2], acc[2*t+1][3], phi[t][3], plo[t][3]);
    }

    // ---- O = P @ Vv over 2 cv chunks ----
    float ssum = 0.f, ssq = 0.f;
    __half* sV = sat;                  // [128][136]
    for (int cv = 0; cv < 2; ++cv) {
        __syncthreads();
#pragma unroll
        for (int i = tid; i < 2048; i += 256) {
            int r = i >> 4, c4 = i & 15;
            int gi = r * 32 + cv * 16 + c4;
            int so = r * 136 + c4 * 8;
            *(uint4*)(sV + so) = gVh[gi];
        }
        __syncthreads();
        float oacc[16][4];
#pragma unroll
        for (int j = 0; j < 16; ++j)
#pragma unroll
            for (int e = 0; e < 4; ++e) oacc[j][e] = 0.f;
#pragma unroll
        for (int mk = 0; mk < 8; ++mk) {
#pragma unroll
            for (int ng = 0; ng < 8; ++ng) {
                int bo = (mk * 16 + tRow) * 136 + ng * 16 + tCol;
                unsigned vV[4];
                LDSM_X4_T(vV[0], vV[1], vV[2], vV[3], smem_u32(sV + bo));
                mma_f16(oacc[ng*2],   phi[mk], vV);
                mma_f16(oacc[ng*2+1], phi[mk], vV + 2);
                mma_f16(oacc[ng*2],   plo[mk], vV);
                mma_f16(oacc[ng*2+1], plo[mk], vV + 2);
            }
        }
#pragma unroll
        for (int j = 0; j < 16; ++j) {
            int col = cv * 128 + j * 8 + (lane & 3) * 2;
            int n0 = wid * 16 + (lane >> 2);
            size_t gi = (size_t)win * WSZ + n0 * 256 + col;
            float2 b0 = *(const float2*)(tgt2 + gi);
            float2 r0 = {b0.x + oacc[j][0], b0.y + oacc[j][1]};
            *(float2*)(tgt3 + gi) = r0;
            size_t gi1 = gi + 8 * 256;
            float2 b1 = *(const float2*)(tgt2 + gi1);
            float2 r1 = {b1.x + oacc[j][2], b1.y + oacc[j][3]};
            *(float2*)(tgt3 + gi1) = r1;
            ssum += r0.x + r0.y + r1.x + r1.y;
            ssq  += r0.x*r0.x + r0.y*r0.y + r1.x*r1.x + r1.y*r1.y;
        }
    }

#pragma unroll
    for (int off = 16; off; off >>= 1) {
        ssum += __shfl_down_sync(0xffffffffu, ssum, off);
        ssq  += __shfl_down_sync(0xffffffffu, ssq,  off);
    }
    if (lane == 0) { ared[wid] = ssum; ared[8 + wid] = ssq; }
    __syncthreads();
    if (tid == 0) {
        float ts = 0.f, tq = 0.f;
#pragma unroll
        for (int i = 0; i < 8; ++i) { ts += ared[i]; tq += ared[8 + i]; }
        out_part[win*16 + 0] = ts; out_part[win*16 + 1] = tq;
    }
}

// ---------------- host orchestration ---------------------------------------
extern "C" void kernel_launch(void* const* d_in, const int* in_sizes, int n_in,
                              void* d_out, int out_size) {
    const float* src  = (const float*)d_in[0];
    const float* qf   = (const float*)d_in[1];
    const float* gn1w = (const float*)d_in[2];
    const float* gn1b = (const float*)d_in[3];
    const float* gn2w = (const float*)d_in[4];
    const float* gn2b = (const float*)d_in[5];
    const float* ls1  = (const float*)d_in[6];
    const float* ls2  = (const float*)d_in[7];
    const float* ls3  = (const float*)d_in[8];
    const float* qw   = (const float*)d_in[9];
    const float* qb   = (const float*)d_in[10];
    const float* kw   = (const float*)d_in[11];
    const float* kb   = (const float*)d_in[12];
    const float* vw   = (const float*)d_in[13];
    const float* vb   = (const float*)d_in[14];
    const float* fc1w = (const float*)d_in[15];
    const float* fc1b = (const float*)d_in[16];
    const float* fc2w = (const float*)d_in[17];
    const float* fc2b = (const float*)d_in[18];
    const float* gnfw = (const float*)d_in[19];
    const float* gnfb = (const float*)d_in[20];
    float* out = (float*)d_out;

    float *tgt, *tgt2, *tgt3, *fin, *p1, *p2, *p3;
    __half *memh, *tgth, *qh, *ql, *kh, *vh, *hh, *wh, *wl;
    cudaGetSymbolAddress((void**)&tgt,  g_tgt);
    cudaGetSymbolAddress((void**)&tgt2, g_tgt2);
    cudaGetSymbolAddress((void**)&tgt3, g_tgt3);
    cudaGetSymbolAddress((void**)&fin,  g_fin);
    cudaGetSymbolAddress((void**)&p1,   g_p1);
    cudaGetSymbolAddress((void**)&p2,   g_p2);
    cudaGetSymbolAddress((void**)&p3,   g_p3);
    cudaGetSymbolAddress((void**)&memh, g_memh);
    cudaGetSymbolAddress((void**)&tgth, g_tgth);
    cudaGetSymbolAddress((void**)&qh,   g_qh);
    cudaGetSymbolAddress((void**)&ql,   g_ql);
    cudaGetSymbolAddress((void**)&kh,   g_kh);
    cudaGetSymbolAddress((void**)&vh,   g_vh);
    cudaGetSymbolAddress((void**)&hh,   g_hh);
    cudaGetSymbolAddress((void**)&wh,   g_wh);
    cudaGetSymbolAddress((void**)&wl,   g_wl);

    const int SM_ATTN = 55296;   // 3 x [128][72] fp16
    const int SM_TC   = 54272;   // 2 x [128][72] + [64][136] fp16
    cudaFuncSetAttribute(attn_kernel,    cudaFuncAttributeMaxDynamicSharedMemorySize, SM_ATTN);
    cudaFuncSetAttribute(gemm_tc_kernel, cudaFuncAttributeMaxDynamicSharedMemorySize, SM_TC);

    partition_kernel<<<65536, 256>>>(src, qf, memh, tgth, tgt);
    conv_w_all<<<448, 256>>>(qw, kw, vw, fc1w, fc2w, wh, wl);
    gn_stats<<<NW, 256>>>(tgt, p1);

    for (int l = 0; l < 2; ++l) {
        int lC = l * CDIM;
        size_t lb = (size_t)l * 458752;
        // tgt2 = tgt + ls1 * mix(gn1(tgt))
        gn_mix_apply<<<dim3(NW,8), 256>>>(tgt, tgt, p1, 2, gn1w + lC, gn1b + lC, ls1 + lC, tgt2, nullptr);
        // merged Q/K/V: Q <- tgth (hi/lo out), K/V <- memh (single out)
        gemm_tc_kernel<<<dim3(NW,6), 256, SM_TC>>>(wh + lb, wl + lb,
            tgth, memh, nullptr, nullptr, nullptr, nullptr,
            qb + lC, kb + lC, vb + lC,
            nullptr, qh, ql, kh, vh, 256, 0, nullptr, nullptr, nullptr);
        // tgt3 = tgt2 + attention  (+stats -> p2)
        attn_kernel<<<NW, 256, SM_ATTN>>>(qh, ql, kh, vh, tgt2, tgt3, p2);
        // tgt3 = tgt2 + ls2*mix(gn1(tgt3))  (stats p2, partials -> p3)
        gn_mix_apply<<<dim3(NW,8), 256>>>(tgt3, tgt2, p2, 1, gn1w + lC, gn1b + lC, ls2 + lC, tgt3, p3);
        // h = gelu(fc1(gn2(tgt3)))  (gn2 fused; stats p3) -> hh single
        gemm_tc_kernel<<<dim3(NW,4), 256, SM_TC>>>(wh + lb + 196608, wl + lb + 196608,
            nullptr, nullptr, tgt3, gn2w + lC, gn2b + lC, p3,
            fc1b + (size_t)l*512, nullptr, nullptr,
            nullptr, hh, nullptr, nullptr, nullptr, 256, 1, nullptr, nullptr, nullptr);
        // tgt = tgt3 + ls3*fc2(h)  (+stats -> p1; fp32 + single fp16 out)
        gemm_tc_kernel<<<dim3(NW,2), 256, SM_TC>>>(wh + lb + 327680, wl + lb + 327680,
            hh, nullptr, nullptr, nullptr, nullptr, nullptr,
            fc2b + lC, nullptr, nullptr,
            tgt, tgth, nullptr, nullptr, nullptr, 512, 2, tgt3, ls3 + lC, p1);
    }

    gn_elem_apply<<<dim3(NW,8), 256>>>(tgt, p1, 2, gnfw, gnfb, fin);
    scatter_kernel<<<65536, 256>>>(fin, out);
}

// round 10
// speedup vs baseline: 5.2936x; 1.2998x over previous
#include <cuda_runtime.h>
#include <cuda_fp16.h>
#include <math.h>
#include <stdint.h>

#define NW   512
#define CDIM 256
#define PDIM 128
#define WSZ  (CDIM*PDIM)

// ---------------- scratch (static device globals; no allocations) ----------
__device__ float g_tgt [NW*WSZ];
__device__ float g_tgt2[NW*WSZ];
__device__ float g_tgt3[NW*WSZ];
__device__ float g_fin [NW*WSZ];
__device__ __half g_memh[NW*WSZ];
__device__ __half g_tgth[NW*WSZ];
__device__ __half g_qh [NW*WSZ];
__device__ __half g_kh [NW*WSZ];
__device__ __half g_vh [NW*WSZ];
__device__ __half g_hh [NW*2*WSZ];
__device__ __half g_wh[2*458752];
__device__ float g_p1[NW*16];
__device__ float g_p2[NW*16];
__device__ float g_p3[NW*16];

// ================= helpers =================================================
__device__ __forceinline__ uint32_t smem_u32(const void* p) {
    uint32_t a;
    asm("{ .reg .u64 t; cvta.to.shared.u64 t, %1; cvt.u32.u64 %0, t; }" : "=r"(a) : "l"(p));
    return a;
}
#define LDSM_X4(r0,r1,r2,r3,addr) \
    asm volatile("ldmatrix.sync.aligned.m8n8.x4.shared.b16 {%0,%1,%2,%3}, [%4];" \
        : "=r"(r0),"=r"(r1),"=r"(r2),"=r"(r3) : "r"(addr))
#define LDSM_X4_T(r0,r1,r2,r3,addr) \
    asm volatile("ldmatrix.sync.aligned.m8n8.x4.trans.shared.b16 {%0,%1,%2,%3}, [%4];" \
        : "=r"(r0),"=r"(r1),"=r"(r2),"=r"(r3) : "r"(addr))
__device__ __forceinline__ void mma_f16(float* d, const unsigned* a, const unsigned* b) {
    asm volatile("mma.sync.aligned.m16n8k16.row.col.f32.f16.f16.f32 "
        "{%0,%1,%2,%3}, {%4,%5,%6,%7}, {%8,%9}, {%0,%1,%2,%3};"
        : "+f"(d[0]),"+f"(d[1]),"+f"(d[2]),"+f"(d[3])
        : "r"(a[0]),"r"(a[1]),"r"(a[2]),"r"(a[3]), "r"(b[0]),"r"(b[1]));
}
__device__ __forceinline__ unsigned pack2h(float a, float b) {
    __half ah = __float2half_rn(a), bh = __float2half_rn(b);
    return (unsigned)__half_as_ushort(ah) | ((unsigned)__half_as_ushort(bh) << 16);
}
__device__ __forceinline__ void read_stats(const float* part, int win, int nparts,
                                           float& mean, float& rstd) {
    float S = 0.f, Q = 0.f;
    for (int i = 0; i < nparts; ++i) { S += part[win*16 + i*2]; Q += part[win*16 + i*2 + 1]; }
    mean = S * (1.f / 32768.f);
    float var = Q * (1.f / 32768.f) - mean * mean;
    rstd = rsqrtf(var + 1e-5f);
}

// ---------------- partition (merged src + qf) -------------------------------
__global__ void partition_kernel(const float* __restrict__ src, const float* __restrict__ qf,
                                 __half* __restrict__ memh, __half* __restrict__ tgth,
                                 float* __restrict__ tgt) {
    int gb = blockIdx.x;
    bool isq = gb >= 32768;
    int g = (isq ? gb - 32768 : gb) * 256 + threadIdx.x;
    int idx = g * 2;
    int p = idx & 127, c = (idx >> 7) & 255, bw = idx >> 15;
    int b = bw >> 7, wblk = bw & 127;
    int h = (wblk >> 3) * 8 + (p >> 4), w = (wblk & 7) * 16 + (p & 15);
    const float* s = (isq ? qf : src) + (((size_t)b * 256 + c) * 128 + h) * 128 + w;
    float a0 = s[0], a1 = s[1];
    unsigned u = pack2h(a0, a1);
    if (isq) {
        *(unsigned*)(tgth + idx) = u;
        *(float2*)(tgt + idx) = make_float2(a0, a1);
    } else {
        *(unsigned*)(memh + idx) = u;
    }
}

__global__ void scatter_kernel(const float* __restrict__ fin, float* __restrict__ out) {
    int idx = blockIdx.x * 256 + threadIdx.x;
    int c = idx & 255, b = (idx >> 8) & 3, n = idx >> 10;
    int h = n >> 7, w = n & 127;
    int win = b * 128 + (h >> 3) * 8 + (w >> 4);
    int p = (h & 7) * 16 + (w & 15);
    out[idx] = fin[(size_t)win * WSZ + c * 128 + p];
}

// ---------------- all weights fp32 -> single fp16 (one launch) --------------
__global__ void conv_w_all(const float* __restrict__ qw, const float* __restrict__ kw,
                           const float* __restrict__ vw, const float* __restrict__ fc1w,
                           const float* __restrict__ fc2w, __half* __restrict__ hi) {
    int g = blockIdx.x * 256 + threadIdx.x;
    int l = g / 57344, r = g - l * 57344;
    const float* srcp;
    size_t oo;
    if (r < 8192)        { srcp = qw  + (size_t)l*65536  + (size_t)r*8;          oo = (size_t)l*458752 + (size_t)r*8; }
    else if (r < 16384)  { srcp = kw  + (size_t)l*65536  + (size_t)(r-8192)*8;   oo = (size_t)l*458752 + 65536  + (size_t)(r-8192)*8; }
    else if (r < 24576)  { srcp = vw  + (size_t)l*65536  + (size_t)(r-16384)*8;  oo = (size_t)l*458752 + 131072 + (size_t)(r-16384)*8; }
    else if (r < 40960)  { srcp = fc1w+ (size_t)l*131072 + (size_t)(r-24576)*8;  oo = (size_t)l*458752 + 196608 + (size_t)(r-24576)*8; }
    else                 { srcp = fc2w+ (size_t)l*131072 + (size_t)(r-40960)*8;  oo = (size_t)l*458752 + 327680 + (size_t)(r-40960)*8; }
    unsigned hh[4];
#pragma unroll
    for (int j = 0; j < 4; ++j) hh[j] = pack2h(srcp[2*j], srcp[2*j+1]);
    uint4 vh = {hh[0], hh[1], hh[2], hh[3]};
    *(uint4*)(hi + oo) = vh;
}

// ---------------- GN stats ---------------------------------------------------
__global__ __launch_bounds__(256)
void gn_stats(const float* __restrict__ in, float* __restrict__ part) {
    __shared__ float red[16];
    int win = blockIdx.x, tid = threadIdx.x, lane = tid & 31, wid = tid >> 5;
    const float4* x = (const float4*)(in + (size_t)win * WSZ);
    float s = 0.f, q = 0.f;
#pragma unroll
    for (int k = 0; k < 32; ++k) {
        float4 v = x[tid + k * 256];
        s += v.x + v.y + v.z + v.w;
        q += v.x*v.x + v.y*v.y + v.z*v.z + v.w*v.w;
    }
#pragma unroll
    for (int off = 16; off; off >>= 1) {
        s += __shfl_down_sync(0xffffffffu, s, off);
        q += __shfl_down_sync(0xffffffffu, q, off);
    }
    if (lane == 0) { red[wid] = s; red[8 + wid] = q; }
    __syncthreads();
    if (tid == 0) {
        float ts = 0.f, tq = 0.f;
#pragma unroll
        for (int i = 0; i < 8; ++i) { ts += red[i]; tq += red[8 + i]; }
        part[win*16 + 0] = ts; part[win*16 + 1] = tq;
        part[win*16 + 2] = 0.f; part[win*16 + 3] = 0.f;
    }
}

// ---------------- GN apply + separable poolformer mix + residual -------------
__global__ __launch_bounds__(256)
void gn_mix_apply(const float* __restrict__ in, const float* __restrict__ basep,
                  const float* __restrict__ part, int nparts,
                  const float* __restrict__ gw, const float* __restrict__ gb,
                  const float* __restrict__ ls, float* __restrict__ outf,
                  float* __restrict__ out_part) {
    __shared__ float sm[32 * 132];
    __shared__ float hsb[32 * 132];
    __shared__ float red[16];
    int win = blockIdx.x, yb = blockIdx.y, tid = threadIdx.x, lane = tid & 31, wid = tid >> 5;
    float mean, rstd;
    read_stats(part, win, nparts, mean, rstd);

    const float4* src = (const float4*)(in + (size_t)win * WSZ + yb * 4096);
#pragma unroll
    for (int k = 0; k < 4; ++k) {
        int idx = tid + k * 256;
        int cl = idx >> 5, p4 = idx & 31;
        int c = yb * 32 + cl;
        float w = gw[c], bb = gb[c];
        float4 v = src[idx];
        v.x = (v.x - mean) * rstd * w + bb;
        v.y = (v.y - mean) * rstd * w + bb;
        v.z = (v.z - mean) * rstd * w + bb;
        v.w = (v.w - mean) * rstd * w + bb;
        *(float4*)(sm + cl * 132 + p4 * 4) = v;
    }
    __syncthreads();

    int p0 = lane * 4;
    int y = p0 >> 4, x0 = p0 & 15;
    float vcnt = 3.f - (y == 0 ? 1.f : 0.f) - (y == 7 ? 1.f : 0.f);
    float rinv[4];
#pragma unroll
    for (int j = 0; j < 4; ++j) {
        int x = x0 + j;
        float hc = 3.f - (x == 0 ? 1.f : 0.f) - (x == 15 ? 1.f : 0.f);
        rinv[j] = 1.f / (hc * vcnt);
    }
    bool le = (x0 == 0), re = (x0 == 12);

#pragma unroll
    for (int ci = 0; ci < 4; ++ci) {
        int cl = wid * 4 + ci;
        const float* ch = sm + cl * 132;
        float4 v = *(const float4*)(ch + p0);
        float L = le ? 0.f : ch[p0 - 1];
        float R = re ? 0.f : ch[p0 + 4];
        float4 h;
        h.x = L + v.x + v.y;
        h.y = v.x + v.y + v.z;
        h.z = v.y + v.z + v.w;
        h.w = v.z + v.w + R;
        *(float4*)(hsb + cl * 132 + p0) = h;
    }
    __syncwarp();

    float s2 = 0.f, q2 = 0.f;
#pragma unroll
    for (int ci = 0; ci < 4; ++ci) {
        int cl = wid * 4 + ci;
        int c = yb * 32 + cl;
        const float* ch = sm + cl * 132;
        const float* hs = hsb + cl * 132;
        float4 mid = *(const float4*)(hs + p0);
        float4 up = (y > 0) ? *(const float4*)(hs + p0 - 16) : make_float4(0,0,0,0);
        float4 dn = (y < 7) ? *(const float4*)(hs + p0 + 16) : make_float4(0,0,0,0);
        float4 v = *(const float4*)(ch + p0);
        float o0 = (up.x + mid.x + dn.x) * rinv[0] - v.x;
        float o1 = (up.y + mid.y + dn.y) * rinv[1] - v.y;
        float o2 = (up.z + mid.z + dn.z) * rinv[2] - v.z;
        float o3 = (up.w + mid.w + dn.w) * rinv[3] - v.w;
        size_t gi = (size_t)win * WSZ + c * 128 + p0;
        float4 bv = *(const float4*)(basep + gi);
        float lsv = ls[c];
        float4 ov = {bv.x + lsv * o0, bv.y + lsv * o1,
                     bv.z + lsv * o2, bv.w + lsv * o3};
        *(float4*)(outf + gi) = ov;
        if (out_part) {
            s2 += ov.x + ov.y + ov.z + ov.w;
            q2 += ov.x*ov.x + ov.y*ov.y + ov.z*ov.z + ov.w*ov.w;
        }
    }
    if (out_part) {
#pragma unroll
        for (int off = 16; off; off >>= 1) {
            s2 += __shfl_down_sync(0xffffffffu, s2, off);
            q2 += __shfl_down_sync(0xffffffffu, q2, off);
        }
        if (lane == 0) { red[wid] = s2; red[8 + wid] = q2; }
        __syncthreads();
        if (tid == 0) {
            float ts = 0.f, tq = 0.f;
#pragma unroll
            for (int i = 0; i < 8; ++i) { ts += red[i]; tq += red[8 + i]; }
            out_part[win*16 + yb*2] = ts; out_part[win*16 + yb*2 + 1] = tq;
        }
    }
}

// ---------------- elementwise GN apply (final) -------------------------------
__global__ __launch_bounds__(256)
void gn_elem_apply(const float* __restrict__ in, const float* __restrict__ part, int nparts,
                   const float* __restrict__ gw, const float* __restrict__ gb,
                   float* __restrict__ outf) {
    int win = blockIdx.x, yb = blockIdx.y, tid = threadIdx.x;
    float mean, rstd;
    read_stats(part, win, nparts, mean, rstd);
    size_t b0 = (size_t)win * WSZ + yb * 4096;
    const float4* src = (const float4*)(in + b0);
#pragma unroll
    for (int k = 0; k < 4; ++k) {
        int idx = tid + k * 256;
        int c = yb * 32 + (idx >> 5);
        float w = gw[c], bb = gb[c];
        float4 v = src[idx];
        v.x = (v.x - mean) * rstd * w + bb;
        v.y = (v.y - mean) * rstd * w + bb;
        v.z = (v.z - mean) * rstd * w + bb;
        v.w = (v.w - mean) * rstd * w + bb;
        *(float4*)(outf + b0 + idx * 4) = v;
    }
}

// ---------------- tensor-core GEMM (single fp16) -----------------------------
// mode 0: merged QKV  mode 1: fc1 with fused gn2 staging  mode 2: fc2 residual
__global__ __launch_bounds__(256, 2)
void gemm_tc_kernel(const __half* __restrict__ Wh,
                    const __half* __restrict__ Xa, const __half* __restrict__ Xb,
                    const float* __restrict__ Xf, const float* __restrict__ g2w,
                    const float* __restrict__ g2b, const float* __restrict__ statsp,
                    const float* __restrict__ b0p, const float* __restrict__ b1p,
                    const float* __restrict__ b2p,
                    float* __restrict__ Yf,
                    __half* __restrict__ Yq, __half* __restrict__ Yk, __half* __restrict__ Yv,
                    int CIN, int mode,
                    const float* __restrict__ base, const float* __restrict__ ls,
                    float* __restrict__ partials) {
    extern __shared__ __half sb[];
    __half* sW = sb;                  // [128][72]
    __half* sX = sb + 9216;           // [64][136]
    int win = blockIdx.x, ob = blockIdx.y;
    int tid = threadIdx.x, lane = tid & 31, wid = tid >> 5;
    int wr = wid >> 1, wc = wid & 1;

    const __half* gW = Wh + (size_t)ob * 128 * CIN;
    const __half* X = nullptr;
    __half* outH = nullptr;
    const float* bias;
    int O, O0;
    float gmean = 0.f, grstd = 0.f;
    if (mode == 0) {
        int mat = ob >> 1;
        X = (mat == 0) ? Xa : Xb;
        bias = (mat == 0) ? b0p : (mat == 1 ? b1p : b2p);
        outH = (mat == 0) ? Yq : (mat == 1 ? Yk : Yv);
        O = 256; O0 = (ob & 1) * 128;
    } else if (mode == 1) {
        bias = b0p;
        O = 512; O0 = ob * 128;
        outH = Yq;
        read_stats(statsp, win, 8, gmean, grstd);
    } else {
        X = Xa; bias = b0p;
        O = 256; O0 = ob * 128;
        outH = Yq;
    }
    const uint4* gX4 = (mode != 1) ? (const uint4*)X + (size_t)win * CIN * 16 : nullptr;
    const float* gXf = (mode == 1) ? Xf + (size_t)win * WSZ : nullptr;

    float acc[2][8][4];
#pragma unroll
    for (int mt = 0; mt < 2; ++mt)
#pragma unroll
        for (int nt = 0; nt < 8; ++nt)
#pragma unroll
            for (int e = 0; e < 4; ++e) acc[mt][nt][e] = 0.f;

    int aRow = (lane & 15), aCol = (lane >> 4) * 8;
    int brbase = ((lane >> 3) & 1) * 8 + (lane & 7);
    int bcofs  = (lane >> 4) * 8;

    for (int kc = 0; kc < CIN; kc += 64) {
        __syncthreads();
#pragma unroll
        for (int i = tid; i < 1024; i += 256) {      // W tile
            int r = i >> 3, c4 = i & 7;
            size_t go = (size_t)r * CIN + kc + c4 * 8;
            *(uint4*)(sW + r * 72 + c4 * 8) = *(const uint4*)(gW + go);
        }
        if (mode == 1) {
#pragma unroll
            for (int i = tid; i < 2048; i += 256) {
                int r = i >> 5, p4 = i & 31;
                int c = kc + r;
                float4 v = *(const float4*)(gXf + (size_t)c * 128 + p4 * 4);
                float w = g2w[c], bb = g2b[c];
                v.x = (v.x - gmean) * grstd * w + bb;
                v.y = (v.y - gmean) * grstd * w + bb;
                v.z = (v.z - gmean) * grstd * w + bb;
                v.w = (v.w - gmean) * grstd * w + bb;
                uint2 u = {pack2h(v.x, v.y), pack2h(v.z, v.w)};
                *(uint2*)(sX + r * 136 + p4 * 4) = u;
            }
        } else {
#pragma unroll
            for (int i = tid; i < 1024; i += 256) {
                int r = i >> 4, c4 = i & 15;
                *(uint4*)(sX + r * 136 + c4 * 8) = gX4[(kc + r) * 16 + c4];
            }
        }
        __syncthreads();
#pragma unroll
        for (int ks = 0; ks < 4; ++ks) {
            unsigned aW[2][4];
#pragma unroll
            for (int mt = 0; mt < 2; ++mt) {
                int ro = (wr * 32 + mt * 16 + aRow) * 72 + ks * 16 + aCol;
                LDSM_X4(aW[mt][0], aW[mt][1], aW[mt][2], aW[mt][3], smem_u32(sW + ro));
            }
#pragma unroll
            for (int np = 0; np < 4; ++np) {
                int bo = (ks * 16 + brbase) * 136 + wc * 64 + np * 16 + bcofs;
                unsigned bX[4];
                LDSM_X4_T(bX[0], bX[1], bX[2], bX[3], smem_u32(sX + bo));
#pragma unroll
                for (int mt = 0; mt < 2; ++mt) {
                    mma_f16(acc[mt][np*2],   aW[mt], bX);
                    mma_f16(acc[mt][np*2+1], aW[mt], bX + 2);
                }
            }
        }
    }

    float ssum = 0.f, ssq = 0.f;
#pragma unroll
    for (int mt = 0; mt < 2; ++mt)
#pragma unroll
        for (int nt = 0; nt < 8; ++nt) {
            int p = wc * 64 + nt * 8 + (lane & 3) * 2;
#pragma unroll
            for (int half = 0; half < 2; ++half) {
                int o = O0 + wr * 32 + mt * 16 + (lane >> 2) + half * 8;
                float bv = bias[o];
                float2 v;
                v.x = acc[mt][nt][half * 2]     + bv;
                v.y = acc[mt][nt][half * 2 + 1] + bv;
                size_t gi = ((size_t)win * O + o) * 128 + p;
                if (mode == 1) {
                    v.x = 0.5f * v.x * (1.f + erff(v.x * 0.70710678118654752f));
                    v.y = 0.5f * v.y * (1.f + erff(v.y * 0.70710678118654752f));
                } else if (mode == 2) {
                    float lsv = ls[o];
                    float2 b2 = *(const float2*)(base + gi);
                    v.x = b2.x + lsv * v.x;
                    v.y = b2.y + lsv * v.y;
                    *(float2*)(Yf + gi) = v;
                    ssum += v.x + v.y;
                    ssq  += v.x*v.x + v.y*v.y;
                }
                *(unsigned*)(outH + gi) = pack2h(v.x, v.y);
            }
        }

    if (mode == 2) {
        __syncthreads();
        float* red = (float*)sb;
#pragma unroll
        for (int off = 16; off; off >>= 1) {
            ssum += __shfl_down_sync(0xffffffffu, ssum, off);
            ssq  += __shfl_down_sync(0xffffffffu, ssq,  off);
        }
        if (lane == 0) { red[wid] = ssum; red[8 + wid] = ssq; }
        __syncthreads();
        if (tid == 0) {
            float ts = 0.f, tq = 0.f;
#pragma unroll
            for (int i = 0; i < 8; ++i) { ts += red[i]; tq += red[8 + i]; }
            partials[win*16 + ob*2] = ts; partials[win*16 + ob*2 + 1] = tq;
        }
    }
}

// ---------------- attention (single fp16 throughout) -------------------------
__global__ __launch_bounds__(256, 2)
void attn_kernel(const __half* __restrict__ Qh, const __half* __restrict__ Kh,
                 const __half* __restrict__ Vh,
                 const float* __restrict__ tgt2, float* __restrict__ tgt3,
                 float* __restrict__ out_part) {
    extern __shared__ __half sat[];
    __half* sQ = sat;                  // [128][72]
    __half* sK = sat + 9216;
    __shared__ float ared[16];
    int win = blockIdx.x, tid = threadIdx.x, lane = tid & 31, wid = tid >> 5;

    const uint4* gQ = (const uint4*)Qh + (size_t)win * 4096;
    const uint4* gK = (const uint4*)Kh + (size_t)win * 4096;
    const uint4* gV = (const uint4*)Vh + (size_t)win * 4096;

    float acc[16][4];
#pragma unroll
    for (int j = 0; j < 16; ++j)
#pragma unroll
        for (int e = 0; e < 4; ++e) acc[j][e] = 0.f;

    int aRow = lane & 15, aCol = (lane >> 4) * 8;
    int kRow = (lane & 7) + ((lane >> 4) & 1) * 8;
    int kCol = ((lane >> 3) & 1) * 8;
    int tRow = ((lane >> 3) & 1) * 8 + (lane & 7);
    int tCol = (lane >> 4) * 8;

    // ---- S = Qv @ Kv^T over 4 chunks of 64 channels ----
    for (int ch = 0; ch < 4; ++ch) {
        __syncthreads();
#pragma unroll
        for (int i = tid; i < 1024; i += 256) {
            int r = i >> 3, c4 = i & 7;
            int gi = r * 32 + ch * 8 + c4;
            int so = r * 72 + c4 * 8;
            *(uint4*)(sQ + so) = gQ[gi];
            *(uint4*)(sK + so) = gK[gi];
        }
        __syncthreads();
#pragma unroll
        for (int ks = 0; ks < 4; ++ks) {
            unsigned aQ[4];
            int ro = (wid * 16 + aRow) * 72 + ks * 16 + aCol;
            LDSM_X4(aQ[0], aQ[1], aQ[2], aQ[3], smem_u32(sQ + ro));
#pragma unroll
            for (int ng = 0; ng < 8; ++ng) {
                int bo = (ng * 16 + kRow) * 72 + ks * 16 + kCol;
                unsigned bK[4];
                LDSM_X4(bK[0], bK[1], bK[2], bK[3], smem_u32(sK + bo));
                mma_f16(acc[ng*2],   aQ, bK);
                mma_f16(acc[ng*2+1], aQ, bK + 2);
            }
        }
    }

    // ---- softmax ----
    float mx0 = -1e30f, mx1 = -1e30f;
#pragma unroll
    for (int j = 0; j < 16; ++j) {
        mx0 = fmaxf(mx0, fmaxf(acc[j][0], acc[j][1]));
        mx1 = fmaxf(mx1, fmaxf(acc[j][2], acc[j][3]));
    }
#pragma unroll
    for (int off = 1; off <= 2; off <<= 1) {
        mx0 = fmaxf(mx0, __shfl_xor_sync(0xffffffffu, mx0, off));
        mx1 = fmaxf(mx1, __shfl_xor_sync(0xffffffffu, mx1, off));
    }
    float s0 = 0.f, s1 = 0.f;
#pragma unroll
    for (int j = 0; j < 16; ++j) {
        acc[j][0] = expf(acc[j][0] - mx0); s0 += acc[j][0];
        acc[j][1] = expf(acc[j][1] - mx0); s0 += acc[j][1];
        acc[j][2] = expf(acc[j][2] - mx1); s1 += acc[j][2];
        acc[j][3] = expf(acc[j][3] - mx1); s1 += acc[j][3];
    }
#pragma unroll
    for (int off = 1; off <= 2; off <<= 1) {
        s0 += __shfl_xor_sync(0xffffffffu, s0, off);
        s1 += __shfl_xor_sync(0xffffffffu, s1, off);
    }
    float i0 = 1.f / s0, i1 = 1.f / s1;
#pragma unroll
    for (int j = 0; j < 16; ++j) {
        acc[j][0] *= i0; acc[j][1] *= i0;
        acc[j][2] *= i1; acc[j][3] *= i1;
    }

    // ---- pack P into fp16 a-fragments ----
    unsigned pfr[8][4];
#pragma unroll
    for (int t = 0; t < 8; ++t) {
        pfr[t][0] = pack2h(acc[2*t][0],   acc[2*t][1]);
        pfr[t][1] = pack2h(acc[2*t][2],   acc[2*t][3]);
        pfr[t][2] = pack2h(acc[2*t+1][0], acc[2*t+1][1]);
        pfr[t][3] = pack2h(acc[2*t+1][2], acc[2*t+1][3]);
    }

    // ---- O = P @ Vv over 2 cv chunks ----
    float ssum = 0.f, ssq = 0.f;
    __half* sV = sat;                  // [128][136]
    for (int cv = 0; cv < 2; ++cv) {
        __syncthreads();
#pragma unroll
        for (int i = tid; i < 2048; i += 256) {
            int r = i >> 4, c4 = i & 15;
            *(uint4*)(sV + r * 136 + c4 * 8) = gV[r * 32 + cv * 16 + c4];
        }
        __syncthreads();
        float oacc[16][4];
#pragma unroll
        for (int j = 0; j < 16; ++j)
#pragma unroll
            for (int e = 0; e < 4; ++e) oacc[j][e] = 0.f;
#pragma unroll
        for (int mk = 0; mk < 8; ++mk) {
#pragma unroll
            for (int ng = 0; ng < 8; ++ng) {
                int bo = (mk * 16 + tRow) * 136 + ng * 16 + tCol;
                unsigned vV[4];
                LDSM_X4_T(vV[0], vV[1], vV[2], vV[3], smem_u32(sV + bo));
                mma_f16(oacc[ng*2],   pfr[mk], vV);
                mma_f16(oacc[ng*2+1], pfr[mk], vV + 2);
            }
        }
#pragma unroll
        for (int j = 0; j < 16; ++j) {
            int col = cv * 128 + j * 8 + (lane & 3) * 2;
            int n0 = wid * 16 + (lane >> 2);
            size_t gi = (size_t)win * WSZ + n0 * 256 + col;
            float2 b0 = *(const float2*)(tgt2 + gi);
            float2 r0 = {b0.x + oacc[j][0], b0.y + oacc[j][1]};
            *(float2*)(tgt3 + gi) = r0;
            size_t gi1 = gi + 8 * 256;
            float2 b1 = *(const float2*)(tgt2 + gi1);
            float2 r1 = {b1.x + oacc[j][2], b1.y + oacc[j][3]};
            *(float2*)(tgt3 + gi1) = r1;
            ssum += r0.x + r0.y + r1.x + r1.y;
            ssq  += r0.x*r0.x + r0.y*r0.y + r1.x*r1.x + r1.y*r1.y;
        }
    }

#pragma unroll
    for (int off = 16; off; off >>= 1) {
        ssum += __shfl_down_sync(0xffffffffu, ssum, off);
        ssq  += __shfl_down_sync(0xffffffffu, ssq,  off);
    }
    if (lane == 0) { ared[wid] = ssum; ared[8 + wid] = ssq; }
    __syncthreads();
    if (tid == 0) {
        float ts = 0.f, tq = 0.f;
#pragma unroll
        for (int i = 0; i < 8; ++i) { ts += ared[i]; tq += ared[8 + i]; }
        out_part[win*16 + 0] = ts; out_part[win*16 + 1] = tq;
    }
}

// ---------------- host orchestration ---------------------------------------
extern "C" void kernel_launch(void* const* d_in, const int* in_sizes, int n_in,
                              void* d_out, int out_size) {
    const float* src  = (const float*)d_in[0];
    const float* qf   = (const float*)d_in[1];
    const float* gn1w = (const float*)d_in[2];
    const float* gn1b = (const float*)d_in[3];
    const float* gn2w = (const float*)d_in[4];
    const float* gn2b = (const float*)d_in[5];
    const float* ls1  = (const float*)d_in[6];
    const float* ls2  = (const float*)d_in[7];
    const float* ls3  = (const float*)d_in[8];
    const float* qw   = (const float*)d_in[9];
    const float* qb   = (const float*)d_in[10];
    const float* kw   = (const float*)d_in[11];
    const float* kb   = (const float*)d_in[12];
    const float* vw   = (const float*)d_in[13];
    const float* vb   = (const float*)d_in[14];
    const float* fc1w = (const float*)d_in[15];
    const float* fc1b = (const float*)d_in[16];
    const float* fc2w = (const float*)d_in[17];
    const float* fc2b = (const float*)d_in[18];
    const float* gnfw = (const float*)d_in[19];
    const float* gnfb = (const float*)d_in[20];
    float* out = (float*)d_out;

    float *tgt, *tgt2, *tgt3, *fin, *p1, *p2, *p3;
    __half *memh, *tgth, *qh, *kh, *vh, *hh, *wh;
    cudaGetSymbolAddress((void**)&tgt,  g_tgt);
    cudaGetSymbolAddress((void**)&tgt2, g_tgt2);
    cudaGetSymbolAddress((void**)&tgt3, g_tgt3);
    cudaGetSymbolAddress((void**)&fin,  g_fin);
    cudaGetSymbolAddress((void**)&p1,   g_p1);
    cudaGetSymbolAddress((void**)&p2,   g_p2);
    cudaGetSymbolAddress((void**)&p3,   g_p3);
    cudaGetSymbolAddress((void**)&memh, g_memh);
    cudaGetSymbolAddress((void**)&tgth, g_tgth);
    cudaGetSymbolAddress((void**)&qh,   g_qh);
    cudaGetSymbolAddress((void**)&kh,   g_kh);
    cudaGetSymbolAddress((void**)&vh,   g_vh);
    cudaGetSymbolAddress((void**)&hh,   g_hh);
    cudaGetSymbolAddress((void**)&wh,   g_wh);

    const int SM_ATTN = 36864;   // max(2x[128][72], [128][136]) fp16
    const int SM_TC   = 35840;   // [128][72] + [64][136] fp16
    cudaFuncSetAttribute(attn_kernel,    cudaFuncAttributeMaxDynamicSharedMemorySize, SM_ATTN);
    cudaFuncSetAttribute(gemm_tc_kernel, cudaFuncAttributeMaxDynamicSharedMemorySize, SM_TC);

    partition_kernel<<<65536, 256>>>(src, qf, memh, tgth, tgt);
    conv_w_all<<<448, 256>>>(qw, kw, vw, fc1w, fc2w, wh);
    gn_stats<<<NW, 256>>>(tgt, p1);

    for (int l = 0; l < 2; ++l) {
        int lC = l * CDIM;
        size_t lb = (size_t)l * 458752;
        gn_mix_apply<<<dim3(NW,8), 256>>>(tgt, tgt, p1, 2, gn1w + lC, gn1b + lC, ls1 + lC, tgt2, nullptr);
        gemm_tc_kernel<<<dim3(NW,6), 256, SM_TC>>>(wh + lb,
            tgth, memh, nullptr, nullptr, nullptr, nullptr,
            qb + lC, kb + lC, vb + lC,
            nullptr, qh, kh, vh, 256, 0, nullptr, nullptr, nullptr);
        attn_kernel<<<NW, 256, SM_ATTN>>>(qh, kh, vh, tgt2, tgt3, p2);
        gn_mix_apply<<<dim3(NW,8), 256>>>(tgt3, tgt2, p2, 1, gn1w + lC, gn1b + lC, ls2 + lC, tgt3, p3);
        gemm_tc_kernel<<<dim3(NW,4), 256, SM_TC>>>(wh + lb + 196608,
            nullptr, nullptr, tgt3, gn2w + lC, gn2b + lC, p3,
            fc1b + (size_t)l*512, nullptr, nullptr,
            nullptr, hh, nullptr, nullptr, 256, 1, nullptr, nullptr, nullptr);
        gemm_tc_kernel<<<dim3(NW,2), 256, SM_TC>>>(wh + lb + 327680,
            hh, nullptr, nullptr, nullptr, nullptr, nullptr,
            fc2b + lC, nullptr, nullptr,
            tgt, tgth, nullptr, nullptr, 512, 2, tgt3, ls3 + lC, p1);
    }

    gn_elem_apply<<<dim3(NW,8), 256>>>(tgt, p1, 2, gnfw, gnfb, fin);
    scatter_kernel<<<65536, 256>>>(fin, out);
}

// round 11
// speedup vs baseline: 6.4943x; 1.2268x over previous
#include <cuda_runtime.h>
#include <cuda_fp16.h>
#include <math.h>
#include <stdint.h>

#define NW   512
#define CDIM 256
#define PDIM 128
#define WSZ  (CDIM*PDIM)

// ---------------- scratch (static device globals; no allocations) ----------
__device__ float g_tgt [NW*WSZ];
__device__ float g_tgt2[NW*WSZ];
__device__ float g_tgt3[NW*WSZ];
__device__ __half g_memh[NW*WSZ];
__device__ __half g_tgth[NW*WSZ];
__device__ __half g_qh [NW*WSZ];
__device__ __half g_kh [NW*WSZ];
__device__ __half g_vh [NW*WSZ];
__device__ __half g_hh [NW*2*WSZ];
__device__ __half g_wh[2*458752];
__device__ float g_p1[NW*16];
__device__ float g_p2[NW*16];
__device__ float g_p3[NW*16];

// ================= helpers =================================================
__device__ __forceinline__ uint32_t smem_u32(const void* p) {
    uint32_t a;
    asm("{ .reg .u64 t; cvta.to.shared.u64 t, %1; cvt.u32.u64 %0, t; }" : "=r"(a) : "l"(p));
    return a;
}
#define LDSM_X4(r0,r1,r2,r3,addr) \
    asm volatile("ldmatrix.sync.aligned.m8n8.x4.shared.b16 {%0,%1,%2,%3}, [%4];" \
        : "=r"(r0),"=r"(r1),"=r"(r2),"=r"(r3) : "r"(addr))
#define LDSM_X4_T(r0,r1,r2,r3,addr) \
    asm volatile("ldmatrix.sync.aligned.m8n8.x4.trans.shared.b16 {%0,%1,%2,%3}, [%4];" \
        : "=r"(r0),"=r"(r1),"=r"(r2),"=r"(r3) : "r"(addr))
__device__ __forceinline__ void mma_f16(float* d, const unsigned* a, const unsigned* b) {
    asm volatile("mma.sync.aligned.m16n8k16.row.col.f32.f16.f16.f32 "
        "{%0,%1,%2,%3}, {%4,%5,%6,%7}, {%8,%9}, {%0,%1,%2,%3};"
        : "+f"(d[0]),"+f"(d[1]),"+f"(d[2]),"+f"(d[3])
        : "r"(a[0]),"r"(a[1]),"r"(a[2]),"r"(a[3]), "r"(b[0]),"r"(b[1]));
}
__device__ __forceinline__ unsigned pack2h(float a, float b) {
    __half ah = __float2half_rn(a), bh = __float2half_rn(b);
    return (unsigned)__half_as_ushort(ah) | ((unsigned)__half_as_ushort(bh) << 16);
}
__device__ __forceinline__ void read_stats(const float* part, int win, int nparts,
                                           float& mean, float& rstd) {
    float S = 0.f, Q = 0.f;
    for (int i = 0; i < nparts; ++i) { S += part[win*16 + i*2]; Q += part[win*16 + i*2 + 1]; }
    mean = S * (1.f / 32768.f);
    float var = Q * (1.f / 32768.f) - mean * mean;
    rstd = rsqrtf(var + 1e-5f);
}

// ---------------- partition (merged src + qf) -------------------------------
__global__ void partition_kernel(const float* __restrict__ src, const float* __restrict__ qf,
                                 __half* __restrict__ memh, __half* __restrict__ tgth,
                                 float* __restrict__ tgt) {
    int gb = blockIdx.x;
    bool isq = gb >= 32768;
    int g = (isq ? gb - 32768 : gb) * 256 + threadIdx.x;
    int idx = g * 2;
    int p = idx & 127, c = (idx >> 7) & 255, bw = idx >> 15;
    int b = bw >> 7, wblk = bw & 127;
    int h = (wblk >> 3) * 8 + (p >> 4), w = (wblk & 7) * 16 + (p & 15);
    const float* s = (isq ? qf : src) + (((size_t)b * 256 + c) * 128 + h) * 128 + w;
    float a0 = s[0], a1 = s[1];
    unsigned u = pack2h(a0, a1);
    if (isq) {
        *(unsigned*)(tgth + idx) = u;
        *(float2*)(tgt + idx) = make_float2(a0, a1);
    } else {
        *(unsigned*)(memh + idx) = u;
    }
}

// ---------------- all weights fp32 -> single fp16 (one launch) --------------
__global__ void conv_w_all(const float* __restrict__ qw, const float* __restrict__ kw,
                           const float* __restrict__ vw, const float* __restrict__ fc1w,
                           const float* __restrict__ fc2w, __half* __restrict__ hi) {
    int g = blockIdx.x * 256 + threadIdx.x;
    int l = g / 57344, r = g - l * 57344;
    const float* srcp;
    size_t oo;
    if (r < 8192)        { srcp = qw  + (size_t)l*65536  + (size_t)r*8;          oo = (size_t)l*458752 + (size_t)r*8; }
    else if (r < 16384)  { srcp = kw  + (size_t)l*65536  + (size_t)(r-8192)*8;   oo = (size_t)l*458752 + 65536  + (size_t)(r-8192)*8; }
    else if (r < 24576)  { srcp = vw  + (size_t)l*65536  + (size_t)(r-16384)*8;  oo = (size_t)l*458752 + 131072 + (size_t)(r-16384)*8; }
    else if (r < 40960)  { srcp = fc1w+ (size_t)l*131072 + (size_t)(r-24576)*8;  oo = (size_t)l*458752 + 196608 + (size_t)(r-24576)*8; }
    else                 { srcp = fc2w+ (size_t)l*131072 + (size_t)(r-40960)*8;  oo = (size_t)l*458752 + 327680 + (size_t)(r-40960)*8; }
    unsigned hh[4];
#pragma unroll
    for (int j = 0; j < 4; ++j) hh[j] = pack2h(srcp[2*j], srcp[2*j+1]);
    uint4 vh = {hh[0], hh[1], hh[2], hh[3]};
    *(uint4*)(hi + oo) = vh;
}

// ---------------- GN stats ---------------------------------------------------
__global__ __launch_bounds__(256)
void gn_stats(const float* __restrict__ in, float* __restrict__ part) {
    __shared__ float red[16];
    int win = blockIdx.x, tid = threadIdx.x, lane = tid & 31, wid = tid >> 5;
    const float4* x = (const float4*)(in + (size_t)win * WSZ);
    float s = 0.f, q = 0.f;
#pragma unroll
    for (int k = 0; k < 32; ++k) {
        float4 v = x[tid + k * 256];
        s += v.x + v.y + v.z + v.w;
        q += v.x*v.x + v.y*v.y + v.z*v.z + v.w*v.w;
    }
#pragma unroll
    for (int off = 16; off; off >>= 1) {
        s += __shfl_down_sync(0xffffffffu, s, off);
        q += __shfl_down_sync(0xffffffffu, q, off);
    }
    if (lane == 0) { red[wid] = s; red[8 + wid] = q; }
    __syncthreads();
    if (tid == 0) {
        float ts = 0.f, tq = 0.f;
#pragma unroll
        for (int i = 0; i < 8; ++i) { ts += red[i]; tq += red[8 + i]; }
        part[win*16 + 0] = ts; part[win*16 + 1] = tq;
        part[win*16 + 2] = 0.f; part[win*16 + 3] = 0.f;
    }
}

// ---------------- GN apply + shuffle-stencil mix + residual ------------------
__global__ __launch_bounds__(256)
void gn_mix_apply(const float* __restrict__ in, const float* __restrict__ basep,
                  const float* __restrict__ part, int nparts,
                  const float* __restrict__ gw, const float* __restrict__ gb,
                  const float* __restrict__ ls, float* __restrict__ outf,
                  float* __restrict__ out_part) {
    __shared__ float red[16];
    int win = blockIdx.x, yb = blockIdx.y, tid = threadIdx.x, lane = tid & 31, wid = tid >> 5;
    float mean, rstd;
    read_stats(part, win, nparts, mean, rstd);

    int p0 = lane * 4;
    int y = lane >> 2, x0 = (lane & 3) * 4;
    float vcnt = 3.f - (y == 0 ? 1.f : 0.f) - (y == 7 ? 1.f : 0.f);
    float rinv[4];
#pragma unroll
    for (int j = 0; j < 4; ++j) {
        int x = x0 + j;
        float hc = 3.f - (x == 0 ? 1.f : 0.f) - (x == 15 ? 1.f : 0.f);
        rinv[j] = 1.f / (hc * vcnt);
    }

    float s2 = 0.f, q2 = 0.f;
#pragma unroll
    for (int ci = 0; ci < 4; ++ci) {
        int c = yb * 32 + wid * 4 + ci;
        size_t gi = (size_t)win * WSZ + c * 128 + p0;
        float w = gw[c], bb = gb[c];
        float4 v = *(const float4*)(in + gi);
        v.x = (v.x - mean) * rstd * w + bb;
        v.y = (v.y - mean) * rstd * w + bb;
        v.z = (v.z - mean) * rstd * w + bb;
        v.w = (v.w - mean) * rstd * w + bb;
        float L = __shfl_up_sync(0xffffffffu, v.w, 1);
        float R = __shfl_down_sync(0xffffffffu, v.x, 1);
        if (x0 == 0)  L = 0.f;
        if (x0 == 12) R = 0.f;
        float4 h;
        h.x = L + v.x + v.y;
        h.y = v.x + v.y + v.z;
        h.z = v.y + v.z + v.w;
        h.w = v.z + v.w + R;
        float4 up, dn;
        up.x = __shfl_up_sync(0xffffffffu, h.x, 4);
        up.y = __shfl_up_sync(0xffffffffu, h.y, 4);
        up.z = __shfl_up_sync(0xffffffffu, h.z, 4);
        up.w = __shfl_up_sync(0xffffffffu, h.w, 4);
        dn.x = __shfl_down_sync(0xffffffffu, h.x, 4);
        dn.y = __shfl_down_sync(0xffffffffu, h.y, 4);
        dn.z = __shfl_down_sync(0xffffffffu, h.z, 4);
        dn.w = __shfl_down_sync(0xffffffffu, h.w, 4);
        if (y == 0) { up.x = up.y = up.z = up.w = 0.f; }
        if (y == 7) { dn.x = dn.y = dn.z = dn.w = 0.f; }
        float o0 = (up.x + h.x + dn.x) * rinv[0] - v.x;
        float o1 = (up.y + h.y + dn.y) * rinv[1] - v.y;
        float o2 = (up.z + h.z + dn.z) * rinv[2] - v.z;
        float o3 = (up.w + h.w + dn.w) * rinv[3] - v.w;
        float4 bv = *(const float4*)(basep + gi);
        float lsv = ls[c];
        float4 ov = {bv.x + lsv * o0, bv.y + lsv * o1,
                     bv.z + lsv * o2, bv.w + lsv * o3};
        *(float4*)(outf + gi) = ov;
        if (out_part) {
            s2 += ov.x + ov.y + ov.z + ov.w;
            q2 += ov.x*ov.x + ov.y*ov.y + ov.z*ov.z + ov.w*ov.w;
        }
    }
    if (out_part) {
#pragma unroll
        for (int off = 16; off; off >>= 1) {
            s2 += __shfl_down_sync(0xffffffffu, s2, off);
            q2 += __shfl_down_sync(0xffffffffu, q2, off);
        }
        if (lane == 0) { red[wid] = s2; red[8 + wid] = q2; }
        __syncthreads();
        if (tid == 0) {
            float ts = 0.f, tq = 0.f;
#pragma unroll
            for (int i = 0; i < 8; ++i) { ts += red[i]; tq += red[8 + i]; }
            out_part[win*16 + yb*2] = ts; out_part[win*16 + yb*2 + 1] = tq;
        }
    }
}

// ---------------- final GN + fused window-reverse transpose ------------------
// out[1, N, B, C] <- gnf(tgt)
__global__ __launch_bounds__(256)
void gn_final_apply(const float* __restrict__ in, const float* __restrict__ part, int nparts,
                    const float* __restrict__ gw, const float* __restrict__ gb,
                    float* __restrict__ out) {
    __shared__ float tile[32 * 129];
    int win = blockIdx.x, yb = blockIdx.y, tid = threadIdx.x, lane = tid & 31, wid = tid >> 5;
    float mean, rstd;
    read_stats(part, win, nparts, mean, rstd);
    size_t b0 = (size_t)win * WSZ + yb * 4096;
    const float4* src = (const float4*)(in + b0);
#pragma unroll
    for (int k = 0; k < 4; ++k) {
        int idx = tid + k * 256;
        int cl = idx >> 5, p4 = idx & 31;
        float w = gw[yb * 32 + cl], bb = gb[yb * 32 + cl];
        float4 v = src[idx];
        float* t = tile + cl * 129 + p4 * 4;
        t[0] = (v.x - mean) * rstd * w + bb;
        t[1] = (v.y - mean) * rstd * w + bb;
        t[2] = (v.z - mean) * rstd * w + bb;
        t[3] = (v.w - mean) * rstd * w + bb;
    }
    __syncthreads();
    int b = win >> 7, wblk = win & 127;
    int hb = (wblk >> 3) * 8, wb = (wblk & 7) * 16;
#pragma unroll
    for (int k = 0; k < 16; ++k) {
        int p = k * 8 + wid;
        int h = hb + (p >> 4), w = wb + (p & 15);
        int n = h * 128 + w;
        out[((size_t)n * 4 + b) * 256 + yb * 32 + lane] = tile[lane * 129 + p];
    }
}

// ---------------- tensor-core GEMM (single fp16, double-buffered) ------------
// mode 0: merged QKV  mode 1: fc1 with fused gn2 staging  mode 2: fc2 residual
__global__ __launch_bounds__(256, 2)
void gemm_tc_kernel(const __half* __restrict__ Wh,
                    const __half* __restrict__ Xa, const __half* __restrict__ Xb,
                    const float* __restrict__ Xf, const float* __restrict__ g2w,
                    const float* __restrict__ g2b, const float* __restrict__ statsp,
                    const float* __restrict__ b0p, const float* __restrict__ b1p,
                    const float* __restrict__ b2p,
                    float* __restrict__ Yf,
                    __half* __restrict__ Yq, __half* __restrict__ Yk, __half* __restrict__ Yv,
                    int CIN, int mode,
                    const float* __restrict__ base, const float* __restrict__ ls,
                    float* __restrict__ partials) {
    extern __shared__ __half sb[];
    // per buffer: sW [128][72] (9216 halfs) + sX [64][136] (8704 halfs)
    __half* sWb[2] = { sb, sb + 17920 };
    __half* sXb[2] = { sb + 9216, sb + 17920 + 9216 };
    int win = blockIdx.x, ob = blockIdx.y;
    int tid = threadIdx.x, lane = tid & 31, wid = tid >> 5;
    int wr = wid >> 1, wc = wid & 1;

    const __half* gW = Wh + (size_t)ob * 128 * CIN;
    const __half* X = nullptr;
    __half* outH = nullptr;
    const float* bias;
    int O, O0;
    float gmean = 0.f, grstd = 0.f;
    if (mode == 0) {
        int mat = ob >> 1;
        X = (mat == 0) ? Xa : Xb;
        bias = (mat == 0) ? b0p : (mat == 1 ? b1p : b2p);
        outH = (mat == 0) ? Yq : (mat == 1 ? Yk : Yv);
        O = 256; O0 = (ob & 1) * 128;
    } else if (mode == 1) {
        bias = b0p;
        O = 512; O0 = ob * 128;
        outH = Yq;
        read_stats(statsp, win, 8, gmean, grstd);
    } else {
        X = Xa; bias = b0p;
        O = 256; O0 = ob * 128;
        outH = Yq;
    }
    const uint4* gX4 = (mode != 1) ? (const uint4*)X + (size_t)win * CIN * 16 : nullptr;
    const float* gXf = (mode == 1) ? Xf + (size_t)win * WSZ : nullptr;

    auto stage = [&](int t, int buf) {
        int kc = t << 6;
        __half* sW = sWb[buf];
        __half* sX = sXb[buf];
#pragma unroll
        for (int i = tid; i < 1024; i += 256) {
            int r = i >> 3, c4 = i & 7;
            *(uint4*)(sW + r * 72 + c4 * 8) = *(const uint4*)(gW + (size_t)r * CIN + kc + c4 * 8);
        }
        if (mode == 1) {
#pragma unroll
            for (int i = tid; i < 2048; i += 256) {
                int r = i >> 5, p4 = i & 31;
                int c = kc + r;
                float4 v = *(const float4*)(gXf + (size_t)c * 128 + p4 * 4);
                float w = g2w[c], bb = g2b[c];
                v.x = (v.x - gmean) * grstd * w + bb;
                v.y = (v.y - gmean) * grstd * w + bb;
                v.z = (v.z - gmean) * grstd * w + bb;
                v.w = (v.w - gmean) * grstd * w + bb;
                uint2 u = {pack2h(v.x, v.y), pack2h(v.z, v.w)};
                *(uint2*)(sX + r * 136 + p4 * 4) = u;
            }
        } else {
#pragma unroll
            for (int i = tid; i < 1024; i += 256) {
                int r = i >> 4, c4 = i & 15;
                *(uint4*)(sX + r * 136 + c4 * 8) = gX4[(kc + r) * 16 + c4];
            }
        }
    };

    float acc[2][8][4];
#pragma unroll
    for (int mt = 0; mt < 2; ++mt)
#pragma unroll
        for (int nt = 0; nt < 8; ++nt)
#pragma unroll
            for (int e = 0; e < 4; ++e) acc[mt][nt][e] = 0.f;

    int aRow = (lane & 15), aCol = (lane >> 4) * 8;
    int brbase = ((lane >> 3) & 1) * 8 + (lane & 7);
    int bcofs  = (lane >> 4) * 8;
    int nkc = CIN >> 6;

    stage(0, 0);
    for (int t = 0; t < nkc; ++t) {
        __syncthreads();
        if (t + 1 < nkc) stage(t + 1, (t + 1) & 1);
        const __half* sW = sWb[t & 1];
        const __half* sX = sXb[t & 1];
#pragma unroll
        for (int ks = 0; ks < 4; ++ks) {
            unsigned aW[2][4];
#pragma unroll
            for (int mt = 0; mt < 2; ++mt) {
                int ro = (wr * 32 + mt * 16 + aRow) * 72 + ks * 16 + aCol;
                LDSM_X4(aW[mt][0], aW[mt][1], aW[mt][2], aW[mt][3], smem_u32(sW + ro));
            }
#pragma unroll
            for (int np = 0; np < 4; ++np) {
                int bo = (ks * 16 + brbase) * 136 + wc * 64 + np * 16 + bcofs;
                unsigned bX[4];
                LDSM_X4_T(bX[0], bX[1], bX[2], bX[3], smem_u32(sX + bo));
#pragma unroll
                for (int mt = 0; mt < 2; ++mt) {
                    mma_f16(acc[mt][np*2],   aW[mt], bX);
                    mma_f16(acc[mt][np*2+1], aW[mt], bX + 2);
                }
            }
        }
    }

    float ssum = 0.f, ssq = 0.f;
#pragma unroll
    for (int mt = 0; mt < 2; ++mt)
#pragma unroll
        for (int nt = 0; nt < 8; ++nt) {
            int p = wc * 64 + nt * 8 + (lane & 3) * 2;
#pragma unroll
            for (int half = 0; half < 2; ++half) {
                int o = O0 + wr * 32 + mt * 16 + (lane >> 2) + half * 8;
                float bv = bias[o];
                float2 v;
                v.x = acc[mt][nt][half * 2]     + bv;
                v.y = acc[mt][nt][half * 2 + 1] + bv;
                size_t gi = ((size_t)win * O + o) * 128 + p;
                if (mode == 1) {
                    v.x = 0.5f * v.x * (1.f + erff(v.x * 0.70710678118654752f));
                    v.y = 0.5f * v.y * (1.f + erff(v.y * 0.70710678118654752f));
                } else if (mode == 2) {
                    float lsv = ls[o];
                    float2 b2 = *(const float2*)(base + gi);
                    v.x = b2.x + lsv * v.x;
                    v.y = b2.y + lsv * v.y;
                    *(float2*)(Yf + gi) = v;
                    ssum += v.x + v.y;
                    ssq  += v.x*v.x + v.y*v.y;
                }
                *(unsigned*)(outH + gi) = pack2h(v.x, v.y);
            }
        }

    if (mode == 2) {
        __syncthreads();
        float* red = (float*)sb;
#pragma unroll
        for (int off = 16; off; off >>= 1) {
            ssum += __shfl_down_sync(0xffffffffu, ssum, off);
            ssq  += __shfl_down_sync(0xffffffffu, ssq,  off);
        }
        if (lane == 0) { red[wid] = ssum; red[8 + wid] = ssq; }
        __syncthreads();
        if (tid == 0) {
            float ts = 0.f, tq = 0.f;
#pragma unroll
            for (int i = 0; i < 8; ++i) { ts += red[i]; tq += red[8 + i]; }
            partials[win*16 + ob*2] = ts; partials[win*16 + ob*2 + 1] = tq;
        }
    }
}

// ---------------- attention (single fp16, double-buffered staging) -----------
__global__ __launch_bounds__(256, 2)
void attn_kernel(const __half* __restrict__ Qh, const __half* __restrict__ Kh,
                 const __half* __restrict__ Vh,
                 const float* __restrict__ tgt2, float* __restrict__ tgt3,
                 float* __restrict__ out_part) {
    extern __shared__ __half sat[];
    // S phase: per buffer sQ [128][72] + sK [128][72] = 18432 halfs
    __half* sQb[2] = { sat, sat + 18432 };
    __half* sKb[2] = { sat + 9216, sat + 18432 + 9216 };
    // PV phase: per buffer sV [128][136] = 17408 halfs
    __half* sVb[2] = { sat, sat + 17408 };
    __shared__ float ared[16];
    int win = blockIdx.x, tid = threadIdx.x, lane = tid & 31, wid = tid >> 5;

    const uint4* gQ = (const uint4*)Qh + (size_t)win * 4096;
    const uint4* gK = (const uint4*)Kh + (size_t)win * 4096;
    const uint4* gV = (const uint4*)Vh + (size_t)win * 4096;

    auto stage_s = [&](int ch, int buf) {
        __half* sQ = sQb[buf];
        __half* sK = sKb[buf];
#pragma unroll
        for (int i = tid; i < 1024; i += 256) {
            int r = i >> 3, c4 = i & 7;
            int gi = r * 32 + ch * 8 + c4;
            int so = r * 72 + c4 * 8;
            *(uint4*)(sQ + so) = gQ[gi];
            *(uint4*)(sK + so) = gK[gi];
        }
    };
    auto stage_v = [&](int cv, int buf) {
        __half* sV = sVb[buf];
#pragma unroll
        for (int i = tid; i < 2048; i += 256) {
            int r = i >> 4, c4 = i & 15;
            *(uint4*)(sV + r * 136 + c4 * 8) = gV[r * 32 + cv * 16 + c4];
        }
    };

    float acc[16][4];
#pragma unroll
    for (int j = 0; j < 16; ++j)
#pragma unroll
        for (int e = 0; e < 4; ++e) acc[j][e] = 0.f;

    int aRow = lane & 15, aCol = (lane >> 4) * 8;
    int kRow = (lane & 7) + ((lane >> 4) & 1) * 8;
    int kCol = ((lane >> 3) & 1) * 8;
    int tRow = ((lane >> 3) & 1) * 8 + (lane & 7);
    int tCol = (lane >> 4) * 8;

    // ---- S = Qv @ Kv^T over 4 chunks of 64 channels (ping-pong) ----
    stage_s(0, 0);
    for (int ch = 0; ch < 4; ++ch) {
        __syncthreads();
        if (ch + 1 < 4) stage_s(ch + 1, (ch + 1) & 1);
        const __half* sQ = sQb[ch & 1];
        const __half* sK = sKb[ch & 1];
#pragma unroll
        for (int ks = 0; ks < 4; ++ks) {
            unsigned aQ[4];
            int ro = (wid * 16 + aRow) * 72 + ks * 16 + aCol;
            LDSM_X4(aQ[0], aQ[1], aQ[2], aQ[3], smem_u32(sQ + ro));
#pragma unroll
            for (int ng = 0; ng < 8; ++ng) {
                int bo = (ng * 16 + kRow) * 72 + ks * 16 + kCol;
                unsigned bK[4];
                LDSM_X4(bK[0], bK[1], bK[2], bK[3], smem_u32(sK + bo));
                mma_f16(acc[ng*2],   aQ, bK);
                mma_f16(acc[ng*2+1], aQ, bK + 2);
            }
        }
    }

    // ---- softmax ----
    float mx0 = -1e30f, mx1 = -1e30f;
#pragma unroll
    for (int j = 0; j < 16; ++j) {
        mx0 = fmaxf(mx0, fmaxf(acc[j][0], acc[j][1]));
        mx1 = fmaxf(mx1, fmaxf(acc[j][2], acc[j][3]));
    }
#pragma unroll
    for (int off = 1; off <= 2; off <<= 1) {
        mx0 = fmaxf(mx0, __shfl_xor_sync(0xffffffffu, mx0, off));
        mx1 = fmaxf(mx1, __shfl_xor_sync(0xffffffffu, mx1, off));
    }
    float s0 = 0.f, s1 = 0.f;
#pragma unroll
    for (int j = 0; j < 16; ++j) {
        acc[j][0] = expf(acc[j][0] - mx0); s0 += acc[j][0];
        acc[j][1] = expf(acc[j][1] - mx0); s0 += acc[j][1];
        acc[j][2] = expf(acc[j][2] - mx1); s1 += acc[j][2];
        acc[j][3] = expf(acc[j][3] - mx1); s1 += acc[j][3];
    }
#pragma unroll
    for (int off = 1; off <= 2; off <<= 1) {
        s0 += __shfl_xor_sync(0xffffffffu, s0, off);
        s1 += __shfl_xor_sync(0xffffffffu, s1, off);
    }
    float i0 = 1.f / s0, i1 = 1.f / s1;
#pragma unroll
    for (int j = 0; j < 16; ++j) {
        acc[j][0] *= i0; acc[j][1] *= i0;
        acc[j][2] *= i1; acc[j][3] *= i1;
    }

    unsigned pfr[8][4];
#pragma unroll
    for (int t = 0; t < 8; ++t) {
        pfr[t][0] = pack2h(acc[2*t][0],   acc[2*t][1]);
        pfr[t][1] = pack2h(acc[2*t][2],   acc[2*t][3]);
        pfr[t][2] = pack2h(acc[2*t+1][0], acc[2*t+1][1]);
        pfr[t][3] = pack2h(acc[2*t+1][2], acc[2*t+1][3]);
    }

    // ---- O = P @ Vv over 2 cv chunks (ping-pong) ----
    float ssum = 0.f, ssq = 0.f;
    __syncthreads();              // all warps done with S-phase smem
    stage_v(0, 0);
    for (int cv = 0; cv < 2; ++cv) {
        __syncthreads();
        if (cv + 1 < 2) stage_v(cv + 1, 1);
        const __half* sV = sVb[cv & 1];
        float oacc[16][4];
#pragma unroll
        for (int j = 0; j < 16; ++j)
#pragma unroll
            for (int e = 0; e < 4; ++e) oacc[j][e] = 0.f;
#pragma unroll
        for (int mk = 0; mk < 8; ++mk) {
#pragma unroll
            for (int ng = 0; ng < 8; ++ng) {
                int bo = (mk * 16 + tRow) * 136 + ng * 16 + tCol;
                unsigned vV[4];
                LDSM_X4_T(vV[0], vV[1], vV[2], vV[3], smem_u32(sV + bo));
                mma_f16(oacc[ng*2],   pfr[mk], vV);
                mma_f16(oacc[ng*2+1], pfr[mk], vV + 2);
            }
        }
#pragma unroll
        for (int j = 0; j < 16; ++j) {
            int col = cv * 128 + j * 8 + (lane & 3) * 2;
            int n0 = wid * 16 + (lane >> 2);
            size_t gi = (size_t)win * WSZ + n0 * 256 + col;
            float2 b0 = *(const float2*)(tgt2 + gi);
            float2 r0 = {b0.x + oacc[j][0], b0.y + oacc[j][1]};
            *(float2*)(tgt3 + gi) = r0;
            size_t gi1 = gi + 8 * 256;
            float2 b1 = *(const float2*)(tgt2 + gi1);
            float2 r1 = {b1.x + oacc[j][2], b1.y + oacc[j][3]};
            *(float2*)(tgt3 + gi1) = r1;
            ssum += r0.x + r0.y + r1.x + r1.y;
            ssq  += r0.x*r0.x + r0.y*r0.y + r1.x*r1.x + r1.y*r1.y;
        }
    }

#pragma unroll
    for (int off = 16; off; off >>= 1) {
        ssum += __shfl_down_sync(0xffffffffu, ssum, off);
        ssq  += __shfl_down_sync(0xffffffffu, ssq,  off);
    }
    if (lane == 0) { ared[wid] = ssum; ared[8 + wid] = ssq; }
    __syncthreads();
    if (tid == 0) {
        float ts = 0.f, tq = 0.f;
#pragma unroll
        for (int i = 0; i < 8; ++i) { ts += ared[i]; tq += ared[8 + i]; }
        out_part[win*16 + 0] = ts; out_part[win*16 + 1] = tq;
    }
}

// ---------------- host orchestration ---------------------------------------
extern "C" void kernel_launch(void* const* d_in, const int* in_sizes, int n_in,
                              void* d_out, int out_size) {
    const float* src  = (const float*)d_in[0];
    const float* qf   = (const float*)d_in[1];
    const float* gn1w = (const float*)d_in[2];
    const float* gn1b = (const float*)d_in[3];
    const float* gn2w = (const float*)d_in[4];
    const float* gn2b = (const float*)d_in[5];
    const float* ls1  = (const float*)d_in[6];
    const float* ls2  = (const float*)d_in[7];
    const float* ls3  = (const float*)d_in[8];
    const float* qw   = (const float*)d_in[9];
    const float* qb   = (const float*)d_in[10];
    const float* kw   = (const float*)d_in[11];
    const float* kb   = (const float*)d_in[12];
    const float* vw   = (const float*)d_in[13];
    const float* vb   = (const float*)d_in[14];
    const float* fc1w = (const float*)d_in[15];
    const float* fc1b = (const float*)d_in[16];
    const float* fc2w = (const float*)d_in[17];
    const float* fc2b = (const float*)d_in[18];
    const float* gnfw = (const float*)d_in[19];
    const float* gnfb = (const float*)d_in[20];
    float* out = (float*)d_out;

    float *tgt, *tgt2, *tgt3, *p1, *p2, *p3;
    __half *memh, *tgth, *qh, *kh, *vh, *hh, *wh;
    cudaGetSymbolAddress((void**)&tgt,  g_tgt);
    cudaGetSymbolAddress((void**)&tgt2, g_tgt2);
    cudaGetSymbolAddress((void**)&tgt3, g_tgt3);
    cudaGetSymbolAddress((void**)&p1,   g_p1);
    cudaGetSymbolAddress((void**)&p2,   g_p2);
    cudaGetSymbolAddress((void**)&p3,   g_p3);
    cudaGetSymbolAddress((void**)&memh, g_memh);
    cudaGetSymbolAddress((void**)&tgth, g_tgth);
    cudaGetSymbolAddress((void**)&qh,   g_qh);
    cudaGetSymbolAddress((void**)&kh,   g_kh);
    cudaGetSymbolAddress((void**)&vh,   g_vh);
    cudaGetSymbolAddress((void**)&hh,   g_hh);
    cudaGetSymbolAddress((void**)&wh,   g_wh);

    const int SM_ATTN = 73728;   // 2 x (sQ+sK) buffers
    const int SM_TC   = 71680;   // 2 x (sW+sX) buffers
    cudaFuncSetAttribute(attn_kernel,    cudaFuncAttributeMaxDynamicSharedMemorySize, SM_ATTN);
    cudaFuncSetAttribute(gemm_tc_kernel, cudaFuncAttributeMaxDynamicSharedMemorySize, SM_TC);

    partition_kernel<<<65536, 256>>>(src, qf, memh, tgth, tgt);
    conv_w_all<<<448, 256>>>(qw, kw, vw, fc1w, fc2w, wh);
    gn_stats<<<NW, 256>>>(tgt, p1);

    for (int l = 0; l < 2; ++l) {
        int lC = l * CDIM;
        size_t lb = (size_t)l * 458752;
        gn_mix_apply<<<dim3(NW,8), 256>>>(tgt, tgt, p1, 2, gn1w + lC, gn1b + lC, ls1 + lC, tgt2, nullptr);
        gemm_tc_kernel<<<dim3(NW,6), 256, SM_TC>>>(wh + lb,
            tgth, memh, nullptr, nullptr, nullptr, nullptr,
            qb + lC, kb + lC, vb + lC,
            nullptr, qh, kh, vh, 256, 0, nullptr, nullptr, nullptr);
        attn_kernel<<<NW, 256, SM_ATTN>>>(qh, kh, vh, tgt2, tgt3, p2);
        gn_mix_apply<<<dim3(NW,8), 256>>>(tgt3, tgt2, p2, 1, gn1w + lC, gn1b + lC, ls2 + lC, tgt3, p3);
        gemm_tc_kernel<<<dim3(NW,4), 256, SM_TC>>>(wh + lb + 196608,
            nullptr, nullptr, tgt3, gn2w + lC, gn2b + lC, p3,
            fc1b + (size_t)l*512, nullptr, nullptr,
            nullptr, hh, nullptr, nullptr, 256, 1, nullptr, nullptr, nullptr);
        gemm_tc_kernel<<<dim3(NW,2), 256, SM_TC>>>(wh + lb + 327680,
            hh, nullptr, nullptr, nullptr, nullptr, nullptr,
            fc2b + lC, nullptr, nullptr,
            tgt, tgth, nullptr, nullptr, 512, 2, tgt3, ls3 + lC, p1);
    }

    gn_final_apply<<<dim3(NW,8), 256>>>(tgt, p1, 2, gnfw, gnfb, out);
}

// round 12
// speedup vs baseline: 6.8072x; 1.0482x over previous
#include <cuda_runtime.h>
#include <cuda_fp16.h>
#include <math.h>
#include <stdint.h>

#define NW   512
#define CDIM 256
#define PDIM 128
#define WSZ  (CDIM*PDIM)

// ---------------- scratch (static device globals; no allocations) ----------
__device__ float g_tgt [NW*WSZ];
__device__ float g_tgt2[NW*WSZ];
__device__ float g_tgt3[NW*WSZ];
__device__ __half g_memh[NW*WSZ];
__device__ __half g_tgth[NW*WSZ];
__device__ __half g_qh [NW*WSZ];
__device__ __half g_kh [NW*WSZ];
__device__ __half g_vh [NW*WSZ];
__device__ __half g_hh [NW*2*WSZ];
__device__ __half g_wh[2*458752];
__device__ float g_p0[NW*128];   // partition partials (64 slots/win)
__device__ float g_p1[NW*16];
__device__ float g_p2[NW*16];
__device__ float g_p3[NW*16];

// ================= helpers =================================================
__device__ __forceinline__ uint32_t smem_u32(const void* p) {
    uint32_t a;
    asm("{ .reg .u64 t; cvta.to.shared.u64 t, %1; cvt.u32.u64 %0, t; }" : "=r"(a) : "l"(p));
    return a;
}
#define LDSM_X4(r0,r1,r2,r3,addr) \
    asm volatile("ldmatrix.sync.aligned.m8n8.x4.shared.b16 {%0,%1,%2,%3}, [%4];" \
        : "=r"(r0),"=r"(r1),"=r"(r2),"=r"(r3) : "r"(addr))
#define LDSM_X4_T(r0,r1,r2,r3,addr) \
    asm volatile("ldmatrix.sync.aligned.m8n8.x4.trans.shared.b16 {%0,%1,%2,%3}, [%4];" \
        : "=r"(r0),"=r"(r1),"=r"(r2),"=r"(r3) : "r"(addr))
__device__ __forceinline__ void mma_f16(float* d, const unsigned* a, const unsigned* b) {
    asm volatile("mma.sync.aligned.m16n8k16.row.col.f32.f16.f16.f32 "
        "{%0,%1,%2,%3}, {%4,%5,%6,%7}, {%8,%9}, {%0,%1,%2,%3};"
        : "+f"(d[0]),"+f"(d[1]),"+f"(d[2]),"+f"(d[3])
        : "r"(a[0]),"r"(a[1]),"r"(a[2]),"r"(a[3]), "r"(b[0]),"r"(b[1]));
}
#define CP_ASYNC16(sa, gp) \
    asm volatile("cp.async.cg.shared.global [%0], [%1], 16;" :: "r"(sa), "l"(gp))
#define CP_COMMIT() asm volatile("cp.async.commit_group;" ::: "memory")
#define CP_WAIT0()  asm volatile("cp.async.wait_group 0;" ::: "memory")
__device__ __forceinline__ unsigned pack2h(float a, float b) {
    __half ah = __float2half_rn(a), bh = __float2half_rn(b);
    return (unsigned)__half_as_ushort(ah) | ((unsigned)__half_as_ushort(bh) << 16);
}
__device__ __forceinline__ void read_stats(const float* part, int win, int pstride, int nparts,
                                           float& mean, float& rstd) {
    float S = 0.f, Q = 0.f;
    for (int i = 0; i < nparts; ++i) { S += part[win*pstride + i*2]; Q += part[win*pstride + i*2 + 1]; }
    mean = S * (1.f / 32768.f);
    float var = Q * (1.f / 32768.f) - mean * mean;
    rstd = rsqrtf(var + 1e-5f);
}

// ---- shuffle-stencil GN+mix body (no partial output) ----
__device__ __forceinline__ void gn_mix_body(
        int win, int yb, int tid,
        const float* __restrict__ in, const float* __restrict__ basep,
        const float* __restrict__ part, int pstride, int nparts,
        const float* __restrict__ gw, const float* __restrict__ gb,
        const float* __restrict__ ls, float* __restrict__ outf) {
    int lane = tid & 31, wid = tid >> 5;
    float mean, rstd;
    read_stats(part, win, pstride, nparts, mean, rstd);
    int p0 = lane * 4;
    int y = lane >> 2, x0 = (lane & 3) * 4;
    float vcnt = 3.f - (y == 0 ? 1.f : 0.f) - (y == 7 ? 1.f : 0.f);
    float rinv[4];
#pragma unroll
    for (int j = 0; j < 4; ++j) {
        int x = x0 + j;
        float hc = 3.f - (x == 0 ? 1.f : 0.f) - (x == 15 ? 1.f : 0.f);
        rinv[j] = 1.f / (hc * vcnt);
    }
#pragma unroll
    for (int ci = 0; ci < 4; ++ci) {
        int c = yb * 32 + wid * 4 + ci;
        size_t gi = (size_t)win * WSZ + c * 128 + p0;
        float w = gw[c], bb = gb[c];
        float4 v = *(const float4*)(in + gi);
        v.x = (v.x - mean) * rstd * w + bb;
        v.y = (v.y - mean) * rstd * w + bb;
        v.z = (v.z - mean) * rstd * w + bb;
        v.w = (v.w - mean) * rstd * w + bb;
        float L = __shfl_up_sync(0xffffffffu, v.w, 1);
        float R = __shfl_down_sync(0xffffffffu, v.x, 1);
        if (x0 == 0)  L = 0.f;
        if (x0 == 12) R = 0.f;
        float4 h;
        h.x = L + v.x + v.y;
        h.y = v.x + v.y + v.z;
        h.z = v.y + v.z + v.w;
        h.w = v.z + v.w + R;
        float4 up, dn;
        up.x = __shfl_up_sync(0xffffffffu, h.x, 4);
        up.y = __shfl_up_sync(0xffffffffu, h.y, 4);
        up.z = __shfl_up_sync(0xffffffffu, h.z, 4);
        up.w = __shfl_up_sync(0xffffffffu, h.w, 4);
        dn.x = __shfl_down_sync(0xffffffffu, h.x, 4);
        dn.y = __shfl_down_sync(0xffffffffu, h.y, 4);
        dn.z = __shfl_down_sync(0xffffffffu, h.z, 4);
        dn.w = __shfl_down_sync(0xffffffffu, h.w, 4);
        if (y == 0) { up.x = up.y = up.z = up.w = 0.f; }
        if (y == 7) { dn.x = dn.y = dn.z = dn.w = 0.f; }
        float o0 = (up.x + h.x + dn.x) * rinv[0] - v.x;
        float o1 = (up.y + h.y + dn.y) * rinv[1] - v.y;
        float o2 = (up.z + h.z + dn.z) * rinv[2] - v.z;
        float o3 = (up.w + h.w + dn.w) * rinv[3] - v.w;
        float4 bv = *(const float4*)(basep + gi);
        float lsv = ls[c];
        float4 ov = {bv.x + lsv * o0, bv.y + lsv * o1,
                     bv.z + lsv * o2, bv.w + lsv * o3};
        *(float4*)(outf + gi) = ov;
    }
}

// ---------------- partition (merged src + qf, fused qf stats) ----------------
__global__ void partition_kernel(const float* __restrict__ src, const float* __restrict__ qf,
                                 __half* __restrict__ memh, __half* __restrict__ tgth,
                                 float* __restrict__ tgt, float* __restrict__ p0) {
    __shared__ float red[16];
    int gb = blockIdx.x;
    bool isq = gb >= 32768;
    int g = (isq ? gb - 32768 : gb) * 256 + threadIdx.x;
    int idx = g * 2;
    int p = idx & 127, c = (idx >> 7) & 255, bw = idx >> 15;
    int b = bw >> 7, wblk = bw & 127;
    int h = (wblk >> 3) * 8 + (p >> 4), w = (wblk & 7) * 16 + (p & 15);
    const float* s = (isq ? qf : src) + (((size_t)b * 256 + c) * 128 + h) * 128 + w;
    float a0 = s[0], a1 = s[1];
    unsigned u = pack2h(a0, a1);
    if (isq) {
        *(unsigned*)(tgth + idx) = u;
        *(float2*)(tgt + idx) = make_float2(a0, a1);
        // block covers one 512-elem aligned segment of one window
        int tid = threadIdx.x, lane = tid & 31, wid = tid >> 5;
        float ss = a0 + a1, qq = a0*a0 + a1*a1;
#pragma unroll
        for (int off = 16; off; off >>= 1) {
            ss += __shfl_down_sync(0xffffffffu, ss, off);
            qq += __shfl_down_sync(0xffffffffu, qq, off);
        }
        if (lane == 0) { red[wid] = ss; red[8 + wid] = qq; }
        __syncthreads();
        if (tid == 0) {
            float ts = 0.f, tq = 0.f;
#pragma unroll
            for (int i = 0; i < 8; ++i) { ts += red[i]; tq += red[8 + i]; }
            int sb = gb - 32768;
            int win = sb >> 6, slot = sb & 63;
            p0[win*128 + slot*2] = ts; p0[win*128 + slot*2 + 1] = tq;
        }
    } else {
        *(unsigned*)(memh + idx) = u;
    }
}

// ---------------- all weights fp32 -> single fp16 (one launch) --------------
__global__ void conv_w_all(const float* __restrict__ qw, const float* __restrict__ kw,
                           const float* __restrict__ vw, const float* __restrict__ fc1w,
                           const float* __restrict__ fc2w, __half* __restrict__ hi) {
    int g = blockIdx.x * 256 + threadIdx.x;
    int l = g / 57344, r = g - l * 57344;
    const float* srcp;
    size_t oo;
    if (r < 8192)        { srcp = qw  + (size_t)l*65536  + (size_t)r*8;          oo = (size_t)l*458752 + (size_t)r*8; }
    else if (r < 16384)  { srcp = kw  + (size_t)l*65536  + (size_t)(r-8192)*8;   oo = (size_t)l*458752 + 65536  + (size_t)(r-8192)*8; }
    else if (r < 24576)  { srcp = vw  + (size_t)l*65536  + (size_t)(r-16384)*8;  oo = (size_t)l*458752 + 131072 + (size_t)(r-16384)*8; }
    else if (r < 40960)  { srcp = fc1w+ (size_t)l*131072 + (size_t)(r-24576)*8;  oo = (size_t)l*458752 + 196608 + (size_t)(r-24576)*8; }
    else                 { srcp = fc2w+ (size_t)l*131072 + (size_t)(r-40960)*8;  oo = (size_t)l*458752 + 327680 + (size_t)(r-40960)*8; }
    unsigned hh[4];
#pragma unroll
    for (int j = 0; j < 4; ++j) hh[j] = pack2h(srcp[2*j], srcp[2*j+1]);
    uint4 vh = {hh[0], hh[1], hh[2], hh[3]};
    *(uint4*)(hi + oo) = vh;
}

// ---------------- standalone GN+mix (with partial-stats output) --------------
__global__ __launch_bounds__(256)
void gn_mix_apply(const float* __restrict__ in, const float* __restrict__ basep,
                  const float* __restrict__ part, int pstride, int nparts,
                  const float* __restrict__ gw, const float* __restrict__ gb,
                  const float* __restrict__ ls, float* __restrict__ outf,
                  float* __restrict__ out_part) {
    __shared__ float red[16];
    int win = blockIdx.x, yb = blockIdx.y, tid = threadIdx.x, lane = tid & 31, wid = tid >> 5;
    float mean, rstd;
    read_stats(part, win, pstride, nparts, mean, rstd);

    int p0 = lane * 4;
    int y = lane >> 2, x0 = (lane & 3) * 4;
    float vcnt = 3.f - (y == 0 ? 1.f : 0.f) - (y == 7 ? 1.f : 0.f);
    float rinv[4];
#pragma unroll
    for (int j = 0; j < 4; ++j) {
        int x = x0 + j;
        float hc = 3.f - (x == 0 ? 1.f : 0.f) - (x == 15 ? 1.f : 0.f);
        rinv[j] = 1.f / (hc * vcnt);
    }
    float s2 = 0.f, q2 = 0.f;
#pragma unroll
    for (int ci = 0; ci < 4; ++ci) {
        int c = yb * 32 + wid * 4 + ci;
        size_t gi = (size_t)win * WSZ + c * 128 + p0;
        float w = gw[c], bb = gb[c];
        float4 v = *(const float4*)(in + gi);
        v.x = (v.x - mean) * rstd * w + bb;
        v.y = (v.y - mean) * rstd * w + bb;
        v.z = (v.z - mean) * rstd * w + bb;
        v.w = (v.w - mean) * rstd * w + bb;
        float L = __shfl_up_sync(0xffffffffu, v.w, 1);
        float R = __shfl_down_sync(0xffffffffu, v.x, 1);
        if (x0 == 0)  L = 0.f;
        if (x0 == 12) R = 0.f;
        float4 h;
        h.x = L + v.x + v.y;
        h.y = v.x + v.y + v.z;
        h.z = v.y + v.z + v.w;
        h.w = v.z + v.w + R;
        float4 up, dn;
        up.x = __shfl_up_sync(0xffffffffu, h.x, 4);
        up.y = __shfl_up_sync(0xffffffffu, h.y, 4);
        up.z = __shfl_up_sync(0xffffffffu, h.z, 4);
        up.w = __shfl_up_sync(0xffffffffu, h.w, 4);
        dn.x = __shfl_down_sync(0xffffffffu, h.x, 4);
        dn.y = __shfl_down_sync(0xffffffffu, h.y, 4);
        dn.z = __shfl_down_sync(0xffffffffu, h.z, 4);
        dn.w = __shfl_down_sync(0xffffffffu, h.w, 4);
        if (y == 0) { up.x = up.y = up.z = up.w = 0.f; }
        if (y == 7) { dn.x = dn.y = dn.z = dn.w = 0.f; }
        float o0 = (up.x + h.x + dn.x) * rinv[0] - v.x;
        float o1 = (up.y + h.y + dn.y) * rinv[1] - v.y;
        float o2 = (up.z + h.z + dn.z) * rinv[2] - v.z;
        float o3 = (up.w + h.w + dn.w) * rinv[3] - v.w;
        float4 bv = *(const float4*)(basep + gi);
        float lsv = ls[c];
        float4 ov = {bv.x + lsv * o0, bv.y + lsv * o1,
                     bv.z + lsv * o2, bv.w + lsv * o3};
        *(float4*)(outf + gi) = ov;
        s2 += ov.x + ov.y + ov.z + ov.w;
        q2 += ov.x*ov.x + ov.y*ov.y + ov.z*ov.z + ov.w*ov.w;
    }
#pragma unroll
    for (int off = 16; off; off >>= 1) {
        s2 += __shfl_down_sync(0xffffffffu, s2, off);
        q2 += __shfl_down_sync(0xffffffffu, q2, off);
    }
    if (lane == 0) { red[wid] = s2; red[8 + wid] = q2; }
    __syncthreads();
    if (tid == 0) {
        float ts = 0.f, tq = 0.f;
#pragma unroll
        for (int i = 0; i < 8; ++i) { ts += red[i]; tq += red[8 + i]; }
        out_part[win*16 + yb*2] = ts; out_part[win*16 + yb*2 + 1] = tq;
    }
}

// ---------------- final GN + fused window-reverse transpose ------------------
__global__ __launch_bounds__(256)
void gn_final_apply(const float* __restrict__ in, const float* __restrict__ part, int nparts,
                    const float* __restrict__ gw, const float* __restrict__ gb,
                    float* __restrict__ out) {
    __shared__ float tile[32 * 129];
    int win = blockIdx.x, yb = blockIdx.y, tid = threadIdx.x, lane = tid & 31, wid = tid >> 5;
    float mean, rstd;
    read_stats(part, win, 16, nparts, mean, rstd);
    size_t b0 = (size_t)win * WSZ + yb * 4096;
    const float4* src = (const float4*)(in + b0);
#pragma unroll
    for (int k = 0; k < 4; ++k) {
        int idx = tid + k * 256;
        int cl = idx >> 5, p4 = idx & 31;
        float w = gw[yb * 32 + cl], bb = gb[yb * 32 + cl];
        float4 v = src[idx];
        float* t = tile + cl * 129 + p4 * 4;
        t[0] = (v.x - mean) * rstd * w + bb;
        t[1] = (v.y - mean) * rstd * w + bb;
        t[2] = (v.z - mean) * rstd * w + bb;
        t[3] = (v.w - mean) * rstd * w + bb;
    }
    __syncthreads();
    int b = win >> 7, wblk = win & 127;
    int hb = (wblk >> 3) * 8, wb = (wblk & 7) * 16;
#pragma unroll
    for (int k = 0; k < 16; ++k) {
        int p = k * 8 + wid;
        int h = hb + (p >> 4), w = wb + (p & 15);
        int n = h * 128 + w;
        out[((size_t)n * 4 + b) * 256 + yb * 32 + lane] = tile[lane * 129 + p];
    }
}

// ---------------- tensor-core GEMM (cp.async double-buffered) ----------------
// mode 0: merged QKV + gn_mix slices (ob>=6)  mode 1: fc1+gn2  mode 2: fc2
__global__ __launch_bounds__(256, 2)
void gemm_tc_kernel(const __half* __restrict__ Wh,
                    const __half* __restrict__ Xa, const __half* __restrict__ Xb,
                    const float* __restrict__ Xf, const float* __restrict__ g2w,
                    const float* __restrict__ g2b, const float* __restrict__ statsp,
                    const float* __restrict__ b0p, const float* __restrict__ b1p,
                    const float* __restrict__ b2p,
                    float* __restrict__ Yf,
                    __half* __restrict__ Yq, __half* __restrict__ Yk, __half* __restrict__ Yv,
                    int CIN, int mode,
                    const float* __restrict__ base, const float* __restrict__ ls,
                    float* __restrict__ partials,
                    const float* __restrict__ mixIn, const float* __restrict__ mixBase,
                    const float* __restrict__ mixPart, int mixPstride, int mixNparts,
                    const float* __restrict__ mixGw, const float* __restrict__ mixGb,
                    const float* __restrict__ mixLs, float* __restrict__ mixOut) {
    extern __shared__ __half sb[];
    int win = blockIdx.x, ob = blockIdx.y;
    int tid = threadIdx.x, lane = tid & 31, wid = tid >> 5;

    if (mode == 0 && ob >= 6) {
        gn_mix_body(win, ob - 6, tid, mixIn, mixBase, mixPart, mixPstride, mixNparts,
                    mixGw, mixGb, mixLs, mixOut);
        return;
    }

    __half* sWb[2] = { sb, sb + 17920 };
    __half* sXb[2] = { sb + 9216, sb + 17920 + 9216 };
    int wr = wid >> 1, wc = wid & 1;

    const __half* gW = Wh + (size_t)ob * 128 * CIN;
    const __half* X = nullptr;
    __half* outH = nullptr;
    const float* bias;
    int O, O0;
    float gmean = 0.f, grstd = 0.f;
    if (mode == 0) {
        int mat = ob >> 1;
        X = (mat == 0) ? Xa : Xb;
        bias = (mat == 0) ? b0p : (mat == 1 ? b1p : b2p);
        outH = (mat == 0) ? Yq : (mat == 1 ? Yk : Yv);
        O = 256; O0 = (ob & 1) * 128;
    } else if (mode == 1) {
        bias = b0p;
        O = 512; O0 = ob * 128;
        outH = Yq;
        read_stats(statsp, win, 16, 8, gmean, grstd);
    } else {
        X = Xa; bias = b0p;
        O = 256; O0 = ob * 128;
        outH = Yq;
    }
    const uint4* gX4 = (mode != 1) ? (const uint4*)X + (size_t)win * CIN * 16 : nullptr;
    const float* gXf = (mode == 1) ? Xf + (size_t)win * WSZ : nullptr;

    auto stage = [&](int t, int buf) {
        int kc = t << 6;
        __half* sW = sWb[buf];
        __half* sX = sXb[buf];
#pragma unroll
        for (int i = tid; i < 1024; i += 256) {
            int r = i >> 3, c4 = i & 7;
            CP_ASYNC16(smem_u32(sW + r * 72 + c4 * 8), gW + (size_t)r * CIN + kc + c4 * 8);
        }
        if (mode == 1) {
#pragma unroll
            for (int i = tid; i < 2048; i += 256) {
                int r = i >> 5, p4 = i & 31;
                int c = kc + r;
                float4 v = *(const float4*)(gXf + (size_t)c * 128 + p4 * 4);
                float w = g2w[c], bb = g2b[c];
                v.x = (v.x - gmean) * grstd * w + bb;
                v.y = (v.y - gmean) * grstd * w + bb;
                v.z = (v.z - gmean) * grstd * w + bb;
                v.w = (v.w - gmean) * grstd * w + bb;
                uint2 u = {pack2h(v.x, v.y), pack2h(v.z, v.w)};
                *(uint2*)(sX + r * 136 + p4 * 4) = u;
            }
        } else {
#pragma unroll
            for (int i = tid; i < 1024; i += 256) {
                int r = i >> 4, c4 = i & 15;
                CP_ASYNC16(smem_u32(sX + r * 136 + c4 * 8), gX4 + (kc + r) * 16 + c4);
            }
        }
        CP_COMMIT();
    };

    float acc[2][8][4];
#pragma unroll
    for (int mt = 0; mt < 2; ++mt)
#pragma unroll
        for (int nt = 0; nt < 8; ++nt)
#pragma unroll
            for (int e = 0; e < 4; ++e) acc[mt][nt][e] = 0.f;

    int aRow = (lane & 15), aCol = (lane >> 4) * 8;
    int brbase = ((lane >> 3) & 1) * 8 + (lane & 7);
    int bcofs  = (lane >> 4) * 8;
    int nkc = CIN >> 6;

    stage(0, 0);
    for (int t = 0; t < nkc; ++t) {
        CP_WAIT0();
        __syncthreads();
        if (t + 1 < nkc) stage(t + 1, (t + 1) & 1);
        const __half* sW = sWb[t & 1];
        const __half* sX = sXb[t & 1];
#pragma unroll
        for (int ks = 0; ks < 4; ++ks) {
            unsigned aW[2][4];
#pragma unroll
            for (int mt = 0; mt < 2; ++mt) {
                int ro = (wr * 32 + mt * 16 + aRow) * 72 + ks * 16 + aCol;
                LDSM_X4(aW[mt][0], aW[mt][1], aW[mt][2], aW[mt][3], smem_u32(sW + ro));
            }
#pragma unroll
            for (int np = 0; np < 4; ++np) {
                int bo = (ks * 16 + brbase) * 136 + wc * 64 + np * 16 + bcofs;
                unsigned bX[4];
                LDSM_X4_T(bX[0], bX[1], bX[2], bX[3], smem_u32(sX + bo));
#pragma unroll
                for (int mt = 0; mt < 2; ++mt) {
                    mma_f16(acc[mt][np*2],   aW[mt], bX);
                    mma_f16(acc[mt][np*2+1], aW[mt], bX + 2);
                }
            }
        }
    }

    float ssum = 0.f, ssq = 0.f;
#pragma unroll
    for (int mt = 0; mt < 2; ++mt)
#pragma unroll
        for (int nt = 0; nt < 8; ++nt) {
            int p = wc * 64 + nt * 8 + (lane & 3) * 2;
#pragma unroll
            for (int half = 0; half < 2; ++half) {
                int o = O0 + wr * 32 + mt * 16 + (lane >> 2) + half * 8;
                float bv = bias[o];
                float2 v;
                v.x = acc[mt][nt][half * 2]     + bv;
                v.y = acc[mt][nt][half * 2 + 1] + bv;
                size_t gi = ((size_t)win * O + o) * 128 + p;
                if (mode == 1) {
                    v.x = 0.5f * v.x * (1.f + erff(v.x * 0.70710678118654752f));
                    v.y = 0.5f * v.y * (1.f + erff(v.y * 0.70710678118654752f));
                } else if (mode == 2) {
                    float lsv = ls[o];
                    float2 b2 = *(const float2*)(base + gi);
                    v.x = b2.x + lsv * v.x;
                    v.y = b2.y + lsv * v.y;
                    *(float2*)(Yf + gi) = v;
                    ssum += v.x + v.y;
                    ssq  += v.x*v.x + v.y*v.y;
                }
                *(unsigned*)(outH + gi) = pack2h(v.x, v.y);
            }
        }

    if (mode == 2) {
        __syncthreads();
        float* red = (float*)sb;
#pragma unroll
        for (int off = 16; off; off >>= 1) {
            ssum += __shfl_down_sync(0xffffffffu, ssum, off);
            ssq  += __shfl_down_sync(0xffffffffu, ssq,  off);
        }
        if (lane == 0) { red[wid] = ssum; red[8 + wid] = ssq; }
        __syncthreads();
        if (tid == 0) {
            float ts = 0.f, tq = 0.f;
#pragma unroll
            for (int i = 0; i < 8; ++i) { ts += red[i]; tq += red[8 + i]; }
            partials[win*16 + ob*2] = ts; partials[win*16 + ob*2 + 1] = tq;
        }
    }
}

// ---------------- attention (cp.async double-buffered) -----------------------
__global__ __launch_bounds__(256, 2)
void attn_kernel(const __half* __restrict__ Qh, const __half* __restrict__ Kh,
                 const __half* __restrict__ Vh,
                 const float* __restrict__ tgt2, float* __restrict__ tgt3,
                 float* __restrict__ out_part) {
    extern __shared__ __half sat[];
    __half* sQb[2] = { sat, sat + 18432 };
    __half* sKb[2] = { sat + 9216, sat + 18432 + 9216 };
    __half* sVb[2] = { sat, sat + 17408 };
    __shared__ float ared[16];
    int win = blockIdx.x, tid = threadIdx.x, lane = tid & 31, wid = tid >> 5;

    const uint4* gQ = (const uint4*)Qh + (size_t)win * 4096;
    const uint4* gK = (const uint4*)Kh + (size_t)win * 4096;
    const uint4* gV = (const uint4*)Vh + (size_t)win * 4096;

    auto stage_s = [&](int ch, int buf) {
        __half* sQ = sQb[buf];
        __half* sK = sKb[buf];
#pragma unroll
        for (int i = tid; i < 1024; i += 256) {
            int r = i >> 3, c4 = i & 7;
            int gi = r * 32 + ch * 8 + c4;
            int so = r * 72 + c4 * 8;
            CP_ASYNC16(smem_u32(sQ + so), gQ + gi);
            CP_ASYNC16(smem_u32(sK + so), gK + gi);
        }
        CP_COMMIT();
    };
    auto stage_v = [&](int cv, int buf) {
        __half* sV = sVb[buf];
#pragma unroll
        for (int i = tid; i < 2048; i += 256) {
            int r = i >> 4, c4 = i & 15;
            CP_ASYNC16(smem_u32(sV + r * 136 + c4 * 8), gV + r * 32 + cv * 16 + c4);
        }
        CP_COMMIT();
    };

    float acc[16][4];
#pragma unroll
    for (int j = 0; j < 16; ++j)
#pragma unroll
        for (int e = 0; e < 4; ++e) acc[j][e] = 0.f;

    int aRow = lane & 15, aCol = (lane >> 4) * 8;
    int kRow = (lane & 7) + ((lane >> 4) & 1) * 8;
    int kCol = ((lane >> 3) & 1) * 8;
    int tRow = ((lane >> 3) & 1) * 8 + (lane & 7);
    int tCol = (lane >> 4) * 8;

    stage_s(0, 0);
    for (int ch = 0; ch < 4; ++ch) {
        CP_WAIT0();
        __syncthreads();
        if (ch + 1 < 4) stage_s(ch + 1, (ch + 1) & 1);
        const __half* sQ = sQb[ch & 1];
        const __half* sK = sKb[ch & 1];
#pragma unroll
        for (int ks = 0; ks < 4; ++ks) {
            unsigned aQ[4];
            int ro = (wid * 16 + aRow) * 72 + ks * 16 + aCol;
            LDSM_X4(aQ[0], aQ[1], aQ[2], aQ[3], smem_u32(sQ + ro));
#pragma unroll
            for (int ng = 0; ng < 8; ++ng) {
                int bo = (ng * 16 + kRow) * 72 + ks * 16 + kCol;
                unsigned bK[4];
                LDSM_X4(bK[0], bK[1], bK[2], bK[3], smem_u32(sK + bo));
                mma_f16(acc[ng*2],   aQ, bK);
                mma_f16(acc[ng*2+1], aQ, bK + 2);
            }
        }
    }

    float mx0 = -1e30f, mx1 = -1e30f;
#pragma unroll
    for (int j = 0; j < 16; ++j) {
        mx0 = fmaxf(mx0, fmaxf(acc[j][0], acc[j][1]));
        mx1 = fmaxf(mx1, fmaxf(acc[j][2], acc[j][3]));
    }
#pragma unroll
    for (int off = 1; off <= 2; off <<= 1) {
        mx0 = fmaxf(mx0, __shfl_xor_sync(0xffffffffu, mx0, off));
        mx1 = fmaxf(mx1, __shfl_xor_sync(0xffffffffu, mx1, off));
    }
    float s0 = 0.f, s1 = 0.f;
#pragma unroll
    for (int j = 0; j < 16; ++j) {
        acc[j][0] = expf(acc[j][0] - mx0); s0 += acc[j][0];
        acc[j][1] = expf(acc[j][1] - mx0); s0 += acc[j][1];
        acc[j][2] = expf(acc[j][2] - mx1); s1 += acc[j][2];
        acc[j][3] = expf(acc[j][3] - mx1); s1 += acc[j][3];
    }
#pragma unroll
    for (int off = 1; off <= 2; off <<= 1) {
        s0 += __shfl_xor_sync(0xffffffffu, s0, off);
        s1 += __shfl_xor_sync(0xffffffffu, s1, off);
    }
    float i0 = 1.f / s0, i1 = 1.f / s1;
#pragma unroll
    for (int j = 0; j < 16; ++j) {
        acc[j][0] *= i0; acc[j][1] *= i0;
        acc[j][2] *= i1; acc[j][3] *= i1;
    }

    unsigned pfr[8][4];
#pragma unroll
    for (int t = 0; t < 8; ++t) {
        pfr[t][0] = pack2h(acc[2*t][0],   acc[2*t][1]);
        pfr[t][1] = pack2h(acc[2*t][2],   acc[2*t][3]);
        pfr[t][2] = pack2h(acc[2*t+1][0], acc[2*t+1][1]);
        pfr[t][3] = pack2h(acc[2*t+1][2], acc[2*t+1][3]);
    }

    float ssum = 0.f, ssq = 0.f;
    __syncthreads();
    stage_v(0, 0);
    for (int cv = 0; cv < 2; ++cv) {
        CP_WAIT0();
        __syncthreads();
        if (cv + 1 < 2) stage_v(1, 1);
        const __half* sV = sVb[cv & 1];
        float oacc[16][4];
#pragma unroll
        for (int j = 0; j < 16; ++j)
#pragma unroll
            for (int e = 0; e < 4; ++e) oacc[j][e] = 0.f;
#pragma unroll
        for (int mk = 0; mk < 8; ++mk) {
#pragma unroll
            for (int ng = 0; ng < 8; ++ng) {
                int bo = (mk * 16 + tRow) * 136 + ng * 16 + tCol;
                unsigned vV[4];
                LDSM_X4_T(vV[0], vV[1], vV[2], vV[3], smem_u32(sV + bo));
                mma_f16(oacc[ng*2],   pfr[mk], vV);
                mma_f16(oacc[ng*2+1], pfr[mk], vV + 2);
            }
        }
#pragma unroll
        for (int j = 0; j < 16; ++j) {
            int col = cv * 128 + j * 8 + (lane & 3) * 2;
            int n0 = wid * 16 + (lane >> 2);
            size_t gi = (size_t)win * WSZ + n0 * 256 + col;
            float2 b0 = *(const float2*)(tgt2 + gi);
            float2 r0 = {b0.x + oacc[j][0], b0.y + oacc[j][1]};
            *(float2*)(tgt3 + gi) = r0;
            size_t gi1 = gi + 8 * 256;
            float2 b1 = *(const float2*)(tgt2 + gi1);
            float2 r1 = {b1.x + oacc[j][2], b1.y + oacc[j][3]};
            *(float2*)(tgt3 + gi1) = r1;
            ssum += r0.x + r0.y + r1.x + r1.y;
            ssq  += r0.x*r0.x + r0.y*r0.y + r1.x*r1.x + r1.y*r1.y;
        }
    }

#pragma unroll
    for (int off = 16; off; off >>= 1) {
        ssum += __shfl_down_sync(0xffffffffu, ssum, off);
        ssq  += __shfl_down_sync(0xffffffffu, ssq,  off);
    }
    if (lane == 0) { ared[wid] = ssum; ared[8 + wid] = ssq; }
    __syncthreads();
    if (tid == 0) {
        float ts = 0.f, tq = 0.f;
#pragma unroll
        for (int i = 0; i < 8; ++i) { ts += ared[i]; tq += ared[8 + i]; }
        out_part[win*16 + 0] = ts; out_part[win*16 + 1] = tq;
    }
}

// ---------------- host orchestration ---------------------------------------
extern "C" void kernel_launch(void* const* d_in, const int* in_sizes, int n_in,
                              void* d_out, int out_size) {
    const float* src  = (const float*)d_in[0];
    const float* qf   = (const float*)d_in[1];
    const float* gn1w = (const float*)d_in[2];
    const float* gn1b = (const float*)d_in[3];
    const float* gn2w = (const float*)d_in[4];
    const float* gn2b = (const float*)d_in[5];
    const float* ls1  = (const float*)d_in[6];
    const float* ls2  = (const float*)d_in[7];
    const float* ls3  = (const float*)d_in[8];
    const float* qw   = (const float*)d_in[9];
    const float* qb   = (const float*)d_in[10];
    const float* kw   = (const float*)d_in[11];
    const float* kb   = (const float*)d_in[12];
    const float* vw   = (const float*)d_in[13];
    const float* vb   = (const float*)d_in[14];
    const float* fc1w = (const float*)d_in[15];
    const float* fc1b = (const float*)d_in[16];
    const float* fc2w = (const float*)d_in[17];
    const float* fc2b = (const float*)d_in[18];
    const float* gnfw = (const float*)d_in[19];
    const float* gnfb = (const float*)d_in[20];
    float* out = (float*)d_out;

    float *tgt, *tgt2, *tgt3, *p0, *p1, *p2, *p3;
    __half *memh, *tgth, *qh, *kh, *vh, *hh, *wh;
    cudaGetSymbolAddress((void**)&tgt,  g_tgt);
    cudaGetSymbolAddress((void**)&tgt2, g_tgt2);
    cudaGetSymbolAddress((void**)&tgt3, g_tgt3);
    cudaGetSymbolAddress((void**)&p0,   g_p0);
    cudaGetSymbolAddress((void**)&p1,   g_p1);
    cudaGetSymbolAddress((void**)&p2,   g_p2);
    cudaGetSymbolAddress((void**)&p3,   g_p3);
    cudaGetSymbolAddress((void**)&memh, g_memh);
    cudaGetSymbolAddress((void**)&tgth, g_tgth);
    cudaGetSymbolAddress((void**)&qh,   g_qh);
    cudaGetSymbolAddress((void**)&kh,   g_kh);
    cudaGetSymbolAddress((void**)&vh,   g_vh);
    cudaGetSymbolAddress((void**)&hh,   g_hh);
    cudaGetSymbolAddress((void**)&wh,   g_wh);

    const int SM_ATTN = 73728;
    const int SM_TC   = 71680;
    cudaFuncSetAttribute(attn_kernel,    cudaFuncAttributeMaxDynamicSharedMemorySize, SM_ATTN);
    cudaFuncSetAttribute(gemm_tc_kernel, cudaFuncAttributeMaxDynamicSharedMemorySize, SM_TC);

    partition_kernel<<<65536, 256>>>(src, qf, memh, tgth, tgt, p0);
    conv_w_all<<<448, 256>>>(qw, kw, vw, fc1w, fc2w, wh);

    for (int l = 0; l < 2; ++l) {
        int lC = l * CDIM;
        size_t lb = (size_t)l * 458752;
        const float* mp = (l == 0) ? p0 : p1;
        int mstride = (l == 0) ? 128 : 16;
        int mnp = (l == 0) ? 64 : 2;
        // merged: QKV gemm (ob<6) + gn_mix1 tgt->tgt2 (ob 6..13)
        gemm_tc_kernel<<<dim3(NW,14), 256, SM_TC>>>(wh + lb,
            tgth, memh, nullptr, nullptr, nullptr, nullptr,
            qb + lC, kb + lC, vb + lC,
            nullptr, qh, kh, vh, 256, 0, nullptr, nullptr, nullptr,
            tgt, tgt, mp, mstride, mnp, gn1w + lC, gn1b + lC, ls1 + lC, tgt2);
        attn_kernel<<<NW, 256, SM_ATTN>>>(qh, kh, vh, tgt2, tgt3, p2);
        gn_mix_apply<<<dim3(NW,8), 256>>>(tgt3, tgt2, p2, 16, 1, gn1w + lC, gn1b + lC, ls2 + lC, tgt3, p3);
        gemm_tc_kernel<<<dim3(NW,4), 256, SM_TC>>>(wh + lb + 196608,
            nullptr, nullptr, tgt3, gn2w + lC, gn2b + lC, p3,
            fc1b + (size_t)l*512, nullptr, nullptr,
            nullptr, hh, nullptr, nullptr, 256, 1, nullptr, nullptr, nullptr,
            nullptr, nullptr, nullptr, 0, 0, nullptr, nullptr, nullptr, nullptr);
        gemm_tc_kernel<<<dim3(NW,2), 256, SM_TC>>>(wh + lb + 327680,
            hh, nullptr, nullptr, nullptr, nullptr, nullptr,
            fc2b + lC, nullptr, nullptr,
            tgt, tgth, nullptr, nullptr, 512, 2, tgt3, ls3 + lC, p1,
            nullptr, nullptr, nullptr, 0, 0, nullptr, nullptr, nullptr, nullptr);
    }

    gn_final_apply<<<dim3(NW,8), 256>>>(tgt, p1, 2, gnfw, gnfb, out);
}

// round 13
// speedup vs baseline: 6.8600x; 1.0077x over previous
#include <cuda_runtime.h>
#include <cuda_fp16.h>
#include <math.h>
#include <stdint.h>

#define NW   512
#define CDIM 256
#define PDIM 128
#define WSZ  (CDIM*PDIM)

// ---------------- scratch (static device globals; no allocations) ----------
__device__ float g_tgt [NW*WSZ];
__device__ float g_tgt2[NW*WSZ];
__device__ float g_tgt3[NW*WSZ];
__device__ __half g_memh[NW*WSZ];
__device__ __half g_tgth[NW*WSZ];
__device__ __half g_qh [NW*WSZ];
__device__ __half g_kh [NW*WSZ];
__device__ __half g_vh [NW*WSZ];
__device__ __half g_hh [NW*2*WSZ];
__device__ __half g_wh[2*458752];
__device__ float g_p0[NW*128];   // partition partials (64 slots/win)
__device__ float g_p1[NW*16];
__device__ float g_p3[NW*16];

// ================= helpers =================================================
__device__ __forceinline__ uint32_t smem_u32(const void* p) {
    uint32_t a;
    asm("{ .reg .u64 t; cvta.to.shared.u64 t, %1; cvt.u32.u64 %0, t; }" : "=r"(a) : "l"(p));
    return a;
}
#define LDSM_X4(r0,r1,r2,r3,addr) \
    asm volatile("ldmatrix.sync.aligned.m8n8.x4.shared.b16 {%0,%1,%2,%3}, [%4];" \
        : "=r"(r0),"=r"(r1),"=r"(r2),"=r"(r3) : "r"(addr))
#define LDSM_X4_T(r0,r1,r2,r3,addr) \
    asm volatile("ldmatrix.sync.aligned.m8n8.x4.trans.shared.b16 {%0,%1,%2,%3}, [%4];" \
        : "=r"(r0),"=r"(r1),"=r"(r2),"=r"(r3) : "r"(addr))
__device__ __forceinline__ void mma_f16(float* d, const unsigned* a, const unsigned* b) {
    asm volatile("mma.sync.aligned.m16n8k16.row.col.f32.f16.f16.f32 "
        "{%0,%1,%2,%3}, {%4,%5,%6,%7}, {%8,%9}, {%0,%1,%2,%3};"
        : "+f"(d[0]),"+f"(d[1]),"+f"(d[2]),"+f"(d[3])
        : "r"(a[0]),"r"(a[1]),"r"(a[2]),"r"(a[3]), "r"(b[0]),"r"(b[1]));
}
#define CP_ASYNC16(sa, gp) \
    asm volatile("cp.async.cg.shared.global [%0], [%1], 16;" :: "r"(sa), "l"(gp))
#define CP_COMMIT() asm volatile("cp.async.commit_group;" ::: "memory")
#define CP_WAIT0()  asm volatile("cp.async.wait_group 0;" ::: "memory")
__device__ __forceinline__ unsigned pack2h(float a, float b) {
    __half ah = __float2half_rn(a), bh = __float2half_rn(b);
    return (unsigned)__half_as_ushort(ah) | ((unsigned)__half_as_ushort(bh) << 16);
}
__device__ __forceinline__ void read_stats(const float* part, int win, int pstride, int nparts,
                                           float& mean, float& rstd) {
    float S = 0.f, Q = 0.f;
    for (int i = 0; i < nparts; ++i) { S += part[win*pstride + i*2]; Q += part[win*pstride + i*2 + 1]; }
    mean = S * (1.f / 32768.f);
    float var = Q * (1.f / 32768.f) - mean * mean;
    rstd = rsqrtf(var + 1e-5f);
}

// ---- shuffle-stencil GN+mix body for one 32-channel slice; returns out sums ----
__device__ __forceinline__ void gn_mix_slice(
        int win, int yb, int lane, int wid, float mean, float rstd,
        const float* __restrict__ in, const float* __restrict__ basep,
        const float* __restrict__ gw, const float* __restrict__ gb,
        const float* __restrict__ ls, float* __restrict__ outf,
        float& s2, float& q2, bool want_stats) {
    int p0 = lane * 4;
    int y = lane >> 2, x0 = (lane & 3) * 4;
    float vcnt = 3.f - (y == 0 ? 1.f : 0.f) - (y == 7 ? 1.f : 0.f);
    float rinv[4];
#pragma unroll
    for (int j = 0; j < 4; ++j) {
        int x = x0 + j;
        float hc = 3.f - (x == 0 ? 1.f : 0.f) - (x == 15 ? 1.f : 0.f);
        rinv[j] = 1.f / (hc * vcnt);
    }
#pragma unroll
    for (int ci = 0; ci < 4; ++ci) {
        int c = yb * 32 + wid * 4 + ci;
        size_t gi = (size_t)win * WSZ + c * 128 + p0;
        float w = gw[c], bb = gb[c];
        float4 v = *(const float4*)(in + gi);
        v.x = (v.x - mean) * rstd * w + bb;
        v.y = (v.y - mean) * rstd * w + bb;
        v.z = (v.z - mean) * rstd * w + bb;
        v.w = (v.w - mean) * rstd * w + bb;
        float L = __shfl_up_sync(0xffffffffu, v.w, 1);
        float R = __shfl_down_sync(0xffffffffu, v.x, 1);
        if (x0 == 0)  L = 0.f;
        if (x0 == 12) R = 0.f;
        float4 h;
        h.x = L + v.x + v.y;
        h.y = v.x + v.y + v.z;
        h.z = v.y + v.z + v.w;
        h.w = v.z + v.w + R;
        float4 up, dn;
        up.x = __shfl_up_sync(0xffffffffu, h.x, 4);
        up.y = __shfl_up_sync(0xffffffffu, h.y, 4);
        up.z = __shfl_up_sync(0xffffffffu, h.z, 4);
        up.w = __shfl_up_sync(0xffffffffu, h.w, 4);
        dn.x = __shfl_down_sync(0xffffffffu, h.x, 4);
        dn.y = __shfl_down_sync(0xffffffffu, h.y, 4);
        dn.z = __shfl_down_sync(0xffffffffu, h.z, 4);
        dn.w = __shfl_down_sync(0xffffffffu, h.w, 4);
        if (y == 0) { up.x = up.y = up.z = up.w = 0.f; }
        if (y == 7) { dn.x = dn.y = dn.z = dn.w = 0.f; }
        float o0 = (up.x + h.x + dn.x) * rinv[0] - v.x;
        float o1 = (up.y + h.y + dn.y) * rinv[1] - v.y;
        float o2 = (up.z + h.z + dn.z) * rinv[2] - v.z;
        float o3 = (up.w + h.w + dn.w) * rinv[3] - v.w;
        float4 bv = *(const float4*)(basep + gi);
        float lsv = ls[c];
        float4 ov = {bv.x + lsv * o0, bv.y + lsv * o1,
                     bv.z + lsv * o2, bv.w + lsv * o3};
        *(float4*)(outf + gi) = ov;
        if (want_stats) {
            s2 += ov.x + ov.y + ov.z + ov.w;
            q2 += ov.x*ov.x + ov.y*ov.y + ov.z*ov.z + ov.w*ov.w;
        }
    }
}

// ---------------- partition (merged src + qf, fused qf stats) ----------------
__global__ void partition_kernel(const float* __restrict__ src, const float* __restrict__ qf,
                                 __half* __restrict__ memh, __half* __restrict__ tgth,
                                 float* __restrict__ tgt, float* __restrict__ p0) {
    __shared__ float red[16];
    int gb = blockIdx.x;
    bool isq = gb >= 32768;
    int g = (isq ? gb - 32768 : gb) * 256 + threadIdx.x;
    int idx = g * 2;
    int p = idx & 127, c = (idx >> 7) & 255, bw = idx >> 15;
    int b = bw >> 7, wblk = bw & 127;
    int h = (wblk >> 3) * 8 + (p >> 4), w = (wblk & 7) * 16 + (p & 15);
    const float* s = (isq ? qf : src) + (((size_t)b * 256 + c) * 128 + h) * 128 + w;
    float a0 = s[0], a1 = s[1];
    unsigned u = pack2h(a0, a1);
    if (isq) {
        *(unsigned*)(tgth + idx) = u;
        *(float2*)(tgt + idx) = make_float2(a0, a1);
        int tid = threadIdx.x, lane = tid & 31, wid = tid >> 5;
        float ss = a0 + a1, qq = a0*a0 + a1*a1;
#pragma unroll
        for (int off = 16; off; off >>= 1) {
            ss += __shfl_down_sync(0xffffffffu, ss, off);
            qq += __shfl_down_sync(0xffffffffu, qq, off);
        }
        if (lane == 0) { red[wid] = ss; red[8 + wid] = qq; }
        __syncthreads();
        if (tid == 0) {
            float ts = 0.f, tq = 0.f;
#pragma unroll
            for (int i = 0; i < 8; ++i) { ts += red[i]; tq += red[8 + i]; }
            int sb = gb - 32768;
            int win = sb >> 6, slot = sb & 63;
            p0[win*128 + slot*2] = ts; p0[win*128 + slot*2 + 1] = tq;
        }
    } else {
        *(unsigned*)(memh + idx) = u;
    }
}

// ---------------- all weights fp32 -> single fp16 (one launch) --------------
__global__ void conv_w_all(const float* __restrict__ qw, const float* __restrict__ kw,
                           const float* __restrict__ vw, const float* __restrict__ fc1w,
                           const float* __restrict__ fc2w, __half* __restrict__ hi) {
    int g = blockIdx.x * 256 + threadIdx.x;
    int l = g / 57344, r = g - l * 57344;
    const float* srcp;
    size_t oo;
    if (r < 8192)        { srcp = qw  + (size_t)l*65536  + (size_t)r*8;          oo = (size_t)l*458752 + (size_t)r*8; }
    else if (r < 16384)  { srcp = kw  + (size_t)l*65536  + (size_t)(r-8192)*8;   oo = (size_t)l*458752 + 65536  + (size_t)(r-8192)*8; }
    else if (r < 24576)  { srcp = vw  + (size_t)l*65536  + (size_t)(r-16384)*8;  oo = (size_t)l*458752 + 131072 + (size_t)(r-16384)*8; }
    else if (r < 40960)  { srcp = fc1w+ (size_t)l*131072 + (size_t)(r-24576)*8;  oo = (size_t)l*458752 + 196608 + (size_t)(r-24576)*8; }
    else                 { srcp = fc2w+ (size_t)l*131072 + (size_t)(r-40960)*8;  oo = (size_t)l*458752 + 327680 + (size_t)(r-40960)*8; }
    unsigned hh[4];
#pragma unroll
    for (int j = 0; j < 4; ++j) hh[j] = pack2h(srcp[2*j], srcp[2*j+1]);
    uint4 vh = {hh[0], hh[1], hh[2], hh[3]};
    *(uint4*)(hi + oo) = vh;
}

// ---------------- final GN + fused window-reverse transpose ------------------
__global__ __launch_bounds__(256)
void gn_final_apply(const float* __restrict__ in, const float* __restrict__ part, int nparts,
                    const float* __restrict__ gw, const float* __restrict__ gb,
                    float* __restrict__ out) {
    __shared__ float tile[32 * 129];
    int win = blockIdx.x, yb = blockIdx.y, tid = threadIdx.x, lane = tid & 31, wid = tid >> 5;
    float mean, rstd;
    read_stats(part, win, 16, nparts, mean, rstd);
    size_t b0 = (size_t)win * WSZ + yb * 4096;
    const float4* src = (const float4*)(in + b0);
#pragma unroll
    for (int k = 0; k < 4; ++k) {
        int idx = tid + k * 256;
        int cl = idx >> 5, p4 = idx & 31;
        float w = gw[yb * 32 + cl], bb = gb[yb * 32 + cl];
        float4 v = src[idx];
        float* t = tile + cl * 129 + p4 * 4;
        t[0] = (v.x - mean) * rstd * w + bb;
        t[1] = (v.y - mean) * rstd * w + bb;
        t[2] = (v.z - mean) * rstd * w + bb;
        t[3] = (v.w - mean) * rstd * w + bb;
    }
    __syncthreads();
    int b = win >> 7, wblk = win & 127;
    int hb = (wblk >> 3) * 8, wb = (wblk & 7) * 16;
#pragma unroll
    for (int k = 0; k < 16; ++k) {
        int p = k * 8 + wid;
        int h = hb + (p >> 4), w = wb + (p & 15);
        int n = h * 128 + w;
        out[((size_t)n * 4 + b) * 256 + yb * 32 + lane] = tile[lane * 129 + p];
    }
}

// ---------------- tensor-core GEMM (cp.async double-buffered) ----------------
// mode 0: merged QKV + gn_mix1 slices (ob>=6)  mode 1: fc1+gn2  mode 2: fc2
__global__ __launch_bounds__(256, 2)
void gemm_tc_kernel(const __half* __restrict__ Wh,
                    const __half* __restrict__ Xa, const __half* __restrict__ Xb,
                    const float* __restrict__ Xf, const float* __restrict__ g2w,
                    const float* __restrict__ g2b, const float* __restrict__ statsp,
                    const float* __restrict__ b0p, const float* __restrict__ b1p,
                    const float* __restrict__ b2p,
                    float* __restrict__ Yf,
                    __half* __restrict__ Yq, __half* __restrict__ Yk, __half* __restrict__ Yv,
                    int CIN, int mode,
                    const float* __restrict__ base, const float* __restrict__ ls,
                    float* __restrict__ partials,
                    const float* __restrict__ mixIn, const float* __restrict__ mixBase,
                    const float* __restrict__ mixPart, int mixPstride, int mixNparts,
                    const float* __restrict__ mixGw, const float* __restrict__ mixGb,
                    const float* __restrict__ mixLs, float* __restrict__ mixOut) {
    extern __shared__ __half sb[];
    int win = blockIdx.x, ob = blockIdx.y;
    int tid = threadIdx.x, lane = tid & 31, wid = tid >> 5;

    if (mode == 0 && ob >= 6) {
        float mean, rstd, du0, du1;
        read_stats(mixPart, win, mixPstride, mixNparts, mean, rstd);
        gn_mix_slice(win, ob - 6, lane, wid, mean, rstd, mixIn, mixBase,
                     mixGw, mixGb, mixLs, mixOut, du0, du1, false);
        return;
    }

    __half* sWb[2] = { sb, sb + 17920 };
    __half* sXb[2] = { sb + 9216, sb + 17920 + 9216 };
    int wr = wid >> 1, wc = wid & 1;

    const __half* gW = Wh + (size_t)ob * 128 * CIN;
    const __half* X = nullptr;
    __half* outH = nullptr;
    const float* bias;
    int O, O0;
    float gmean = 0.f, grstd = 0.f;
    if (mode == 0) {
        int mat = ob >> 1;
        X = (mat == 0) ? Xa : Xb;
        bias = (mat == 0) ? b0p : (mat == 1 ? b1p : b2p);
        outH = (mat == 0) ? Yq : (mat == 1 ? Yk : Yv);
        O = 256; O0 = (ob & 1) * 128;
    } else if (mode == 1) {
        bias = b0p;
        O = 512; O0 = ob * 128;
        outH = Yq;
        read_stats(statsp, win, 16, 1, gmean, grstd);
    } else {
        X = Xa; bias = b0p;
        O = 256; O0 = ob * 128;
        outH = Yq;
    }
    const uint4* gX4 = (mode != 1) ? (const uint4*)X + (size_t)win * CIN * 16 : nullptr;
    const float* gXf = (mode == 1) ? Xf + (size_t)win * WSZ : nullptr;

    auto stage = [&](int t, int buf) {
        int kc = t << 6;
        __half* sW = sWb[buf];
        __half* sX = sXb[buf];
#pragma unroll
        for (int i = tid; i < 1024; i += 256) {
            int r = i >> 3, c4 = i & 7;
            CP_ASYNC16(smem_u32(sW + r * 72 + c4 * 8), gW + (size_t)r * CIN + kc + c4 * 8);
        }
        if (mode == 1) {
#pragma unroll
            for (int i = tid; i < 2048; i += 256) {
                int r = i >> 5, p4 = i & 31;
                int c = kc + r;
                float4 v = *(const float4*)(gXf + (size_t)c * 128 + p4 * 4);
                float w = g2w[c], bb = g2b[c];
                v.x = (v.x - gmean) * grstd * w + bb;
                v.y = (v.y - gmean) * grstd * w + bb;
                v.z = (v.z - gmean) * grstd * w + bb;
                v.w = (v.w - gmean) * grstd * w + bb;
                uint2 u = {pack2h(v.x, v.y), pack2h(v.z, v.w)};
                *(uint2*)(sX + r * 136 + p4 * 4) = u;
            }
        } else {
#pragma unroll
            for (int i = tid; i < 1024; i += 256) {
                int r = i >> 4, c4 = i & 15;
                CP_ASYNC16(smem_u32(sX + r * 136 + c4 * 8), gX4 + (kc + r) * 16 + c4);
            }
        }
        CP_COMMIT();
    };

    float acc[2][8][4];
#pragma unroll
    for (int mt = 0; mt < 2; ++mt)
#pragma unroll
        for (int nt = 0; nt < 8; ++nt)
#pragma unroll
            for (int e = 0; e < 4; ++e) acc[mt][nt][e] = 0.f;

    int aRow = (lane & 15), aCol = (lane >> 4) * 8;
    int brbase = ((lane >> 3) & 1) * 8 + (lane & 7);
    int bcofs  = (lane >> 4) * 8;
    int nkc = CIN >> 6;

    stage(0, 0);
    for (int t = 0; t < nkc; ++t) {
        CP_WAIT0();
        __syncthreads();
        if (t + 1 < nkc) stage(t + 1, (t + 1) & 1);
        const __half* sW = sWb[t & 1];
        const __half* sX = sXb[t & 1];
#pragma unroll
        for (int ks = 0; ks < 4; ++ks) {
            unsigned aW[2][4];
#pragma unroll
            for (int mt = 0; mt < 2; ++mt) {
                int ro = (wr * 32 + mt * 16 + aRow) * 72 + ks * 16 + aCol;
                LDSM_X4(aW[mt][0], aW[mt][1], aW[mt][2], aW[mt][3], smem_u32(sW + ro));
            }
#pragma unroll
            for (int np = 0; np < 4; ++np) {
                int bo = (ks * 16 + brbase) * 136 + wc * 64 + np * 16 + bcofs;
                unsigned bX[4];
                LDSM_X4_T(bX[0], bX[1], bX[2], bX[3], smem_u32(sX + bo));
#pragma unroll
                for (int mt = 0; mt < 2; ++mt) {
                    mma_f16(acc[mt][np*2],   aW[mt], bX);
                    mma_f16(acc[mt][np*2+1], aW[mt], bX + 2);
                }
            }
        }
    }

    float ssum = 0.f, ssq = 0.f;
#pragma unroll
    for (int mt = 0; mt < 2; ++mt)
#pragma unroll
        for (int nt = 0; nt < 8; ++nt) {
            int p = wc * 64 + nt * 8 + (lane & 3) * 2;
#pragma unroll
            for (int half = 0; half < 2; ++half) {
                int o = O0 + wr * 32 + mt * 16 + (lane >> 2) + half * 8;
                float bv = bias[o];
                float2 v;
                v.x = acc[mt][nt][half * 2]     + bv;
                v.y = acc[mt][nt][half * 2 + 1] + bv;
                size_t gi = ((size_t)win * O + o) * 128 + p;
                if (mode == 1) {
                    v.x = 0.5f * v.x * (1.f + erff(v.x * 0.70710678118654752f));
                    v.y = 0.5f * v.y * (1.f + erff(v.y * 0.70710678118654752f));
                } else if (mode == 2) {
                    float lsv = ls[o];
                    float2 b2 = *(const float2*)(base + gi);
                    v.x = b2.x + lsv * v.x;
                    v.y = b2.y + lsv * v.y;
                    *(float2*)(Yf + gi) = v;
                    ssum += v.x + v.y;
                    ssq  += v.x*v.x + v.y*v.y;
                }
                *(unsigned*)(outH + gi) = pack2h(v.x, v.y);
            }
        }

    if (mode == 2) {
        __syncthreads();
        float* red = (float*)sb;
#pragma unroll
        for (int off = 16; off; off >>= 1) {
            ssum += __shfl_down_sync(0xffffffffu, ssum, off);
            ssq  += __shfl_down_sync(0xffffffffu, ssq,  off);
        }
        if (lane == 0) { red[wid] = ssum; red[8 + wid] = ssq; }
        __syncthreads();
        if (tid == 0) {
            float ts = 0.f, tq = 0.f;
#pragma unroll
            for (int i = 0; i < 8; ++i) { ts += red[i]; tq += red[8 + i]; }
            partials[win*16 + ob*2] = ts; partials[win*16 + ob*2 + 1] = tq;
        }
    }
}

// ---------------- attention + fused gn_mix2 ---------------------------------
// tgt3 = tgt2 + attn; then tgt3 = tgt2 + ls2*mix(gn1(tgt3)); p3 <- stats(tgt3 new)
__global__ __launch_bounds__(256, 2)
void attn_kernel(const __half* __restrict__ Qh, const __half* __restrict__ Kh,
                 const __half* __restrict__ Vh,
                 const float* __restrict__ tgt2, float* __restrict__ tgt3,
                 const float* __restrict__ g1w, const float* __restrict__ g1b,
                 const float* __restrict__ ls2, float* __restrict__ p3) {
    extern __shared__ __half sat[];
    __half* sQb[2] = { sat, sat + 18432 };
    __half* sKb[2] = { sat + 9216, sat + 18432 + 9216 };
    __half* sVb[2] = { sat, sat + 17408 };
    __shared__ float ared[16];
    __shared__ float stats2[2];
    int win = blockIdx.x, tid = threadIdx.x, lane = tid & 31, wid = tid >> 5;

    const uint4* gQ = (const uint4*)Qh + (size_t)win * 4096;
    const uint4* gK = (const uint4*)Kh + (size_t)win * 4096;
    const uint4* gV = (const uint4*)Vh + (size_t)win * 4096;

    auto stage_s = [&](int ch, int buf) {
        __half* sQ = sQb[buf];
        __half* sK = sKb[buf];
#pragma unroll
        for (int i = tid; i < 1024; i += 256) {
            int r = i >> 3, c4 = i & 7;
            int gi = r * 32 + ch * 8 + c4;
            int so = r * 72 + c4 * 8;
            CP_ASYNC16(smem_u32(sQ + so), gQ + gi);
            CP_ASYNC16(smem_u32(sK + so), gK + gi);
        }
        CP_COMMIT();
    };
    auto stage_v = [&](int cv, int buf) {
        __half* sV = sVb[buf];
#pragma unroll
        for (int i = tid; i < 2048; i += 256) {
            int r = i >> 4, c4 = i & 15;
            CP_ASYNC16(smem_u32(sV + r * 136 + c4 * 8), gV + r * 32 + cv * 16 + c4);
        }
        CP_COMMIT();
    };

    float acc[16][4];
#pragma unroll
    for (int j = 0; j < 16; ++j)
#pragma unroll
        for (int e = 0; e < 4; ++e) acc[j][e] = 0.f;

    int aRow = lane & 15, aCol = (lane >> 4) * 8;
    int kRow = (lane & 7) + ((lane >> 4) & 1) * 8;
    int kCol = ((lane >> 3) & 1) * 8;
    int tRow = ((lane >> 3) & 1) * 8 + (lane & 7);
    int tCol = (lane >> 4) * 8;

    stage_s(0, 0);
    for (int ch = 0; ch < 4; ++ch) {
        CP_WAIT0();
        __syncthreads();
        if (ch + 1 < 4) stage_s(ch + 1, (ch + 1) & 1);
        const __half* sQ = sQb[ch & 1];
        const __half* sK = sKb[ch & 1];
#pragma unroll
        for (int ks = 0; ks < 4; ++ks) {
            unsigned aQ[4];
            int ro = (wid * 16 + aRow) * 72 + ks * 16 + aCol;
            LDSM_X4(aQ[0], aQ[1], aQ[2], aQ[3], smem_u32(sQ + ro));
#pragma unroll
            for (int ng = 0; ng < 8; ++ng) {
                int bo = (ng * 16 + kRow) * 72 + ks * 16 + kCol;
                unsigned bK[4];
                LDSM_X4(bK[0], bK[1], bK[2], bK[3], smem_u32(sK + bo));
                mma_f16(acc[ng*2],   aQ, bK);
                mma_f16(acc[ng*2+1], aQ, bK + 2);
            }
        }
    }

    float mx0 = -1e30f, mx1 = -1e30f;
#pragma unroll
    for (int j = 0; j < 16; ++j) {
        mx0 = fmaxf(mx0, fmaxf(acc[j][0], acc[j][1]));
        mx1 = fmaxf(mx1, fmaxf(acc[j][2], acc[j][3]));
    }
#pragma unroll
    for (int off = 1; off <= 2; off <<= 1) {
        mx0 = fmaxf(mx0, __shfl_xor_sync(0xffffffffu, mx0, off));
        mx1 = fmaxf(mx1, __shfl_xor_sync(0xffffffffu, mx1, off));
    }
    float s0 = 0.f, s1 = 0.f;
#pragma unroll
    for (int j = 0; j < 16; ++j) {
        acc[j][0] = expf(acc[j][0] - mx0); s0 += acc[j][0];
        acc[j][1] = expf(acc[j][1] - mx0); s0 += acc[j][1];
        acc[j][2] = expf(acc[j][2] - mx1); s1 += acc[j][2];
        acc[j][3] = expf(acc[j][3] - mx1); s1 += acc[j][3];
    }
#pragma unroll
    for (int off = 1; off <= 2; off <<= 1) {
        s0 += __shfl_xor_sync(0xffffffffu, s0, off);
        s1 += __shfl_xor_sync(0xffffffffu, s1, off);
    }
    float i0 = 1.f / s0, i1 = 1.f / s1;
#pragma unroll
    for (int j = 0; j < 16; ++j) {
        acc[j][0] *= i0; acc[j][1] *= i0;
        acc[j][2] *= i1; acc[j][3] *= i1;
    }

    unsigned pfr[8][4];
#pragma unroll
    for (int t = 0; t < 8; ++t) {
        pfr[t][0] = pack2h(acc[2*t][0],   acc[2*t][1]);
        pfr[t][1] = pack2h(acc[2*t][2],   acc[2*t][3]);
        pfr[t][2] = pack2h(acc[2*t+1][0], acc[2*t+1][1]);
        pfr[t][3] = pack2h(acc[2*t+1][2], acc[2*t+1][3]);
    }

    float ssum = 0.f, ssq = 0.f;
    __syncthreads();
    stage_v(0, 0);
    for (int cv = 0; cv < 2; ++cv) {
        CP_WAIT0();
        __syncthreads();
        if (cv + 1 < 2) stage_v(1, 1);
        const __half* sV = sVb[cv & 1];
        float oacc[16][4];
#pragma unroll
        for (int j = 0; j < 16; ++j)
#pragma unroll
            for (int e = 0; e < 4; ++e) oacc[j][e] = 0.f;
#pragma unroll
        for (int mk = 0; mk < 8; ++mk) {
#pragma unroll
            for (int ng = 0; ng < 8; ++ng) {
                int bo = (mk * 16 + tRow) * 136 + ng * 16 + tCol;
                unsigned vV[4];
                LDSM_X4_T(vV[0], vV[1], vV[2], vV[3], smem_u32(sV + bo));
                mma_f16(oacc[ng*2],   pfr[mk], vV);
                mma_f16(oacc[ng*2+1], pfr[mk], vV + 2);
            }
        }
#pragma unroll
        for (int j = 0; j < 16; ++j) {
            int col = cv * 128 + j * 8 + (lane & 3) * 2;
            int n0 = wid * 16 + (lane >> 2);
            size_t gi = (size_t)win * WSZ + n0 * 256 + col;
            float2 b0 = *(const float2*)(tgt2 + gi);
            float2 r0 = {b0.x + oacc[j][0], b0.y + oacc[j][1]};
            *(float2*)(tgt3 + gi) = r0;
            size_t gi1 = gi + 8 * 256;
            float2 b1 = *(const float2*)(tgt2 + gi1);
            float2 r1 = {b1.x + oacc[j][2], b1.y + oacc[j][3]};
            *(float2*)(tgt3 + gi1) = r1;
            ssum += r0.x + r0.y + r1.x + r1.y;
            ssq  += r0.x*r0.x + r0.y*r0.y + r1.x*r1.x + r1.y*r1.y;
        }
    }

    // whole-window stats of attn tgt3 (for gn1 in mix2)
#pragma unroll
    for (int off = 16; off; off >>= 1) {
        ssum += __shfl_down_sync(0xffffffffu, ssum, off);
        ssq  += __shfl_down_sync(0xffffffffu, ssq,  off);
    }
    if (lane == 0) { ared[wid] = ssum; ared[8 + wid] = ssq; }
    __syncthreads();
    if (tid == 0) {
        float ts = 0.f, tq = 0.f;
#pragma unroll
        for (int i = 0; i < 8; ++i) { ts += ared[i]; tq += ared[8 + i]; }
        float mean = ts * (1.f / 32768.f);
        float var  = tq * (1.f / 32768.f) - mean * mean;
        stats2[0] = mean; stats2[1] = rsqrtf(var + 1e-5f);
    }
    __syncthreads();
    float mean2 = stats2[0], rstd2 = stats2[1];

    // fused mix2: tgt3 = tgt2 + ls2*mix(gn1(tgt3)), all 8 slices; p3 stats
    float s3 = 0.f, q3 = 0.f;
    for (int yb = 0; yb < 8; ++yb)
        gn_mix_slice(win, yb, lane, wid, mean2, rstd2, tgt3, tgt2,
                     g1w, g1b, ls2, tgt3, s3, q3, true);
#pragma unroll
    for (int off = 16; off; off >>= 1) {
        s3 += __shfl_down_sync(0xffffffffu, s3, off);
        q3 += __shfl_down_sync(0xffffffffu, q3, off);
    }
    if (lane == 0) { ared[wid] = s3; ared[8 + wid] = q3; }
    __syncthreads();
    if (tid == 0) {
        float ts = 0.f, tq = 0.f;
#pragma unroll
        for (int i = 0; i < 8; ++i) { ts += ared[i]; tq += ared[8 + i]; }
        p3[win*16 + 0] = ts; p3[win*16 + 1] = tq;
    }
}

// ---------------- host orchestration ---------------------------------------
extern "C" void kernel_launch(void* const* d_in, const int* in_sizes, int n_in,
                              void* d_out, int out_size) {
    const float* src  = (const float*)d_in[0];
    const float* qf   = (const float*)d_in[1];
    const float* gn1w = (const float*)d_in[2];
    const float* gn1b = (const float*)d_in[3];
    const float* gn2w = (const float*)d_in[4];
    const float* gn2b = (const float*)d_in[5];
    const float* ls1  = (const float*)d_in[6];
    const float* ls2  = (const float*)d_in[7];
    const float* ls3  = (const float*)d_in[8];
    const float* qw   = (const float*)d_in[9];
    const float* qb   = (const float*)d_in[10];
    const float* kw   = (const float*)d_in[11];
    const float* kb   = (const float*)d_in[12];
    const float* vw   = (const float*)d_in[13];
    const float* vb   = (const float*)d_in[14];
    const float* fc1w = (const float*)d_in[15];
    const float* fc1b = (const float*)d_in[16];
    const float* fc2w = (const float*)d_in[17];
    const float* fc2b = (const float*)d_in[18];
    const float* gnfw = (const float*)d_in[19];
    const float* gnfb = (const float*)d_in[20];
    float* out = (float*)d_out;

    float *tgt, *tgt2, *tgt3, *p0, *p1, *p3;
    __half *memh, *tgth, *qh, *kh, *vh, *hh, *wh;
    cudaGetSymbolAddress((void**)&tgt,  g_tgt);
    cudaGetSymbolAddress((void**)&tgt2, g_tgt2);
    cudaGetSymbolAddress((void**)&tgt3, g_tgt3);
    cudaGetSymbolAddress((void**)&p0,   g_p0);
    cudaGetSymbolAddress((void**)&p1,   g_p1);
    cudaGetSymbolAddress((void**)&p3,   g_p3);
    cudaGetSymbolAddress((void**)&memh, g_memh);
    cudaGetSymbolAddress((void**)&tgth, g_tgth);
    cudaGetSymbolAddress((void**)&qh,   g_qh);
    cudaGetSymbolAddress((void**)&kh,   g_kh);
    cudaGetSymbolAddress((void**)&vh,   g_vh);
    cudaGetSymbolAddress((void**)&hh,   g_hh);
    cudaGetSymbolAddress((void**)&wh,   g_wh);

    const int SM_ATTN = 73728;
    const int SM_TC   = 71680;
    cudaFuncSetAttribute(attn_kernel,    cudaFuncAttributeMaxDynamicSharedMemorySize, SM_ATTN);
    cudaFuncSetAttribute(gemm_tc_kernel, cudaFuncAttributeMaxDynamicSharedMemorySize, SM_TC);

    partition_kernel<<<65536, 256>>>(src, qf, memh, tgth, tgt, p0);
    conv_w_all<<<448, 256>>>(qw, kw, vw, fc1w, fc2w, wh);

    for (int l = 0; l < 2; ++l) {
        int lC = l * CDIM;
        size_t lb = (size_t)l * 458752;
        const float* mp = (l == 0) ? p0 : p1;
        int mstride = (l == 0) ? 128 : 16;
        int mnp = (l == 0) ? 64 : 2;
        // merged: QKV gemm (ob<6) + gn_mix1 tgt->tgt2 (ob 6..13)
        gemm_tc_kernel<<<dim3(NW,14), 256, SM_TC>>>(wh + lb,
            tgth, memh, nullptr, nullptr, nullptr, nullptr,
            qb + lC, kb + lC, vb + lC,
            nullptr, qh, kh, vh, 256, 0, nullptr, nullptr, nullptr,
            tgt, tgt, mp, mstride, mnp, gn1w + lC, gn1b + lC, ls1 + lC, tgt2);
        // attn + fused mix2: tgt3 final, p3 stats for gn2
        attn_kernel<<<NW, 256, SM_ATTN>>>(qh, kh, vh, tgt2, tgt3,
                                          gn1w + lC, gn1b + lC, ls2 + lC, p3);
        // h = gelu(fc1(gn2(tgt3)))
        gemm_tc_kernel<<<dim3(NW,4), 256, SM_TC>>>(wh + lb + 196608,
            nullptr, nullptr, tgt3, gn2w + lC, gn2b + lC, p3,
            fc1b + (size_t)l*512, nullptr, nullptr,
            nullptr, hh, nullptr, nullptr, 256, 1, nullptr, nullptr, nullptr,
            nullptr, nullptr, nullptr, 0, 0, nullptr, nullptr, nullptr, nullptr);
        // tgt = tgt3 + ls3*fc2(h)  (+stats -> p1)
        gemm_tc_kernel<<<dim3(NW,2), 256, SM_TC>>>(wh + lb + 327680,
            hh, nullptr, nullptr, nullptr, nullptr, nullptr,
            fc2b + lC, nullptr, nullptr,
            tgt, tgth, nullptr, nullptr, 512, 2, tgt3, ls3 + lC, p1,
            nullptr, nullptr, nullptr, 0, 0, nullptr, nullptr, nullptr, nullptr);
    }

    gn_final_apply<<<dim3(NW,8), 256>>>(tgt, p1, 2, gnfw, gnfb, out);
}